// round 6
// baseline (speedup 1.0000x reference)
#include <cuda_runtime.h>
#include <math.h>

#define HW   1024
#define DM   64
#define DS   16
#define NV   25
#define TIN  4
#define MAXS 8

// ---------------- scratch (static device globals; no allocation) ----------------
__device__ __align__(128) float g_u[TIN * HW * DM];
__device__ __align__(128) float g_e1[TIN * HW * DM];
__device__ __align__(128) float g_cc[TIN * HW * 96];            // [t][px][dconv|B|C]
__device__ __align__(128) float g_wpack[96 * 576];              // wd|wB|wC transposed [oc][tap][ic]
__device__ __align__(128) float g_wenc2[64 * 576];
__device__ __align__(128) float g_wdec1[64 * 576];
__device__ __align__(128) float g_wdec2[64 * 576];
__device__ __align__(128) float g_bpack[96];
__device__ __align__(128) float g_A[DS * DM];                   // A[n][d] = -exp(logA[d][n])
__device__ __align__(128) float g_rA[DS * DM];
__device__ int   g_uniA;
// history fields, slot s-1 for step s = 1..8
__device__ __align__(128) float g_ef[MAXS * HW * DM * 2];       // [slot][p][dq][{e4,f4}]
__device__ __align__(128) float g_dl[MAXS * HW * DM];           // delta (generic fallback)
__device__ __align__(128) float g_uf[MAXS * HW * DM];           // u history (generic fallback)
__device__ __align__(128) float g_Bf[MAXS * HW * DS];           // B fields [slot][p][n]
__device__ __align__(128) float g_ymax[HW * DM];
__device__ __align__(128) float g_d1[HW * DM];
__device__ __align__(128) float g_d2[HW * DM];

// ---------------- pack: transposed weights + bias + A fields ----------------
__global__ void pack_all(const float* __restrict__ wd, const float* __restrict__ bd,
                         const float* __restrict__ wB, const float* __restrict__ wC,
                         const float* __restrict__ logA,
                         const float* __restrict__ ew2, const float* __restrict__ dw1,
                         const float* __restrict__ dw2)
{
    int k = blockIdx.x * 256 + threadIdx.x;
    const int R0 = 96 * 576;
    const int R1 = R0 + 3 * 64 * 576;
    if (k < R0) {
        int oc = k / 576, rem = k - oc * 576;
        int tap = rem >> 6, ic = rem & 63;
        float v;
        if (oc < 64)      v = wd[oc * 576 + ic * 9 + tap];
        else if (oc < 80) v = wB[(oc - 64) * 576 + ic * 9 + tap];
        else              v = wC[(oc - 80) * 576 + ic * 9 + tap];
        g_wpack[k] = v;
    } else if (k < R1) {
        int k2 = k - R0;
        int which = k2 / (64 * 576);
        int k3 = k2 - which * (64 * 576);
        int oc = k3 / 576, rem = k3 - oc * 576;
        int tap = rem >> 6, ic = rem & 63;
        const float* s = (which == 0) ? ew2 : ((which == 1) ? dw1 : dw2);
        float v = s[oc * 576 + ic * 9 + tap];
        if (which == 0) g_wenc2[k3] = v;
        else if (which == 1) g_wdec1[k3] = v;
        else g_wdec2[k3] = v;
    }
    if (k < DM)       g_bpack[k] = bd[k];
    else if (k < 96)  g_bpack[k] = 0.f;
    if (k < DS * DM) {
        int n = k >> 6, d = k & 63;
        float a = -expf(logA[d * DS + n]);
        g_A[k] = a;
        g_rA[k] = 1.f / a;
    }
}

// row-wise uniformity: A[d][n] == A[d][0] for all n (fast-path requirement)
__global__ void check_uni(const float* __restrict__ logA)
{
    __shared__ int ok;
    if (threadIdx.x == 0) ok = 1;
    __syncthreads();
    bool bad = false;
    for (int i = threadIdx.x; i < DM * DS; i += 256)
        if (logA[i] != logA[(i / DS) * DS]) bad = true;
    if (bad) atomicAnd(&ok, 0);
    __syncthreads();
    if (threadIdx.x == 0) g_uniA = ok;
}

// ---------------- channel-last circular 3x3 conv, IC=64, 16 oc/block ----------------
// Block = 128 thr = 32 px (1 row) x 4 warp-uniform oc-quads; thread = 4 oc (4 FMA chains).
// Weights pre-transposed [oc][tap][ic] -> straight coalesced smem copy. Fully unrolled.
// grid = (32 rows, OC/16, z).
template <bool RELU>
__global__ __launch_bounds__(128) void conv16s(const float* __restrict__ x,
                                               const float* __restrict__ wgt,
                                               const float* __restrict__ bias,
                                               float* __restrict__ y, int OC)
{
    __shared__ float4 xs[3 * 32 * 17];    // 26 KB
    __shared__ float  ws[16 * 576];       // 36 KB
    __shared__ float  bs[16];
    const int tid = threadIdx.x;
    const int obase = blockIdx.y * 16;
    const int r0 = blockIdx.x;
    x += (size_t)blockIdx.z * DM * HW;
    y += (size_t)blockIdx.z * (size_t)OC * HW;

    const float4* x4 = (const float4*)x;
    for (int k = tid; k < 3 * 32 * 16; k += 128) {
        int lr = k >> 9; int rem = k & 511; int c = rem >> 4; int icv = rem & 15;
        int row = (r0 - 1 + lr) & 31;
        xs[(lr * 32 + c) * 17 + icv] = x4[(((row << 5) + c) << 4) + icv];
    }
    {
        const float4* wsrc = (const float4*)(wgt + (size_t)obase * 576);
        float4* wdst = (float4*)ws;
        for (int k = tid; k < 16 * 144; k += 128) wdst[k] = wsrc[k];
    }
    if (tid < 16) bs[tid] = bias[obase + tid];
    __syncthreads();

    const int q = tid >> 5;            // warp-uniform oc-quad
    const int c = tid & 31;
    const int cm = (c + 31) & 31, cp = (c + 1) & 31;

    float a0 = bs[q * 4 + 0], a1 = bs[q * 4 + 1], a2 = bs[q * 4 + 2], a3 = bs[q * 4 + 3];
    const float4* w0 = (const float4*)&ws[(q * 4 + 0) * 576];
    const float4* w1 = (const float4*)&ws[(q * 4 + 1) * 576];
    const float4* w2 = (const float4*)&ws[(q * 4 + 2) * 576];
    const float4* w3 = (const float4*)&ws[(q * 4 + 3) * 576];

#pragma unroll
    for (int tap = 0; tap < 9; tap++) {
        const int tr = tap / 3, tc = tap - tr * 3;
        const int cx = (tc == 0) ? cm : ((tc == 1) ? c : cp);
        const float4* xp = &xs[(tr * 32 + cx) * 17];
#pragma unroll
        for (int icv = 0; icv < 16; icv++) {
            float4 xv = xp[icv];
            float4 v0 = w0[tap * 16 + icv];
            float4 v1 = w1[tap * 16 + icv];
            float4 v2 = w2[tap * 16 + icv];
            float4 v3 = w3[tap * 16 + icv];
            a0 = fmaf(xv.x, v0.x, fmaf(xv.y, v0.y, fmaf(xv.z, v0.z, fmaf(xv.w, v0.w, a0))));
            a1 = fmaf(xv.x, v1.x, fmaf(xv.y, v1.y, fmaf(xv.z, v1.z, fmaf(xv.w, v1.w, a1))));
            a2 = fmaf(xv.x, v2.x, fmaf(xv.y, v2.y, fmaf(xv.z, v2.z, fmaf(xv.w, v2.w, a2))));
            a3 = fmaf(xv.x, v3.x, fmaf(xv.y, v3.y, fmaf(xv.z, v3.z, fmaf(xv.w, v3.w, a3))));
        }
    }
    if (RELU) {
        a0 = fmaxf(a0, 0.f); a1 = fmaxf(a1, 0.f);
        a2 = fmaxf(a2, 0.f); a3 = fmaxf(a3, 0.f);
    }
    const int px = (r0 << 5) + c;
    float4 o; o.x = a0; o.y = a1; o.z = a2; o.w = a3;
    *(float4*)&y[(size_t)px * OC + obase + q * 4] = o;
}

// ---------------- channel-last conv, IC=1 ----------------
__global__ __launch_bounds__(128) void conv1_cl(const float* __restrict__ x,
                                                const float* __restrict__ wgt,
                                                const float* __restrict__ bias,
                                                float* __restrict__ y)
{
    __shared__ float xs[6 * 32];
    __shared__ float ws[4][9];
    __shared__ float bs[4];
    const int tid = threadIdx.x;
    const int obase = blockIdx.y * 4;
    x += blockIdx.z * HW;
    y += (size_t)blockIdx.z * DM * HW;
    const int r0 = blockIdx.x * 4;
    for (int k = tid; k < 6 * 32; k += 128) {
        int lr = k >> 5, c = k & 31;
        xs[k] = x[(((r0 - 1 + lr) & 31) << 5) + c];
    }
    if (tid < 36) ws[tid / 9][tid % 9] = wgt[(obase + tid / 9) * 9 + tid % 9];
    if (tid < 4)  bs[tid] = bias[obase + tid];
    __syncthreads();

    const int hl = tid >> 5, c = tid & 31;
    const int cm = (c + 31) & 31, cp = (c + 1) & 31;
    float xv[9];
#pragma unroll
    for (int tr = 0; tr < 3; tr++) {
        xv[tr * 3 + 0] = xs[(hl + tr) * 32 + cm];
        xv[tr * 3 + 1] = xs[(hl + tr) * 32 + c];
        xv[tr * 3 + 2] = xs[(hl + tr) * 32 + cp];
    }
    float4 o; float* op = &o.x;
#pragma unroll
    for (int j = 0; j < 4; j++) {
        float a = bs[j];
#pragma unroll
        for (int t9 = 0; t9 < 9; t9++) a = fmaf(xv[t9], ws[j][t9], a);
        op[j] = fmaxf(a, 0.f);
    }
    const int px = blockIdx.x * 128 + tid;
    *(float4*)&y[(size_t)px * DM + obase] = o;
}

// ---------------- channel-last conv, OC=1 ----------------
__global__ __launch_bounds__(128) void conv_out(const float* __restrict__ x,
                                                const float* __restrict__ wgt,
                                                const float* __restrict__ bias,
                                                float* __restrict__ y)
{
    __shared__ float4 xs[3 * 32 * 17];
    __shared__ float  ws[9][64];
    const int tid = threadIdx.x;
    const int r0 = blockIdx.x;
    const float4* x4 = (const float4*)x;
    for (int k = tid; k < 3 * 32 * 16; k += 128) {
        int lr = k >> 9; int rem = k & 511; int c = rem >> 4; int icv = rem & 15;
        int row = (r0 - 1 + lr) & 31;
        xs[(lr * 32 + c) * 17 + icv] = x4[(((row << 5) + c) << 4) + icv];
    }
    for (int k = tid; k < 576; k += 128) {
        int tap = k >> 6, ic = k & 63;
        ws[tap][ic] = wgt[ic * 9 + tap];
    }
    __syncthreads();

    const int icq = tid & 3, c = tid >> 2;
    const int cm = (c + 31) & 31, cp = (c + 1) & 31;
    float acc = 0.f;
#pragma unroll
    for (int tr = 0; tr < 3; tr++) {
#pragma unroll
        for (int tc = 0; tc < 3; tc++) {
            const int cx = (tc == 0) ? cm : ((tc == 1) ? c : cp);
            const float4* xp = &xs[(tr * 32 + cx) * 17];
            const float4* wp = (const float4*)&ws[tr * 3 + tc][0];
#pragma unroll
            for (int k = 0; k < 4; k++) {
                float4 xv = xp[icq * 4 + k];
                float4 wv = wp[icq * 4 + k];
                acc = fmaf(xv.x, wv.x, fmaf(xv.y, wv.y, fmaf(xv.z, wv.z, fmaf(xv.w, wv.w, acc))));
            }
        }
    }
    acc += __shfl_xor_sync(0xffffffffu, acc, 1);
    acc += __shfl_xor_sync(0xffffffffu, acc, 2);
    if (icq == 0) y[(r0 << 5) + c] = acc + bias[0];
}

__device__ __forceinline__ float sp_f(float x) { return (x > 20.f) ? x : log1pf(expf(x)); }

// ---------------- prep: e,f,delta,u,B fields for encode slots ----------------
__global__ __launch_bounds__(128) void prep(const float* __restrict__ cc,
                                            const float* __restrict__ u,
                                            const float* __restrict__ dtp)
{
    const int s = blockIdx.z;
    cc += (size_t)s * HW * 96;
    u  += (size_t)s * HW * 64;
    const int tid = threadIdx.x;
    const int pl = tid >> 4, dq = tid & 15;
    const int p = blockIdx.x * 8 + pl;
    const float dti = dtp[0];

    float4 dc = *(const float4*)&cc[p * 96 + dq * 4];
    float4 dl4;
    dl4.x = sp_f(dc.x + dti); dl4.y = sp_f(dc.y + dti);
    dl4.z = sp_f(dc.z + dti); dl4.w = sp_f(dc.w + dti);
    float4 a4  = *(const float4*)&g_A[dq * 4];
    float4 ra4 = *(const float4*)&g_rA[dq * 4];
    float4 e4, f4;
    e4.x = __expf(dl4.x * a4.x); e4.y = __expf(dl4.y * a4.y);
    e4.z = __expf(dl4.z * a4.z); e4.w = __expf(dl4.w * a4.w);
    float4 u4 = *(const float4*)&u[p * 64 + dq * 4];
    f4.x = (e4.x - 1.f) * ra4.x * u4.x;
    f4.y = (e4.y - 1.f) * ra4.y * u4.y;
    f4.z = (e4.z - 1.f) * ra4.z * u4.z;
    f4.w = (e4.w - 1.f) * ra4.w * u4.w;

    float4* efp = (float4*)g_ef + (((size_t)s * HW + p) * 16 + dq) * 2;
    efp[0] = e4; efp[1] = f4;
    *(float4*)&g_dl[((size_t)s * HW + p) * 64 + dq * 4] = dl4;
    *(float4*)&g_uf[((size_t)s * HW + p) * 64 + dq * 4] = u4;
    g_Bf[((size_t)s * HW + p) * 16 + dq] = cc[p * 96 + 64 + dq];
}

// ---------------- fused y-kernel (decode step S, 1-based) ----------------
__global__ __launch_bounds__(128) void fused_y(const float* __restrict__ cc,
                                               const float* __restrict__ u,
                                               const float* __restrict__ Dskip,
                                               const float* __restrict__ dtp,
                                               int S, float* __restrict__ ymax)
{
    __shared__ float Bs[8][16], Cs[8][16];
    __shared__ float Gs[8][NV][MAXS];
    __shared__ float G0[8];
    const int tid = threadIdx.x;
    const int pl = tid >> 4, dq = tid & 15;
    const int p0 = blockIdx.x * 8;
    const int p = p0 + pl;
    const int h = p >> 5, w = p & 31;
    const int slotS = S - 1;
    const float dti = dtp[0];

    float4 dc = *(const float4*)&cc[p * 96 + dq * 4];
    float4 dl4;
    dl4.x = sp_f(dc.x + dti); dl4.y = sp_f(dc.y + dti);
    dl4.z = sp_f(dc.z + dti); dl4.w = sp_f(dc.w + dti);
    float4 a4  = *(const float4*)&g_A[dq * 4];
    float4 ra4 = *(const float4*)&g_rA[dq * 4];
    float4 e4o, f4o;
    e4o.x = __expf(dl4.x * a4.x); e4o.y = __expf(dl4.y * a4.y);
    e4o.z = __expf(dl4.z * a4.z); e4o.w = __expf(dl4.w * a4.w);
    float4 u4 = *(const float4*)&u[p * 64 + dq * 4];
    f4o.x = (e4o.x - 1.f) * ra4.x * u4.x;
    f4o.y = (e4o.y - 1.f) * ra4.y * u4.y;
    f4o.z = (e4o.z - 1.f) * ra4.z * u4.z;
    f4o.w = (e4o.w - 1.f) * ra4.w * u4.w;

    float4* efp = (float4*)g_ef + (((size_t)slotS * HW + p) * 16 + dq) * 2;
    efp[0] = e4o; efp[1] = f4o;
    *(float4*)&g_dl[((size_t)slotS * HW + p) * 64 + dq * 4] = dl4;
    *(float4*)&g_uf[((size_t)slotS * HW + p) * 64 + dq * 4] = u4;
    float bv = cc[p * 96 + 64 + dq];
    g_Bf[((size_t)slotS * HW + p) * 16 + dq] = bv;
    Bs[pl][dq] = bv;
    Cs[pl][dq] = cc[p * 96 + 80 + dq];
    __syncthreads();

    if (tid < 8) {
        float s = 0.f;
#pragma unroll
        for (int n = 0; n < 16; n++) s += Bs[tid][n] * Cs[tid][n];
        G0[tid] = s;
    }
    const int Sm1 = S - 1;
    const int tot = 8 * NV * Sm1;
    for (int idx = tid; idx < tot; idx += 128) {
        int i = idx / (NV * Sm1);
        int rem = idx - i * (NV * Sm1);
        int v = rem / Sm1;
        int k = rem - v * Sm1 + 1;
        int vx = v / 5 - 2, vy = v % 5 - 2;
        int pp = p0 + i;
        int hh = ((pp >> 5) + k * vy) & 31;
        int ww = ((pp & 31) + k * vx) & 31;
        int x = (hh << 5) + ww;
        const float* bp = &g_Bf[((size_t)(S - 1 - k) * HW + x) * 16];
        float s = 0.f;
#pragma unroll
        for (int n = 0; n < 16; n++) s += bp[n] * Cs[i][n];
        Gs[i][v][k] = s;
    }
    __syncthreads();

    float4 best = {-3e38f, -3e38f, -3e38f, -3e38f};
    if (g_uniA) {
        const float g0 = G0[pl];
#pragma unroll 1
        for (int g = 0; g < 5; g++) {
            float4 P[5], acc[5];
#pragma unroll
            for (int j = 0; j < 5; j++) {
                acc[j].x = f4o.x * g0; acc[j].y = f4o.y * g0;
                acc[j].z = f4o.z * g0; acc[j].w = f4o.w * g0;
                P[j] = e4o;
            }
#pragma unroll 1
            for (int k = 1; k < S; k++) {
#pragma unroll
                for (int j = 0; j < 5; j++) {
                    int v = g * 5 + j;
                    int vx = v / 5 - 2, vy = v % 5 - 2;
                    int hh = (h + k * vy) & 31;
                    int ww = (w + k * vx) & 31;
                    int x = (hh << 5) + ww;
                    const float4* ep = (const float4*)g_ef + (((size_t)(S - 1 - k) * HW + x) * 16 + dq) * 2;
                    float4 ee = ep[0];
                    float4 ff = ep[1];
                    float Gv = Gs[pl][v][k];
                    acc[j].x = fmaf(P[j].x * ff.x, Gv, acc[j].x);
                    acc[j].y = fmaf(P[j].y * ff.y, Gv, acc[j].y);
                    acc[j].z = fmaf(P[j].z * ff.z, Gv, acc[j].z);
                    acc[j].w = fmaf(P[j].w * ff.w, Gv, acc[j].w);
                    P[j].x *= ee.x; P[j].y *= ee.y; P[j].z *= ee.z; P[j].w *= ee.w;
                }
            }
#pragma unroll
            for (int j = 0; j < 5; j++) {
                best.x = fmaxf(best.x, acc[j].x);
                best.y = fmaxf(best.y, acc[j].y);
                best.z = fmaxf(best.z, acc[j].z);
                best.w = fmaxf(best.w, acc[j].w);
            }
        }
    } else {
        // generic A fallback (correct for any A)
#pragma unroll 1
        for (int v = 0; v < NV; v++) {
            int vx = v / 5 - 2, vy = v % 5 - 2;
            float4 accv = {0.f, 0.f, 0.f, 0.f};
#pragma unroll 1
            for (int n = 0; n < 16; n++) {
                float4 an4 = *(const float4*)&g_A[n * 64 + dq * 4];
                float4 rn4 = *(const float4*)&g_rA[n * 64 + dq * 4];
                float C = Cs[pl][n];
                float4 e0;
                e0.x = __expf(dl4.x * an4.x); e0.y = __expf(dl4.y * an4.y);
                e0.z = __expf(dl4.z * an4.z); e0.w = __expf(dl4.w * an4.w);
                float bc = Bs[pl][n] * C;
                float4 P = e0, a4c;
                a4c.x = (e0.x - 1.f) * rn4.x * u4.x * bc;
                a4c.y = (e0.y - 1.f) * rn4.y * u4.y * bc;
                a4c.z = (e0.z - 1.f) * rn4.z * u4.z * bc;
                a4c.w = (e0.w - 1.f) * rn4.w * u4.w * bc;
                for (int k = 1; k < S; k++) {
                    int hh = (h + k * vy) & 31;
                    int ww = (w + k * vx) & 31;
                    int x = (hh << 5) + ww;
                    int sl = S - 1 - k;
                    float4 dl = *(const float4*)&g_dl[((size_t)sl * HW + x) * 64 + dq * 4];
                    float4 uu = *(const float4*)&g_uf[((size_t)sl * HW + x) * 64 + dq * 4];
                    float Bt = g_Bf[((size_t)sl * HW + x) * 16 + n] * C;
                    float4 ee;
                    ee.x = __expf(dl.x * an4.x); ee.y = __expf(dl.y * an4.y);
                    ee.z = __expf(dl.z * an4.z); ee.w = __expf(dl.w * an4.w);
                    a4c.x = fmaf(P.x * (ee.x - 1.f) * rn4.x * uu.x, Bt, a4c.x);
                    a4c.y = fmaf(P.y * (ee.y - 1.f) * rn4.y * uu.y, Bt, a4c.y);
                    a4c.z = fmaf(P.z * (ee.z - 1.f) * rn4.z * uu.z, Bt, a4c.z);
                    a4c.w = fmaf(P.w * (ee.w - 1.f) * rn4.w * uu.w, Bt, a4c.w);
                    P.x *= ee.x; P.y *= ee.y; P.z *= ee.z; P.w *= ee.w;
                }
                accv.x += a4c.x; accv.y += a4c.y; accv.z += a4c.z; accv.w += a4c.w;
            }
            best.x = fmaxf(best.x, accv.x);
            best.y = fmaxf(best.y, accv.y);
            best.z = fmaxf(best.z, accv.z);
            best.w = fmaxf(best.w, accv.w);
        }
    }

    float4 dk = *(const float4*)&Dskip[dq * 4];
    float4 o;
    o.x = fmaf(dk.x, u4.x, best.x);
    o.y = fmaf(dk.y, u4.y, best.y);
    o.z = fmaf(dk.z, u4.z, best.z);
    o.w = fmaf(dk.w, u4.w, best.w);
    *(float4*)&ymax[p * 64 + dq * 4] = o;
}

// ---------------- launch ----------------
extern "C" void kernel_launch(void* const* d_in, const int* in_sizes, int n_in,
                              void* d_out, int out_size)
{
    const float* input_seq = (const float*)d_in[0];
    const float* enc_w1 = (const float*)d_in[1];
    const float* enc_b1 = (const float*)d_in[2];
    const float* enc_w2 = (const float*)d_in[3];
    const float* enc_b2 = (const float*)d_in[4];
    const float* wd     = (const float*)d_in[5];
    const float* bd     = (const float*)d_in[6];
    const float* wB     = (const float*)d_in[7];
    const float* wC     = (const float*)d_in[8];
    const float* logA   = (const float*)d_in[9];
    const float* Dskip  = (const float*)d_in[10];
    const float* dt_inv = (const float*)d_in[11];
    const float* dec_w1 = (const float*)d_in[12];
    const float* dec_b1 = (const float*)d_in[13];
    const float* dec_w2 = (const float*)d_in[14];
    const float* dec_b2 = (const float*)d_in[15];
    const float* dec_w3 = (const float*)d_in[16];
    const float* dec_b3 = (const float*)d_in[17];
    float* out = (float*)d_out;

    float *p_u, *p_e1, *p_cc, *p_wpack, *p_wenc2, *p_wdec1, *p_wdec2, *p_bpack;
    float *p_ymax, *p_d1, *p_d2;
    cudaGetSymbolAddress((void**)&p_u, g_u);
    cudaGetSymbolAddress((void**)&p_e1, g_e1);
    cudaGetSymbolAddress((void**)&p_cc, g_cc);
    cudaGetSymbolAddress((void**)&p_wpack, g_wpack);
    cudaGetSymbolAddress((void**)&p_wenc2, g_wenc2);
    cudaGetSymbolAddress((void**)&p_wdec1, g_wdec1);
    cudaGetSymbolAddress((void**)&p_wdec2, g_wdec2);
    cudaGetSymbolAddress((void**)&p_bpack, g_bpack);
    cudaGetSymbolAddress((void**)&p_ymax, g_ymax);
    cudaGetSymbolAddress((void**)&p_d1, g_d1);
    cudaGetSymbolAddress((void**)&p_d2, g_d2);

    pack_all<<<651, 256>>>(wd, bd, wB, wC, logA, enc_w2, dec_w1, dec_w2);
    check_uni<<<1, 256>>>(logA);

    // ---- encode: batched over 4 frames; history fields only ----
    conv1_cl<<<dim3(8, 16, TIN), 128>>>(input_seq, enc_w1, enc_b1, p_e1);
    conv16s<true><<<dim3(32, 4, TIN), 128>>>(p_e1, p_wenc2, enc_b2, p_u, DM);
    conv16s<false><<<dim3(32, 6, TIN), 128>>>(p_u, p_wpack, p_bpack, p_cc, 96);
    prep<<<dim3(128, 1, TIN), 128>>>(p_cc, p_u, dt_inv);

    // ---- decode ----
    int steps = out_size / HW;
    for (int t = 0; t < steps; t++) {
        const float* src = (t == 0) ? (input_seq + 3 * HW) : (out + (size_t)(t - 1) * HW);
        conv1_cl<<<dim3(8, 16, 1), 128>>>(src, enc_w1, enc_b1, p_e1);
        conv16s<true><<<dim3(32, 4, 1), 128>>>(p_e1, p_wenc2, enc_b2, p_u, DM);
        conv16s<false><<<dim3(32, 6, 1), 128>>>(p_u, p_wpack, p_bpack, p_cc, 96);
        fused_y<<<128, 128>>>(p_cc, p_u, Dskip, dt_inv, TIN + 1 + t, p_ymax);
        conv16s<true><<<dim3(32, 4, 1), 128>>>(p_ymax, p_wdec1, dec_b1, p_d1, DM);
        conv16s<true><<<dim3(32, 4, 1), 128>>>(p_d1, p_wdec2, dec_b2, p_d2, DM);
        conv_out<<<32, 128>>>(p_d2, dec_w3, dec_b3, out + (size_t)t * HW);
    }
}

// round 8
// speedup vs baseline: 1.0554x; 1.0554x over previous
#include <cuda_runtime.h>
#include <math.h>

#define HW   1024
#define DM   64
#define DS   16
#define NV   25
#define TIN  4
#define MAXS 8

// ---------------- scratch (static device globals; no allocation) ----------------
__device__ __align__(128) float g_u[TIN * HW * DM];
__device__ __align__(128) float g_e1[TIN * HW * DM];
__device__ __align__(128) float g_cc[TIN * HW * 96];            // [t][px][dconv|B|C]
__device__ __align__(128) float g_wpack[96 * DM * 9];           // wd|wB|wC raw concat [oc][ic][9]
__device__ __align__(128) float g_bpack[96];
__device__ __align__(128) float g_A[DS * DM];                   // A[n][d] = -exp(logA[d][n])
__device__ __align__(128) float g_rA[DS * DM];
__device__ int   g_uniA;
// history fields, slot s-1 for step s = 1..8
__device__ __align__(128) float g_ef[MAXS * HW * DM * 2];       // [slot][p][dq][{e4,f4}]
__device__ __align__(128) float g_dl[MAXS * HW * DM];           // delta (generic fallback)
__device__ __align__(128) float g_uf[MAXS * HW * DM];           // u history (generic fallback)
__device__ __align__(128) float g_Bf[MAXS * HW * DS];           // B fields [slot][p][n]
__device__ __align__(128) float g_ymax[HW * DM];
__device__ __align__(128) float g_d1[HW * DM];
__device__ __align__(128) float g_d2[HW * DM];

// ---------------- pack weights (raw concat) + A fields ----------------
__global__ void pack_w(const float* __restrict__ wd, const float* __restrict__ bd,
                       const float* __restrict__ wB, const float* __restrict__ wC,
                       const float* __restrict__ logA)
{
    int k = blockIdx.x * 256 + threadIdx.x;
    const int W1 = DM * DM * 9;
    const int W2 = DS * DM * 9;
    if (k < W1)                 g_wpack[k] = wd[k];
    else if (k < W1 + W2)       g_wpack[k] = wB[k - W1];
    else if (k < W1 + 2 * W2)   g_wpack[k] = wC[k - W1 - W2];
    if (k < DM)                 g_bpack[k] = bd[k];
    else if (k < 96)            g_bpack[k] = 0.f;
    if (k < DS * DM) {
        int n = k >> 6, d = k & 63;
        float a = -expf(logA[d * DS + n]);
        g_A[k] = a;
        g_rA[k] = 1.f / a;
    }
}

// row-wise uniformity: A[d][n] == A[d][0] for all n (fast-path requirement)
__global__ void check_uni(const float* __restrict__ logA)
{
    __shared__ int ok;
    if (threadIdx.x == 0) ok = 1;
    __syncthreads();
    bool bad = false;
    for (int i = threadIdx.x; i < DM * DS; i += 256)
        if (logA[i] != logA[(i / DS) * DS]) bad = true;
    if (bad) atomicAnd(&ok, 0);
    __syncthreads();
    if (threadIdx.x == 0) g_uniA = ok;
}

// ---------------- channel-last circular 3x3 conv, IC=64, IC-split halves ----------------
// Block = 128 thr = 32 px (1 row) x 2 oc-pairs x 2 ic-halves. Each half runs the proven
// conv_cl inner loop over 32 ICs; partials combined via tiny smem reduce.
// grid = (32 rows, OC/4, z).
template <bool RELU>
__global__ __launch_bounds__(128) void conv_h(const float* __restrict__ x,
                                              const float* __restrict__ wgt,
                                              const float* __restrict__ bias,
                                              float* __restrict__ y, int OC)
{
    __shared__ float4 xs[3 * 32 * 17];     // 26 KB
    __shared__ float  ws[4][9][64];        // 9 KB
    __shared__ float  bs[4];
    __shared__ float2 red[2][32];
    const int tid = threadIdx.x;
    const int obase = blockIdx.y * 4;
    const int r0 = blockIdx.x;
    x += (size_t)blockIdx.z * DM * HW;
    y += (size_t)blockIdx.z * (size_t)OC * HW;

    const float4* x4 = (const float4*)x;
    for (int k = tid; k < 3 * 32 * 16; k += 128) {
        int lr = k >> 9; int rem = k & 511; int c = rem >> 4; int icv = rem & 15;
        int row = (r0 - 1 + lr) & 31;
        xs[(lr * 32 + c) * 17 + icv] = x4[(((row << 5) + c) << 4) + icv];
    }
    for (int k = tid; k < 4 * 9 * 64; k += 128) {
        int ocl = k / 576; int rem = k - ocl * 576; int tap = rem >> 6; int ic = rem & 63;
        ws[ocl][tap][ic] = wgt[(obase + ocl) * 576 + ic * 9 + tap];
    }
    if (tid < 4) bs[tid] = bias[obase + tid];
    __syncthreads();

    const int half = tid >> 6;             // ic-half
    const int ocp  = (tid >> 5) & 1;       // oc-pair
    const int c    = tid & 31;
    const int cm = (c + 31) & 31, cp = (c + 1) & 31;
    const int hb = half * 8;               // float4 offset into ic dimension

    float a0 = half ? 0.f : bs[ocp * 2];
    float a1 = half ? 0.f : bs[ocp * 2 + 1];
    const float4* w0 = (const float4*)&ws[ocp * 2][0][0];
    const float4* w1 = (const float4*)&ws[ocp * 2 + 1][0][0];

#pragma unroll
    for (int tr = 0; tr < 3; tr++) {
#pragma unroll
        for (int tc = 0; tc < 3; tc++) {
            const int cx = (tc == 0) ? cm : ((tc == 1) ? c : cp);
            const float4* xp  = &xs[(tr * 32 + cx) * 17 + hb];
            const float4* wp0 = w0 + (tr * 3 + tc) * 16 + hb;
            const float4* wp1 = w1 + (tr * 3 + tc) * 16 + hb;
#pragma unroll
            for (int icv = 0; icv < 8; icv++) {
                float4 xv = xp[icv];
                float4 v0 = wp0[icv];
                float4 v1 = wp1[icv];
                a0 = fmaf(xv.x, v0.x, fmaf(xv.y, v0.y, fmaf(xv.z, v0.z, fmaf(xv.w, v0.w, a0))));
                a1 = fmaf(xv.x, v1.x, fmaf(xv.y, v1.y, fmaf(xv.z, v1.z, fmaf(xv.w, v1.w, a1))));
            }
        }
    }
    if (half) {
        float2 r; r.x = a0; r.y = a1;
        red[ocp][c] = r;
    }
    __syncthreads();
    if (!half) {
        float2 r = red[ocp][c];
        a0 += r.x; a1 += r.y;
        if (RELU) { a0 = fmaxf(a0, 0.f); a1 = fmaxf(a1, 0.f); }
        const int px = (r0 << 5) + c;
        float2 o; o.x = a0; o.y = a1;
        *(float2*)&y[(size_t)px * OC + obase + ocp * 2] = o;
    }
}

// ---------------- channel-last conv, IC=1 ----------------
__global__ __launch_bounds__(128) void conv1_cl(const float* __restrict__ x,
                                                const float* __restrict__ wgt,
                                                const float* __restrict__ bias,
                                                float* __restrict__ y)
{
    __shared__ float xs[6 * 32];
    __shared__ float ws[4][9];
    __shared__ float bs[4];
    const int tid = threadIdx.x;
    const int obase = blockIdx.y * 4;
    x += blockIdx.z * HW;
    y += (size_t)blockIdx.z * DM * HW;
    const int r0 = blockIdx.x * 4;
    for (int k = tid; k < 6 * 32; k += 128) {
        int lr = k >> 5, c = k & 31;
        xs[k] = x[(((r0 - 1 + lr) & 31) << 5) + c];
    }
    if (tid < 36) ws[tid / 9][tid % 9] = wgt[(obase + tid / 9) * 9 + tid % 9];
    if (tid < 4)  bs[tid] = bias[obase + tid];
    __syncthreads();

    const int hl = tid >> 5, c = tid & 31;
    const int cm = (c + 31) & 31, cp = (c + 1) & 31;
    float xv[9];
#pragma unroll
    for (int tr = 0; tr < 3; tr++) {
        xv[tr * 3 + 0] = xs[(hl + tr) * 32 + cm];
        xv[tr * 3 + 1] = xs[(hl + tr) * 32 + c];
        xv[tr * 3 + 2] = xs[(hl + tr) * 32 + cp];
    }
    float4 o; float* op = &o.x;
#pragma unroll
    for (int j = 0; j < 4; j++) {
        float a = bs[j];
#pragma unroll
        for (int t9 = 0; t9 < 9; t9++) a = fmaf(xv[t9], ws[j][t9], a);
        op[j] = fmaxf(a, 0.f);
    }
    const int px = blockIdx.x * 128 + tid;
    *(float4*)&y[(size_t)px * DM + obase] = o;
}

// ---------------- channel-last conv, OC=1 ----------------
__global__ __launch_bounds__(128) void conv_out(const float* __restrict__ x,
                                                const float* __restrict__ wgt,
                                                const float* __restrict__ bias,
                                                float* __restrict__ y)
{
    __shared__ float4 xs[3 * 32 * 17];
    __shared__ float  ws[9][64];
    const int tid = threadIdx.x;
    const int r0 = blockIdx.x;
    const float4* x4 = (const float4*)x;
    for (int k = tid; k < 3 * 32 * 16; k += 128) {
        int lr = k >> 9; int rem = k & 511; int c = rem >> 4; int icv = rem & 15;
        int row = (r0 - 1 + lr) & 31;
        xs[(lr * 32 + c) * 17 + icv] = x4[(((row << 5) + c) << 4) + icv];
    }
    for (int k = tid; k < 576; k += 128) {
        int tap = k >> 6, ic = k & 63;
        ws[tap][ic] = wgt[ic * 9 + tap];
    }
    __syncthreads();

    const int icq = tid & 3, c = tid >> 2;
    const int cm = (c + 31) & 31, cp = (c + 1) & 31;
    float acc = 0.f;
#pragma unroll
    for (int tr = 0; tr < 3; tr++) {
#pragma unroll
        for (int tc = 0; tc < 3; tc++) {
            const int cx = (tc == 0) ? cm : ((tc == 1) ? c : cp);
            const float4* xp = &xs[(tr * 32 + cx) * 17];
            const float4* wp = (const float4*)&ws[tr * 3 + tc][0];
#pragma unroll
            for (int k = 0; k < 4; k++) {
                float4 xv = xp[icq * 4 + k];
                float4 wv = wp[icq * 4 + k];
                acc = fmaf(xv.x, wv.x, fmaf(xv.y, wv.y, fmaf(xv.z, wv.z, fmaf(xv.w, wv.w, acc))));
            }
        }
    }
    acc += __shfl_xor_sync(0xffffffffu, acc, 1);
    acc += __shfl_xor_sync(0xffffffffu, acc, 2);
    if (icq == 0) y[(r0 << 5) + c] = acc + bias[0];
}

__device__ __forceinline__ float sp_f(float x) { return (x > 20.f) ? x : log1pf(expf(x)); }

// ---------------- prep: e,f,delta,u,B fields for encode slots ----------------
__global__ __launch_bounds__(128) void prep(const float* __restrict__ cc,
                                            const float* __restrict__ u,
                                            const float* __restrict__ dtp)
{
    const int s = blockIdx.z;
    cc += (size_t)s * HW * 96;
    u  += (size_t)s * HW * 64;
    const int tid = threadIdx.x;
    const int pl = tid >> 4, dq = tid & 15;
    const int p = blockIdx.x * 8 + pl;
    const float dti = dtp[0];

    float4 dc = *(const float4*)&cc[p * 96 + dq * 4];
    float4 dl4;
    dl4.x = sp_f(dc.x + dti); dl4.y = sp_f(dc.y + dti);
    dl4.z = sp_f(dc.z + dti); dl4.w = sp_f(dc.w + dti);
    float4 a4  = *(const float4*)&g_A[dq * 4];
    float4 ra4 = *(const float4*)&g_rA[dq * 4];
    float4 e4, f4;
    e4.x = __expf(dl4.x * a4.x); e4.y = __expf(dl4.y * a4.y);
    e4.z = __expf(dl4.z * a4.z); e4.w = __expf(dl4.w * a4.w);
    float4 u4 = *(const float4*)&u[p * 64 + dq * 4];
    f4.x = (e4.x - 1.f) * ra4.x * u4.x;
    f4.y = (e4.y - 1.f) * ra4.y * u4.y;
    f4.z = (e4.z - 1.f) * ra4.z * u4.z;
    f4.w = (e4.w - 1.f) * ra4.w * u4.w;

    float4* efp = (float4*)g_ef + (((size_t)s * HW + p) * 16 + dq) * 2;
    efp[0] = e4; efp[1] = f4;
    *(float4*)&g_dl[((size_t)s * HW + p) * 64 + dq * 4] = dl4;
    *(float4*)&g_uf[((size_t)s * HW + p) * 64 + dq * 4] = u4;
    g_Bf[((size_t)s * HW + p) * 16 + dq] = cc[p * 96 + 64 + dq];
}

// ---- per-chunk v evaluation helper (uniA fast path) ----
template<int CNT>
__device__ __forceinline__ void yv_chunk(int vbase, int S, int h, int w, int dq,
                                         const float* GsRow, float g0,
                                         float4 e4o, float4 f4o, float4& best)
{
    float4 P[CNT], acc[CNT];
#pragma unroll
    for (int j = 0; j < CNT; j++) {
        acc[j].x = f4o.x * g0; acc[j].y = f4o.y * g0;
        acc[j].z = f4o.z * g0; acc[j].w = f4o.w * g0;
        P[j] = e4o;
    }
#pragma unroll 1
    for (int k = 1; k < S; k++) {
#pragma unroll
        for (int j = 0; j < CNT; j++) {
            int v = vbase + j;
            int vx = v / 5 - 2, vy = v % 5 - 2;
            int hh = (h + k * vy) & 31;
            int ww = (w + k * vx) & 31;
            int x = (hh << 5) + ww;
            const float4* ep = (const float4*)g_ef + (((size_t)(S - 1 - k) * HW + x) * 16 + dq) * 2;
            float4 ee = ep[0];
            float4 ff = ep[1];
            float Gv = GsRow[v * MAXS + k];
            acc[j].x = fmaf(P[j].x * ff.x, Gv, acc[j].x);
            acc[j].y = fmaf(P[j].y * ff.y, Gv, acc[j].y);
            acc[j].z = fmaf(P[j].z * ff.z, Gv, acc[j].z);
            acc[j].w = fmaf(P[j].w * ff.w, Gv, acc[j].w);
            P[j].x *= ee.x; P[j].y *= ee.y; P[j].z *= ee.z; P[j].w *= ee.w;
        }
    }
#pragma unroll
    for (int j = 0; j < CNT; j++) {
        best.x = fmaxf(best.x, acc[j].x);
        best.y = fmaxf(best.y, acc[j].y);
        best.z = fmaxf(best.z, acc[j].z);
        best.w = fmaxf(best.w, acc[j].w);
    }
}

// ---------------- fused y-kernel (decode step S, 1-based), 256 thr, v-split ----------------
__global__ __launch_bounds__(256) void fused_y(const float* __restrict__ cc,
                                               const float* __restrict__ u,
                                               const float* __restrict__ Dskip,
                                               const float* __restrict__ dtp,
                                               int S, float* __restrict__ ymax)
{
    __shared__ float Bs[8][16], Cs[8][16];
    __shared__ float Gs[8][NV][MAXS];
    __shared__ float G0[8];
    __shared__ float4 sb1[8][16];
    const int tid = threadIdx.x;
    const int half = tid >> 7;
    const int t128 = tid & 127;
    const int pl = t128 >> 4, dq = t128 & 15;
    const int p0 = blockIdx.x * 8;
    const int p = p0 + pl;
    const int h = p >> 5, w = p & 31;
    const int slotS = S - 1;
    const float dti = dtp[0];

    // own-step prep (both halves compute; global/smem writes by half 0 only)
    float4 dc = *(const float4*)&cc[p * 96 + dq * 4];
    float4 dl4;
    dl4.x = sp_f(dc.x + dti); dl4.y = sp_f(dc.y + dti);
    dl4.z = sp_f(dc.z + dti); dl4.w = sp_f(dc.w + dti);
    float4 a4  = *(const float4*)&g_A[dq * 4];
    float4 ra4 = *(const float4*)&g_rA[dq * 4];
    float4 e4o, f4o;
    e4o.x = __expf(dl4.x * a4.x); e4o.y = __expf(dl4.y * a4.y);
    e4o.z = __expf(dl4.z * a4.z); e4o.w = __expf(dl4.w * a4.w);
    float4 u4 = *(const float4*)&u[p * 64 + dq * 4];
    f4o.x = (e4o.x - 1.f) * ra4.x * u4.x;
    f4o.y = (e4o.y - 1.f) * ra4.y * u4.y;
    f4o.z = (e4o.z - 1.f) * ra4.z * u4.z;
    f4o.w = (e4o.w - 1.f) * ra4.w * u4.w;

    if (half == 0) {
        float4* efp = (float4*)g_ef + (((size_t)slotS * HW + p) * 16 + dq) * 2;
        efp[0] = e4o; efp[1] = f4o;
        *(float4*)&g_dl[((size_t)slotS * HW + p) * 64 + dq * 4] = dl4;
        *(float4*)&g_uf[((size_t)slotS * HW + p) * 64 + dq * 4] = u4;
        float bv = cc[p * 96 + 64 + dq];
        g_Bf[((size_t)slotS * HW + p) * 16 + dq] = bv;
        Bs[pl][dq] = bv;
        Cs[pl][dq] = cc[p * 96 + 80 + dq];
    }
    __syncthreads();

    if (tid < 8) {
        float s = 0.f;
#pragma unroll
        for (int n = 0; n < 16; n++) s += Bs[tid][n] * Cs[tid][n];
        G0[tid] = s;
    }
    const int Sm1 = S - 1;
    const int tot = 8 * NV * Sm1;
    for (int idx = tid; idx < tot; idx += 256) {
        int i = idx / (NV * Sm1);
        int rem = idx - i * (NV * Sm1);
        int v = rem / Sm1;
        int k = rem - v * Sm1 + 1;
        int vx = v / 5 - 2, vy = v % 5 - 2;
        int pp = p0 + i;
        int hh = ((pp >> 5) + k * vy) & 31;
        int ww = ((pp & 31) + k * vx) & 31;
        int x = (hh << 5) + ww;
        const float* bp = &g_Bf[((size_t)(S - 1 - k) * HW + x) * 16];
        float s = 0.f;
#pragma unroll
        for (int n = 0; n < 16; n++) s += bp[n] * Cs[i][n];
        Gs[i][v][k] = s;
    }
    __syncthreads();

    float4 best = {-3e38f, -3e38f, -3e38f, -3e38f};
    if (g_uniA) {
        const float g0 = G0[pl];
        const float* GsRow = &Gs[pl][0][0];
        if (half == 0) {            // v 0..11
            yv_chunk<4>(0, S, h, w, dq, GsRow, g0, e4o, f4o, best);
            yv_chunk<4>(4, S, h, w, dq, GsRow, g0, e4o, f4o, best);
            yv_chunk<4>(8, S, h, w, dq, GsRow, g0, e4o, f4o, best);
        } else {                    // v 12..24
            yv_chunk<4>(12, S, h, w, dq, GsRow, g0, e4o, f4o, best);
            yv_chunk<4>(16, S, h, w, dq, GsRow, g0, e4o, f4o, best);
            yv_chunk<5>(20, S, h, w, dq, GsRow, g0, e4o, f4o, best);
        }
    } else if (half == 0) {
        // generic A fallback (correct for any A; half 0 covers all 25 v)
#pragma unroll 1
        for (int v = 0; v < NV; v++) {
            int vx = v / 5 - 2, vy = v % 5 - 2;
            float4 accv = {0.f, 0.f, 0.f, 0.f};
#pragma unroll 1
            for (int n = 0; n < 16; n++) {
                float4 an4 = *(const float4*)&g_A[n * 64 + dq * 4];
                float4 rn4 = *(const float4*)&g_rA[n * 64 + dq * 4];
                float C = Cs[pl][n];
                float4 e0;
                e0.x = __expf(dl4.x * an4.x); e0.y = __expf(dl4.y * an4.y);
                e0.z = __expf(dl4.z * an4.z); e0.w = __expf(dl4.w * an4.w);
                float bc = Bs[pl][n] * C;
                float4 P = e0, a4c;
                a4c.x = (e0.x - 1.f) * rn4.x * u4.x * bc;
                a4c.y = (e0.y - 1.f) * rn4.y * u4.y * bc;
                a4c.z = (e0.z - 1.f) * rn4.z * u4.z * bc;
                a4c.w = (e0.w - 1.f) * rn4.w * u4.w * bc;
                for (int k = 1; k < S; k++) {
                    int hh = (h + k * vy) & 31;
                    int ww = (w + k * vx) & 31;
                    int x = (hh << 5) + ww;
                    int sl = S - 1 - k;
                    float4 dl = *(const float4*)&g_dl[((size_t)sl * HW + x) * 64 + dq * 4];
                    float4 uu = *(const float4*)&g_uf[((size_t)sl * HW + x) * 64 + dq * 4];
                    float Bt = g_Bf[((size_t)sl * HW + x) * 16 + n] * C;
                    float4 ee;
                    ee.x = __expf(dl.x * an4.x); ee.y = __expf(dl.y * an4.y);
                    ee.z = __expf(dl.z * an4.z); ee.w = __expf(dl.w * an4.w);
                    a4c.x = fmaf(P.x * (ee.x - 1.f) * rn4.x * uu.x, Bt, a4c.x);
                    a4c.y = fmaf(P.y * (ee.y - 1.f) * rn4.y * uu.y, Bt, a4c.y);
                    a4c.z = fmaf(P.z * (ee.z - 1.f) * rn4.z * uu.z, Bt, a4c.z);
                    a4c.w = fmaf(P.w * (ee.w - 1.f) * rn4.w * uu.w, Bt, a4c.w);
                    P.x *= ee.x; P.y *= ee.y; P.z *= ee.z; P.w *= ee.w;
                }
                accv.x += a4c.x; accv.y += a4c.y; accv.z += a4c.z; accv.w += a4c.w;
            }
            best.x = fmaxf(best.x, accv.x);
            best.y = fmaxf(best.y, accv.y);
            best.z = fmaxf(best.z, accv.z);
            best.w = fmaxf(best.w, accv.w);
        }
    }

    if (half == 1) sb1[pl][dq] = best;
    __syncthreads();
    if (half == 0) {
        float4 b1 = sb1[pl][dq];
        best.x = fmaxf(best.x, b1.x);
        best.y = fmaxf(best.y, b1.y);
        best.z = fmaxf(best.z, b1.z);
        best.w = fmaxf(best.w, b1.w);
        float4 dk = *(const float4*)&Dskip[dq * 4];
        float4 o;
        o.x = fmaf(dk.x, u4.x, best.x);
        o.y = fmaf(dk.y, u4.y, best.y);
        o.z = fmaf(dk.z, u4.z, best.z);
        o.w = fmaf(dk.w, u4.w, best.w);
        *(float4*)&ymax[p * 64 + dq * 4] = o;
    }
}

// ---------------- launch ----------------
extern "C" void kernel_launch(void* const* d_in, const int* in_sizes, int n_in,
                              void* d_out, int out_size)
{
    const float* input_seq = (const float*)d_in[0];
    const float* enc_w1 = (const float*)d_in[1];
    const float* enc_b1 = (const float*)d_in[2];
    const float* enc_w2 = (const float*)d_in[3];
    const float* enc_b2 = (const float*)d_in[4];
    const float* wd     = (const float*)d_in[5];
    const float* bd     = (const float*)d_in[6];
    const float* wB     = (const float*)d_in[7];
    const float* wC     = (const float*)d_in[8];
    const float* logA   = (const float*)d_in[9];
    const float* Dskip  = (const float*)d_in[10];
    const float* dt_inv = (const float*)d_in[11];
    const float* dec_w1 = (const float*)d_in[12];
    const float* dec_b1 = (const float*)d_in[13];
    const float* dec_w2 = (const float*)d_in[14];
    const float* dec_b2 = (const float*)d_in[15];
    const float* dec_w3 = (const float*)d_in[16];
    const float* dec_b3 = (const float*)d_in[17];
    float* out = (float*)d_out;

    float *p_u, *p_e1, *p_cc, *p_wpack, *p_bpack, *p_ymax, *p_d1, *p_d2;
    cudaGetSymbolAddress((void**)&p_u, g_u);
    cudaGetSymbolAddress((void**)&p_e1, g_e1);
    cudaGetSymbolAddress((void**)&p_cc, g_cc);
    cudaGetSymbolAddress((void**)&p_wpack, g_wpack);
    cudaGetSymbolAddress((void**)&p_bpack, g_bpack);
    cudaGetSymbolAddress((void**)&p_ymax, g_ymax);
    cudaGetSymbolAddress((void**)&p_d1, g_d1);
    cudaGetSymbolAddress((void**)&p_d2, g_d2);

    pack_w<<<216, 256>>>(wd, bd, wB, wC, logA);
    check_uni<<<1, 256>>>(logA);

    // ---- encode: batched over 4 frames; history fields only ----
    conv1_cl<<<dim3(8, 16, TIN), 128>>>(input_seq, enc_w1, enc_b1, p_e1);
    conv_h<true><<<dim3(32, 16, TIN), 128>>>(p_e1, enc_w2, enc_b2, p_u, DM);
    conv_h<false><<<dim3(32, 24, TIN), 128>>>(p_u, p_wpack, p_bpack, p_cc, 96);
    prep<<<dim3(128, 1, TIN), 128>>>(p_cc, p_u, dt_inv);

    // ---- decode ----
    int steps = out_size / HW;
    for (int t = 0; t < steps; t++) {
        const float* src = (t == 0) ? (input_seq + 3 * HW) : (out + (size_t)(t - 1) * HW);
        conv1_cl<<<dim3(8, 16, 1), 128>>>(src, enc_w1, enc_b1, p_e1);
        conv_h<true><<<dim3(32, 16, 1), 128>>>(p_e1, enc_w2, enc_b2, p_u, DM);
        conv_h<false><<<dim3(32, 24, 1), 128>>>(p_u, p_wpack, p_bpack, p_cc, 96);
        fused_y<<<128, 256>>>(p_cc, p_u, Dskip, dt_inv, TIN + 1 + t, p_ymax);
        conv_h<true><<<dim3(32, 16, 1), 128>>>(p_ymax, dec_w1, dec_b1, p_d1, DM);
        conv_h<true><<<dim3(32, 16, 1), 128>>>(p_d1, dec_w2, dec_b2, p_d2, DM);
        conv_out<<<32, 128>>>(p_d2, dec_w3, dec_b3, out + (size_t)t * HW);
    }
}

// round 9
// speedup vs baseline: 1.1480x; 1.0877x over previous
#include <cuda_runtime.h>
#include <math.h>

#define HW   1024
#define DM   64
#define DS   16
#define NV   25
#define TIN  4
#define MAXS 8

// packed fp32x2 FMA (sm_100+; only reachable via PTX)
#define FMA2(d, a, b) asm("fma.rn.f32x2 %0, %1, %2, %0;" : "+l"(d) : "l"(a), "l"(b))
#define UNPK2(lo, hi, v) asm("mov.b64 {%0, %1}, %2;" : "=f"(lo), "=f"(hi) : "l"(v))

// ---------------- scratch (static device globals; no allocation) ----------------
__device__ __align__(128) float g_u[TIN * HW * DM];
__device__ __align__(128) float g_e1[TIN * HW * DM];
__device__ __align__(128) float g_cc[TIN * HW * 96];            // [t][px][dconv|B|C]
__device__ __align__(128) float g_wpack[96 * DM * 9];           // wd|wB|wC raw concat [oc][ic][9]
__device__ __align__(128) float g_bpack[96];
__device__ __align__(128) float g_A[DS * DM];                   // A[n][d] = -exp(logA[d][n])
__device__ __align__(128) float g_rA[DS * DM];
__device__ int   g_uniA;
// history fields, slot s-1 for step s = 1..8
__device__ __align__(128) float g_ef[MAXS * HW * DM * 2];       // [slot][p][dq][{e4,f4}]
__device__ __align__(128) float g_dl[MAXS * HW * DM];           // delta (generic fallback)
__device__ __align__(128) float g_uf[MAXS * HW * DM];           // u history (generic fallback)
__device__ __align__(128) float g_Bf[MAXS * HW * DS];           // B fields [slot][p][n]
__device__ __align__(128) float g_ymax[HW * DM];
__device__ __align__(128) float g_d1[HW * DM];
__device__ __align__(128) float g_d2[HW * DM];

// ---------------- pack weights (raw concat) + A fields ----------------
__global__ void pack_w(const float* __restrict__ wd, const float* __restrict__ bd,
                       const float* __restrict__ wB, const float* __restrict__ wC,
                       const float* __restrict__ logA)
{
    int k = blockIdx.x * 256 + threadIdx.x;
    const int W1 = DM * DM * 9;
    const int W2 = DS * DM * 9;
    if (k < W1)                 g_wpack[k] = wd[k];
    else if (k < W1 + W2)       g_wpack[k] = wB[k - W1];
    else if (k < W1 + 2 * W2)   g_wpack[k] = wC[k - W1 - W2];
    if (k < DM)                 g_bpack[k] = bd[k];
    else if (k < 96)            g_bpack[k] = 0.f;
    if (k < DS * DM) {
        int n = k >> 6, d = k & 63;
        float a = -expf(logA[d * DS + n]);
        g_A[k] = a;
        g_rA[k] = 1.f / a;
    }
}

// row-wise uniformity: A[d][n] == A[d][0] for all n (fast-path requirement)
__global__ void check_uni(const float* __restrict__ logA)
{
    __shared__ int ok;
    if (threadIdx.x == 0) ok = 1;
    __syncthreads();
    bool bad = false;
    for (int i = threadIdx.x; i < DM * DS; i += 256)
        if (logA[i] != logA[(i / DS) * DS]) bad = true;
    if (bad) atomicAnd(&ok, 0);
    __syncthreads();
    if (threadIdx.x == 0) g_uniA = ok;
}

// ---------------- f32x2 circular 3x3 conv, IC=64, 2 px/thread, ic-split halves ------
// Block = 128 thr = 32 cols x 2 oc-pairs x 2 ic-halves; block computes 2 output rows
// x 4 oc. Packed f32x2 math (2 MACs/issue); x tap-rows + w loads reused across both px.
// grid = (16 row-pairs, OC/4, z).
template <bool RELU>
__global__ __launch_bounds__(128) void conv_f2(const float* __restrict__ x,
                                               const float* __restrict__ wgt,
                                               const float* __restrict__ bias,
                                               float* __restrict__ y, int OC)
{
    __shared__ float4 xs[4 * 32 * 17];     // 34 KB: rows r0-1 .. r0+2
    __shared__ float  ws[4][9][64];        // 9 KB
    __shared__ float  bs[4];
    __shared__ float4 red[2][32];
    const int tid = threadIdx.x;
    const int obase = blockIdx.y * 4;
    const int r0 = blockIdx.x * 2;         // output rows r0, r0+1
    x += (size_t)blockIdx.z * DM * HW;
    y += (size_t)blockIdx.z * (size_t)OC * HW;

    const float4* x4 = (const float4*)x;
    for (int k = tid; k < 4 * 32 * 16; k += 128) {
        int lr = k >> 9; int rem = k & 511; int c = rem >> 4; int icv = rem & 15;
        int row = (r0 - 1 + lr) & 31;
        xs[(lr * 32 + c) * 17 + icv] = x4[(((row << 5) + c) << 4) + icv];
    }
    for (int k = tid; k < 4 * 9 * 64; k += 128) {
        int ocl = k / 576; int rem = k - ocl * 576; int tap = rem >> 6; int ic = rem & 63;
        ws[ocl][tap][ic] = wgt[(obase + ocl) * 576 + ic * 9 + tap];
    }
    if (tid < 4) bs[tid] = bias[obase + tid];
    __syncthreads();

    const int half = tid >> 6;             // ic-half (0: ic 0-31, 1: ic 32-63)
    const int ocp  = (tid >> 5) & 1;       // oc-pair
    const int c    = tid & 31;
    const int cm = (c + 31) & 31, cp = (c + 1) & 31;
    const int hb = half * 8;               // float4 offset into ic

    unsigned long long a00 = 0ull, a01 = 0ull, a10 = 0ull, a11 = 0ull;

#pragma unroll
    for (int tc = 0; tc < 3; tc++) {
        const int cx = (tc == 0) ? cm : ((tc == 1) ? c : cp);
        const ulonglong2* xr0 = (const ulonglong2*)&xs[(0 * 32 + cx) * 17 + hb];
        const ulonglong2* xr1 = (const ulonglong2*)&xs[(1 * 32 + cx) * 17 + hb];
        const ulonglong2* xr2 = (const ulonglong2*)&xs[(2 * 32 + cx) * 17 + hb];
        const ulonglong2* xr3 = (const ulonglong2*)&xs[(3 * 32 + cx) * 17 + hb];
        const ulonglong2* w0t0 = (const ulonglong2*)&ws[ocp * 2 + 0][0 * 3 + tc][half * 32];
        const ulonglong2* w0t1 = (const ulonglong2*)&ws[ocp * 2 + 0][1 * 3 + tc][half * 32];
        const ulonglong2* w0t2 = (const ulonglong2*)&ws[ocp * 2 + 0][2 * 3 + tc][half * 32];
        const ulonglong2* w1t0 = (const ulonglong2*)&ws[ocp * 2 + 1][0 * 3 + tc][half * 32];
        const ulonglong2* w1t1 = (const ulonglong2*)&ws[ocp * 2 + 1][1 * 3 + tc][half * 32];
        const ulonglong2* w1t2 = (const ulonglong2*)&ws[ocp * 2 + 1][2 * 3 + tc][half * 32];
#pragma unroll
        for (int icv = 0; icv < 8; icv++) {
            ulonglong2 xv0 = xr0[icv];
            ulonglong2 xv1 = xr1[icv];
            ulonglong2 xv2 = xr2[icv];
            ulonglong2 xv3 = xr3[icv];
            ulonglong2 wa, wb;
            // tap row 0: px0 uses xv0, px1 uses xv1
            wa = w0t0[icv]; wb = w1t0[icv];
            FMA2(a00, xv0.x, wa.x); FMA2(a00, xv0.y, wa.y);
            FMA2(a01, xv0.x, wb.x); FMA2(a01, xv0.y, wb.y);
            FMA2(a10, xv1.x, wa.x); FMA2(a10, xv1.y, wa.y);
            FMA2(a11, xv1.x, wb.x); FMA2(a11, xv1.y, wb.y);
            // tap row 1: px0 uses xv1, px1 uses xv2
            wa = w0t1[icv]; wb = w1t1[icv];
            FMA2(a00, xv1.x, wa.x); FMA2(a00, xv1.y, wa.y);
            FMA2(a01, xv1.x, wb.x); FMA2(a01, xv1.y, wb.y);
            FMA2(a10, xv2.x, wa.x); FMA2(a10, xv2.y, wa.y);
            FMA2(a11, xv2.x, wb.x); FMA2(a11, xv2.y, wb.y);
            // tap row 2: px0 uses xv2, px1 uses xv3
            wa = w0t2[icv]; wb = w1t2[icv];
            FMA2(a00, xv2.x, wa.x); FMA2(a00, xv2.y, wa.y);
            FMA2(a01, xv2.x, wb.x); FMA2(a01, xv2.y, wb.y);
            FMA2(a10, xv3.x, wa.x); FMA2(a10, xv3.y, wa.y);
            FMA2(a11, xv3.x, wb.x); FMA2(a11, xv3.y, wb.y);
        }
    }

    float l0, h0, l1, h1, l2, h2, l3, h3;
    UNPK2(l0, h0, a00); UNPK2(l1, h1, a01);
    UNPK2(l2, h2, a10); UNPK2(l3, h3, a11);
    float s00 = l0 + h0, s01 = l1 + h1, s10 = l2 + h2, s11 = l3 + h3;

    if (half) {
        float4 r; r.x = s00; r.y = s01; r.z = s10; r.w = s11;
        red[ocp][c] = r;
    }
    __syncthreads();
    if (!half) {
        float4 r = red[ocp][c];
        float b0 = bs[ocp * 2], b1 = bs[ocp * 2 + 1];
        float o00 = s00 + r.x + b0, o01 = s01 + r.y + b1;
        float o10 = s10 + r.z + b0, o11 = s11 + r.w + b1;
        if (RELU) {
            o00 = fmaxf(o00, 0.f); o01 = fmaxf(o01, 0.f);
            o10 = fmaxf(o10, 0.f); o11 = fmaxf(o11, 0.f);
        }
        const int px0 = (r0 << 5) + c;
        const int px1 = ((r0 + 1) << 5) + c;
        float2 oA; oA.x = o00; oA.y = o01;
        float2 oB; oB.x = o10; oB.y = o11;
        *(float2*)&y[(size_t)px0 * OC + obase + ocp * 2] = oA;
        *(float2*)&y[(size_t)px1 * OC + obase + ocp * 2] = oB;
    }
}

// ---------------- channel-last conv, IC=1 ----------------
__global__ __launch_bounds__(128) void conv1_cl(const float* __restrict__ x,
                                                const float* __restrict__ wgt,
                                                const float* __restrict__ bias,
                                                float* __restrict__ y)
{
    __shared__ float xs[6 * 32];
    __shared__ float ws[4][9];
    __shared__ float bs[4];
    const int tid = threadIdx.x;
    const int obase = blockIdx.y * 4;
    x += blockIdx.z * HW;
    y += (size_t)blockIdx.z * DM * HW;
    const int r0 = blockIdx.x * 4;
    for (int k = tid; k < 6 * 32; k += 128) {
        int lr = k >> 5, c = k & 31;
        xs[k] = x[(((r0 - 1 + lr) & 31) << 5) + c];
    }
    if (tid < 36) ws[tid / 9][tid % 9] = wgt[(obase + tid / 9) * 9 + tid % 9];
    if (tid < 4)  bs[tid] = bias[obase + tid];
    __syncthreads();

    const int hl = tid >> 5, c = tid & 31;
    const int cm = (c + 31) & 31, cp = (c + 1) & 31;
    float xv[9];
#pragma unroll
    for (int tr = 0; tr < 3; tr++) {
        xv[tr * 3 + 0] = xs[(hl + tr) * 32 + cm];
        xv[tr * 3 + 1] = xs[(hl + tr) * 32 + c];
        xv[tr * 3 + 2] = xs[(hl + tr) * 32 + cp];
    }
    float4 o; float* op = &o.x;
#pragma unroll
    for (int j = 0; j < 4; j++) {
        float a = bs[j];
#pragma unroll
        for (int t9 = 0; t9 < 9; t9++) a = fmaf(xv[t9], ws[j][t9], a);
        op[j] = fmaxf(a, 0.f);
    }
    const int px = blockIdx.x * 128 + tid;
    *(float4*)&y[(size_t)px * DM + obase] = o;
}

// ---------------- channel-last conv, OC=1 ----------------
__global__ __launch_bounds__(128) void conv_out(const float* __restrict__ x,
                                                const float* __restrict__ wgt,
                                                const float* __restrict__ bias,
                                                float* __restrict__ y)
{
    __shared__ float4 xs[3 * 32 * 17];
    __shared__ float  ws[9][64];
    const int tid = threadIdx.x;
    const int r0 = blockIdx.x;
    const float4* x4 = (const float4*)x;
    for (int k = tid; k < 3 * 32 * 16; k += 128) {
        int lr = k >> 9; int rem = k & 511; int c = rem >> 4; int icv = rem & 15;
        int row = (r0 - 1 + lr) & 31;
        xs[(lr * 32 + c) * 17 + icv] = x4[(((row << 5) + c) << 4) + icv];
    }
    for (int k = tid; k < 576; k += 128) {
        int tap = k >> 6, ic = k & 63;
        ws[tap][ic] = wgt[ic * 9 + tap];
    }
    __syncthreads();

    const int icq = tid & 3, c = tid >> 2;
    const int cm = (c + 31) & 31, cp = (c + 1) & 31;
    float acc = 0.f;
#pragma unroll
    for (int tr = 0; tr < 3; tr++) {
#pragma unroll
        for (int tc = 0; tc < 3; tc++) {
            const int cx = (tc == 0) ? cm : ((tc == 1) ? c : cp);
            const float4* xp = &xs[(tr * 32 + cx) * 17];
            const float4* wp = (const float4*)&ws[tr * 3 + tc][0];
#pragma unroll
            for (int k = 0; k < 4; k++) {
                float4 xv = xp[icq * 4 + k];
                float4 wv = wp[icq * 4 + k];
                acc = fmaf(xv.x, wv.x, fmaf(xv.y, wv.y, fmaf(xv.z, wv.z, fmaf(xv.w, wv.w, acc))));
            }
        }
    }
    acc += __shfl_xor_sync(0xffffffffu, acc, 1);
    acc += __shfl_xor_sync(0xffffffffu, acc, 2);
    if (icq == 0) y[(r0 << 5) + c] = acc + bias[0];
}

__device__ __forceinline__ float sp_f(float x) { return (x > 20.f) ? x : log1pf(expf(x)); }

// ---------------- prep: e,f,delta,u,B fields for encode slots ----------------
__global__ __launch_bounds__(128) void prep(const float* __restrict__ cc,
                                            const float* __restrict__ u,
                                            const float* __restrict__ dtp)
{
    const int s = blockIdx.z;
    cc += (size_t)s * HW * 96;
    u  += (size_t)s * HW * 64;
    const int tid = threadIdx.x;
    const int pl = tid >> 4, dq = tid & 15;
    const int p = blockIdx.x * 8 + pl;
    const float dti = dtp[0];

    float4 dc = *(const float4*)&cc[p * 96 + dq * 4];
    float4 dl4;
    dl4.x = sp_f(dc.x + dti); dl4.y = sp_f(dc.y + dti);
    dl4.z = sp_f(dc.z + dti); dl4.w = sp_f(dc.w + dti);
    float4 a4  = *(const float4*)&g_A[dq * 4];
    float4 ra4 = *(const float4*)&g_rA[dq * 4];
    float4 e4, f4;
    e4.x = __expf(dl4.x * a4.x); e4.y = __expf(dl4.y * a4.y);
    e4.z = __expf(dl4.z * a4.z); e4.w = __expf(dl4.w * a4.w);
    float4 u4 = *(const float4*)&u[p * 64 + dq * 4];
    f4.x = (e4.x - 1.f) * ra4.x * u4.x;
    f4.y = (e4.y - 1.f) * ra4.y * u4.y;
    f4.z = (e4.z - 1.f) * ra4.z * u4.z;
    f4.w = (e4.w - 1.f) * ra4.w * u4.w;

    float4* efp = (float4*)g_ef + (((size_t)s * HW + p) * 16 + dq) * 2;
    efp[0] = e4; efp[1] = f4;
    *(float4*)&g_dl[((size_t)s * HW + p) * 64 + dq * 4] = dl4;
    *(float4*)&g_uf[((size_t)s * HW + p) * 64 + dq * 4] = u4;
    g_Bf[((size_t)s * HW + p) * 16 + dq] = cc[p * 96 + 64 + dq];
}

// ---------------- fused y-kernel (decode step S, 1-based) ----------------
__global__ __launch_bounds__(128) void fused_y(const float* __restrict__ cc,
                                               const float* __restrict__ u,
                                               const float* __restrict__ Dskip,
                                               const float* __restrict__ dtp,
                                               int S, float* __restrict__ ymax)
{
    __shared__ float Bs[8][16], Cs[8][16];
    __shared__ float Gs[8][NV][MAXS];
    __shared__ float G0[8];
    const int tid = threadIdx.x;
    const int pl = tid >> 4, dq = tid & 15;
    const int p0 = blockIdx.x * 8;
    const int p = p0 + pl;
    const int h = p >> 5, w = p & 31;
    const int slotS = S - 1;
    const float dti = dtp[0];

    float4 dc = *(const float4*)&cc[p * 96 + dq * 4];
    float4 dl4;
    dl4.x = sp_f(dc.x + dti); dl4.y = sp_f(dc.y + dti);
    dl4.z = sp_f(dc.z + dti); dl4.w = sp_f(dc.w + dti);
    float4 a4  = *(const float4*)&g_A[dq * 4];
    float4 ra4 = *(const float4*)&g_rA[dq * 4];
    float4 e4o, f4o;
    e4o.x = __expf(dl4.x * a4.x); e4o.y = __expf(dl4.y * a4.y);
    e4o.z = __expf(dl4.z * a4.z); e4o.w = __expf(dl4.w * a4.w);
    float4 u4 = *(const float4*)&u[p * 64 + dq * 4];
    f4o.x = (e4o.x - 1.f) * ra4.x * u4.x;
    f4o.y = (e4o.y - 1.f) * ra4.y * u4.y;
    f4o.z = (e4o.z - 1.f) * ra4.z * u4.z;
    f4o.w = (e4o.w - 1.f) * ra4.w * u4.w;

    float4* efp = (float4*)g_ef + (((size_t)slotS * HW + p) * 16 + dq) * 2;
    efp[0] = e4o; efp[1] = f4o;
    *(float4*)&g_dl[((size_t)slotS * HW + p) * 64 + dq * 4] = dl4;
    *(float4*)&g_uf[((size_t)slotS * HW + p) * 64 + dq * 4] = u4;
    float bv = cc[p * 96 + 64 + dq];
    g_Bf[((size_t)slotS * HW + p) * 16 + dq] = bv;
    Bs[pl][dq] = bv;
    Cs[pl][dq] = cc[p * 96 + 80 + dq];
    __syncthreads();

    if (tid < 8) {
        float s = 0.f;
#pragma unroll
        for (int n = 0; n < 16; n++) s += Bs[tid][n] * Cs[tid][n];
        G0[tid] = s;
    }
    const int Sm1 = S - 1;
    const int tot = 8 * NV * Sm1;
    for (int idx = tid; idx < tot; idx += 128) {
        int i = idx / (NV * Sm1);
        int rem = idx - i * (NV * Sm1);
        int v = rem / Sm1;
        int k = rem - v * Sm1 + 1;
        int vx = v / 5 - 2, vy = v % 5 - 2;
        int pp = p0 + i;
        int hh = ((pp >> 5) + k * vy) & 31;
        int ww = ((pp & 31) + k * vx) & 31;
        int x = (hh << 5) + ww;
        const float* bp = &g_Bf[((size_t)(S - 1 - k) * HW + x) * 16];
        float s = 0.f;
#pragma unroll
        for (int n = 0; n < 16; n++) s += bp[n] * Cs[i][n];
        Gs[i][v][k] = s;
    }
    __syncthreads();

    float4 best = {-3e38f, -3e38f, -3e38f, -3e38f};
    if (g_uniA) {
        const float g0 = G0[pl];
#pragma unroll 1
        for (int g = 0; g < 5; g++) {
            float4 P[5], acc[5];
#pragma unroll
            for (int j = 0; j < 5; j++) {
                acc[j].x = f4o.x * g0; acc[j].y = f4o.y * g0;
                acc[j].z = f4o.z * g0; acc[j].w = f4o.w * g0;
                P[j] = e4o;
            }
#pragma unroll 1
            for (int k = 1; k < S; k++) {
#pragma unroll
                for (int j = 0; j < 5; j++) {
                    int v = g * 5 + j;
                    int vx = v / 5 - 2, vy = v % 5 - 2;
                    int hh = (h + k * vy) & 31;
                    int ww = (w + k * vx) & 31;
                    int x = (hh << 5) + ww;
                    const float4* ep = (const float4*)g_ef + (((size_t)(S - 1 - k) * HW + x) * 16 + dq) * 2;
                    float4 ee = ep[0];
                    float4 ff = ep[1];
                    float Gv = Gs[pl][v][k];
                    acc[j].x = fmaf(P[j].x * ff.x, Gv, acc[j].x);
                    acc[j].y = fmaf(P[j].y * ff.y, Gv, acc[j].y);
                    acc[j].z = fmaf(P[j].z * ff.z, Gv, acc[j].z);
                    acc[j].w = fmaf(P[j].w * ff.w, Gv, acc[j].w);
                    P[j].x *= ee.x; P[j].y *= ee.y; P[j].z *= ee.z; P[j].w *= ee.w;
                }
            }
#pragma unroll
            for (int j = 0; j < 5; j++) {
                best.x = fmaxf(best.x, acc[j].x);
                best.y = fmaxf(best.y, acc[j].y);
                best.z = fmaxf(best.z, acc[j].z);
                best.w = fmaxf(best.w, acc[j].w);
            }
        }
    } else {
        // generic A fallback (correct for any A)
#pragma unroll 1
        for (int v = 0; v < NV; v++) {
            int vx = v / 5 - 2, vy = v % 5 - 2;
            float4 accv = {0.f, 0.f, 0.f, 0.f};
#pragma unroll 1
            for (int n = 0; n < 16; n++) {
                float4 an4 = *(const float4*)&g_A[n * 64 + dq * 4];
                float4 rn4 = *(const float4*)&g_rA[n * 64 + dq * 4];
                float C = Cs[pl][n];
                float4 e0;
                e0.x = __expf(dl4.x * an4.x); e0.y = __expf(dl4.y * an4.y);
                e0.z = __expf(dl4.z * an4.z); e0.w = __expf(dl4.w * an4.w);
                float bc = Bs[pl][n] * C;
                float4 P = e0, a4c;
                a4c.x = (e0.x - 1.f) * rn4.x * u4.x * bc;
                a4c.y = (e0.y - 1.f) * rn4.y * u4.y * bc;
                a4c.z = (e0.z - 1.f) * rn4.z * u4.z * bc;
                a4c.w = (e0.w - 1.f) * rn4.w * u4.w * bc;
                for (int k = 1; k < S; k++) {
                    int hh = (h + k * vy) & 31;
                    int ww = (w + k * vx) & 31;
                    int x = (hh << 5) + ww;
                    int sl = S - 1 - k;
                    float4 dl = *(const float4*)&g_dl[((size_t)sl * HW + x) * 64 + dq * 4];
                    float4 uu = *(const float4*)&g_uf[((size_t)sl * HW + x) * 64 + dq * 4];
                    float Bt = g_Bf[((size_t)sl * HW + x) * 16 + n] * C;
                    float4 ee;
                    ee.x = __expf(dl.x * an4.x); ee.y = __expf(dl.y * an4.y);
                    ee.z = __expf(dl.z * an4.z); ee.w = __expf(dl.w * an4.w);
                    a4c.x = fmaf(P.x * (ee.x - 1.f) * rn4.x * uu.x, Bt, a4c.x);
                    a4c.y = fmaf(P.y * (ee.y - 1.f) * rn4.y * uu.y, Bt, a4c.y);
                    a4c.z = fmaf(P.z * (ee.z - 1.f) * rn4.z * uu.z, Bt, a4c.z);
                    a4c.w = fmaf(P.w * (ee.w - 1.f) * rn4.w * uu.w, Bt, a4c.w);
                    P.x *= ee.x; P.y *= ee.y; P.z *= ee.z; P.w *= ee.w;
                }
                accv.x += a4c.x; accv.y += a4c.y; accv.z += a4c.z; accv.w += a4c.w;
            }
            best.x = fmaxf(best.x, accv.x);
            best.y = fmaxf(best.y, accv.y);
            best.z = fmaxf(best.z, accv.z);
            best.w = fmaxf(best.w, accv.w);
        }
    }

    float4 dk = *(const float4*)&Dskip[dq * 4];
    float4 o;
    o.x = fmaf(dk.x, u4.x, best.x);
    o.y = fmaf(dk.y, u4.y, best.y);
    o.z = fmaf(dk.z, u4.z, best.z);
    o.w = fmaf(dk.w, u4.w, best.w);
    *(float4*)&ymax[p * 64 + dq * 4] = o;
}

// ---------------- launch ----------------
extern "C" void kernel_launch(void* const* d_in, const int* in_sizes, int n_in,
                              void* d_out, int out_size)
{
    const float* input_seq = (const float*)d_in[0];
    const float* enc_w1 = (const float*)d_in[1];
    const float* enc_b1 = (const float*)d_in[2];
    const float* enc_w2 = (const float*)d_in[3];
    const float* enc_b2 = (const float*)d_in[4];
    const float* wd     = (const float*)d_in[5];
    const float* bd     = (const float*)d_in[6];
    const float* wB     = (const float*)d_in[7];
    const float* wC     = (const float*)d_in[8];
    const float* logA   = (const float*)d_in[9];
    const float* Dskip  = (const float*)d_in[10];
    const float* dt_inv = (const float*)d_in[11];
    const float* dec_w1 = (const float*)d_in[12];
    const float* dec_b1 = (const float*)d_in[13];
    const float* dec_w2 = (const float*)d_in[14];
    const float* dec_b2 = (const float*)d_in[15];
    const float* dec_w3 = (const float*)d_in[16];
    const float* dec_b3 = (const float*)d_in[17];
    float* out = (float*)d_out;

    float *p_u, *p_e1, *p_cc, *p_wpack, *p_bpack, *p_ymax, *p_d1, *p_d2;
    cudaGetSymbolAddress((void**)&p_u, g_u);
    cudaGetSymbolAddress((void**)&p_e1, g_e1);
    cudaGetSymbolAddress((void**)&p_cc, g_cc);
    cudaGetSymbolAddress((void**)&p_wpack, g_wpack);
    cudaGetSymbolAddress((void**)&p_bpack, g_bpack);
    cudaGetSymbolAddress((void**)&p_ymax, g_ymax);
    cudaGetSymbolAddress((void**)&p_d1, g_d1);
    cudaGetSymbolAddress((void**)&p_d2, g_d2);

    pack_w<<<216, 256>>>(wd, bd, wB, wC, logA);
    check_uni<<<1, 256>>>(logA);

    // ---- encode: batched over 4 frames; history fields only ----
    conv1_cl<<<dim3(8, 16, TIN), 128>>>(input_seq, enc_w1, enc_b1, p_e1);
    conv_f2<true><<<dim3(16, 16, TIN), 128>>>(p_e1, enc_w2, enc_b2, p_u, DM);
    conv_f2<false><<<dim3(16, 24, TIN), 128>>>(p_u, p_wpack, p_bpack, p_cc, 96);
    prep<<<dim3(128, 1, TIN), 128>>>(p_cc, p_u, dt_inv);

    // ---- decode ----
    int steps = out_size / HW;
    for (int t = 0; t < steps; t++) {
        const float* src = (t == 0) ? (input_seq + 3 * HW) : (out + (size_t)(t - 1) * HW);
        conv1_cl<<<dim3(8, 16, 1), 128>>>(src, enc_w1, enc_b1, p_e1);
        conv_f2<true><<<dim3(16, 16, 1), 128>>>(p_e1, enc_w2, enc_b2, p_u, DM);
        conv_f2<false><<<dim3(16, 24, 1), 128>>>(p_u, p_wpack, p_bpack, p_cc, 96);
        fused_y<<<128, 128>>>(p_cc, p_u, Dskip, dt_inv, TIN + 1 + t, p_ymax);
        conv_f2<true><<<dim3(16, 16, 1), 128>>>(p_ymax, dec_w1, dec_b1, p_d1, DM);
        conv_f2<true><<<dim3(16, 16, 1), 128>>>(p_d1, dec_w2, dec_b2, p_d2, DM);
        conv_out<<<32, 128>>>(p_d2, dec_w3, dec_b3, out + (size_t)t * HW);
    }
}

// round 11
// speedup vs baseline: 1.2044x; 1.0491x over previous
#include <cuda_runtime.h>
#include <math.h>

#define HW   1024
#define DM   64
#define DS   16
#define NV   25
#define TIN  4
#define MAXS 8

// packed fp32x2 FMA (sm_100+; only reachable via PTX)
#define FMA2(d, a, b) asm("fma.rn.f32x2 %0, %1, %2, %0;" : "+l"(d) : "l"(a), "l"(b))
#define UNPK2(lo, hi, v) asm("mov.b64 {%0, %1}, %2;" : "=f"(lo), "=f"(hi) : "l"(v))

// ---------------- scratch (static device globals; no allocation) ----------------
__device__ __align__(128) float g_u[TIN * HW * DM];
__device__ __align__(128) float g_e1[TIN * HW * DM];
__device__ __align__(128) float g_cc[TIN * HW * 96];            // [t][px][dconv|B|C]
__device__ __align__(128) float g_wpack[96 * DM * 9];           // wd|wB|wC raw concat [oc][ic][9]
__device__ __align__(128) float g_bpack[96];
__device__ __align__(128) float g_A[DS * DM];                   // A[n][d] = -exp(logA[d][n])
__device__ __align__(128) float g_rA[DS * DM];
__device__ int   g_uniA;
// history fields, slot s-1 for step s = 1..8
__device__ __align__(128) float g_ef[MAXS * HW * DM * 2];       // [slot][p][dq][{e4,f4}]
__device__ __align__(128) float g_dl[MAXS * HW * DM];           // delta (generic fallback)
__device__ __align__(128) float g_uf[MAXS * HW * DM];           // u history (generic fallback)
__device__ __align__(128) float g_Bf[MAXS * HW * DS];           // B fields [slot][p][n]
__device__ __align__(128) float g_ymax[HW * DM];
__device__ __align__(128) float g_d1[HW * DM];
__device__ __align__(128) float g_d2[HW * DM];

// ---------------- pack weights (raw concat) + A fields ----------------
__global__ void pack_w(const float* __restrict__ wd, const float* __restrict__ bd,
                       const float* __restrict__ wB, const float* __restrict__ wC,
                       const float* __restrict__ logA)
{
    int k = blockIdx.x * 256 + threadIdx.x;
    const int W1 = DM * DM * 9;
    const int W2 = DS * DM * 9;
    if (k < W1)                 g_wpack[k] = wd[k];
    else if (k < W1 + W2)       g_wpack[k] = wB[k - W1];
    else if (k < W1 + 2 * W2)   g_wpack[k] = wC[k - W1 - W2];
    if (k < DM)                 g_bpack[k] = bd[k];
    else if (k < 96)            g_bpack[k] = 0.f;
    if (k < DS * DM) {
        int n = k >> 6, d = k & 63;
        float a = -expf(logA[d * DS + n]);
        g_A[k] = a;
        g_rA[k] = 1.f / a;
    }
}

// row-wise uniformity: A[d][n] == A[d][0] for all n (fast-path requirement)
__global__ void check_uni(const float* __restrict__ logA)
{
    __shared__ int ok;
    if (threadIdx.x == 0) ok = 1;
    __syncthreads();
    bool bad = false;
    for (int i = threadIdx.x; i < DM * DS; i += 256)
        if (logA[i] != logA[(i / DS) * DS]) bad = true;
    if (bad) atomicAnd(&ok, 0);
    __syncthreads();
    if (threadIdx.x == 0) g_uniA = ok;
}

// ---------------- f32x2 conv, 4 rows/thread (batched path) ----------------
// Block = 128 thr = 32 c x 2 ocp x 2 ic-half; computes 4 rows x 4 oc.
// grid = (8 row-quads, OC/4, z). 6 staged x rows serve 12 tap-row uses.
template <bool RELU>
__global__ __launch_bounds__(128) void conv_f4(const float* __restrict__ x,
                                               const float* __restrict__ wgt,
                                               const float* __restrict__ bias,
                                               float* __restrict__ y, int OC)
{
    __shared__ float4 xs[6 * 32 * 17];     // 51 KB: rows r0-1 .. r0+4
    __shared__ float  ws[4][9][64];        // 9 KB
    __shared__ float  bs[4];
    __shared__ float4 red[2][32][2];
    const int tid = threadIdx.x;
    const int obase = blockIdx.y * 4;
    const int r0 = blockIdx.x * 4;
    x += (size_t)blockIdx.z * DM * HW;
    y += (size_t)blockIdx.z * (size_t)OC * HW;

    const float4* x4 = (const float4*)x;
    for (int k = tid; k < 6 * 32 * 16; k += 128) {
        int lr = k >> 9; int rem = k & 511; int c = rem >> 4; int icv = rem & 15;
        int row = (r0 - 1 + lr) & 31;
        xs[(lr * 32 + c) * 17 + icv] = x4[(((row << 5) + c) << 4) + icv];
    }
    for (int k = tid; k < 4 * 9 * 64; k += 128) {
        int ocl = k / 576; int rem = k - ocl * 576; int tap = rem >> 6; int ic = rem & 63;
        ws[ocl][tap][ic] = wgt[(obase + ocl) * 576 + ic * 9 + tap];
    }
    if (tid < 4) bs[tid] = bias[obase + tid];
    __syncthreads();

    const int half = tid >> 6;
    const int ocp  = (tid >> 5) & 1;
    const int c    = tid & 31;
    const int cm = (c + 31) & 31, cp = (c + 1) & 31;
    const int hb = half * 8;

    unsigned long long acc[4][2];
#pragma unroll
    for (int p = 0; p < 4; p++) { acc[p][0] = 0ull; acc[p][1] = 0ull; }

#pragma unroll
    for (int tc = 0; tc < 3; tc++) {
        const int cx = (tc == 0) ? cm : ((tc == 1) ? c : cp);
        const ulonglong2* xr[6];
#pragma unroll
        for (int r = 0; r < 6; r++) xr[r] = (const ulonglong2*)&xs[(r * 32 + cx) * 17 + hb];
        const ulonglong2* w0t[3];
        const ulonglong2* w1t[3];
#pragma unroll
        for (int tr = 0; tr < 3; tr++) {
            w0t[tr] = (const ulonglong2*)&ws[ocp * 2 + 0][tr * 3 + tc][half * 32];
            w1t[tr] = (const ulonglong2*)&ws[ocp * 2 + 1][tr * 3 + tc][half * 32];
        }
#pragma unroll
        for (int icv = 0; icv < 8; icv++) {
            ulonglong2 xv[6];
#pragma unroll
            for (int r = 0; r < 6; r++) xv[r] = xr[r][icv];
#pragma unroll
            for (int tr = 0; tr < 3; tr++) {
                ulonglong2 wa = w0t[tr][icv];
                ulonglong2 wb = w1t[tr][icv];
#pragma unroll
                for (int p = 0; p < 4; p++) {
                    FMA2(acc[p][0], xv[p + tr].x, wa.x); FMA2(acc[p][0], xv[p + tr].y, wa.y);
                    FMA2(acc[p][1], xv[p + tr].x, wb.x); FMA2(acc[p][1], xv[p + tr].y, wb.y);
                }
            }
        }
    }

    float s[4][2];
#pragma unroll
    for (int p = 0; p < 4; p++) {
        float lo, hi;
        UNPK2(lo, hi, acc[p][0]); s[p][0] = lo + hi;
        UNPK2(lo, hi, acc[p][1]); s[p][1] = lo + hi;
    }

    if (half) {
        float4 rA; rA.x = s[0][0]; rA.y = s[0][1]; rA.z = s[1][0]; rA.w = s[1][1];
        float4 rB; rB.x = s[2][0]; rB.y = s[2][1]; rB.z = s[3][0]; rB.w = s[3][1];
        red[ocp][c][0] = rA; red[ocp][c][1] = rB;
    }
    __syncthreads();
    if (!half) {
        float4 rA = red[ocp][c][0];
        float4 rB = red[ocp][c][1];
        float b0 = bs[ocp * 2], b1 = bs[ocp * 2 + 1];
        float o[4][2];
        o[0][0] = s[0][0] + rA.x + b0; o[0][1] = s[0][1] + rA.y + b1;
        o[1][0] = s[1][0] + rA.z + b0; o[1][1] = s[1][1] + rA.w + b1;
        o[2][0] = s[2][0] + rB.x + b0; o[2][1] = s[2][1] + rB.y + b1;
        o[3][0] = s[3][0] + rB.z + b0; o[3][1] = s[3][1] + rB.w + b1;
#pragma unroll
        for (int p = 0; p < 4; p++) {
            float v0 = o[p][0], v1 = o[p][1];
            if (RELU) { v0 = fmaxf(v0, 0.f); v1 = fmaxf(v1, 0.f); }
            const int px = ((r0 + p) << 5) + c;
            float2 ov; ov.x = v0; ov.y = v1;
            *(float2*)&y[(size_t)px * OC + obase + ocp * 2] = ov;
        }
    }
}

// ---------------- f32x2 conv, 2 rows/thread (single-frame path, R9-proven) ----------
template <bool RELU>
__global__ __launch_bounds__(128) void conv_f2(const float* __restrict__ x,
                                               const float* __restrict__ wgt,
                                               const float* __restrict__ bias,
                                               float* __restrict__ y, int OC)
{
    __shared__ float4 xs[4 * 32 * 17];
    __shared__ float  ws[4][9][64];
    __shared__ float  bs[4];
    __shared__ float4 red[2][32];
    const int tid = threadIdx.x;
    const int obase = blockIdx.y * 4;
    const int r0 = blockIdx.x * 2;
    x += (size_t)blockIdx.z * DM * HW;
    y += (size_t)blockIdx.z * (size_t)OC * HW;

    const float4* x4 = (const float4*)x;
    for (int k = tid; k < 4 * 32 * 16; k += 128) {
        int lr = k >> 9; int rem = k & 511; int c = rem >> 4; int icv = rem & 15;
        int row = (r0 - 1 + lr) & 31;
        xs[(lr * 32 + c) * 17 + icv] = x4[(((row << 5) + c) << 4) + icv];
    }
    for (int k = tid; k < 4 * 9 * 64; k += 128) {
        int ocl = k / 576; int rem = k - ocl * 576; int tap = rem >> 6; int ic = rem & 63;
        ws[ocl][tap][ic] = wgt[(obase + ocl) * 576 + ic * 9 + tap];
    }
    if (tid < 4) bs[tid] = bias[obase + tid];
    __syncthreads();

    const int half = tid >> 6;
    const int ocp  = (tid >> 5) & 1;
    const int c    = tid & 31;
    const int cm = (c + 31) & 31, cp = (c + 1) & 31;
    const int hb = half * 8;

    unsigned long long a00 = 0ull, a01 = 0ull, a10 = 0ull, a11 = 0ull;

#pragma unroll
    for (int tc = 0; tc < 3; tc++) {
        const int cx = (tc == 0) ? cm : ((tc == 1) ? c : cp);
        const ulonglong2* xr0 = (const ulonglong2*)&xs[(0 * 32 + cx) * 17 + hb];
        const ulonglong2* xr1 = (const ulonglong2*)&xs[(1 * 32 + cx) * 17 + hb];
        const ulonglong2* xr2 = (const ulonglong2*)&xs[(2 * 32 + cx) * 17 + hb];
        const ulonglong2* xr3 = (const ulonglong2*)&xs[(3 * 32 + cx) * 17 + hb];
        const ulonglong2* w0t0 = (const ulonglong2*)&ws[ocp * 2 + 0][0 * 3 + tc][half * 32];
        const ulonglong2* w0t1 = (const ulonglong2*)&ws[ocp * 2 + 0][1 * 3 + tc][half * 32];
        const ulonglong2* w0t2 = (const ulonglong2*)&ws[ocp * 2 + 0][2 * 3 + tc][half * 32];
        const ulonglong2* w1t0 = (const ulonglong2*)&ws[ocp * 2 + 1][0 * 3 + tc][half * 32];
        const ulonglong2* w1t1 = (const ulonglong2*)&ws[ocp * 2 + 1][1 * 3 + tc][half * 32];
        const ulonglong2* w1t2 = (const ulonglong2*)&ws[ocp * 2 + 1][2 * 3 + tc][half * 32];
#pragma unroll
        for (int icv = 0; icv < 8; icv++) {
            ulonglong2 xv0 = xr0[icv];
            ulonglong2 xv1 = xr1[icv];
            ulonglong2 xv2 = xr2[icv];
            ulonglong2 xv3 = xr3[icv];
            ulonglong2 wa, wb;
            wa = w0t0[icv]; wb = w1t0[icv];
            FMA2(a00, xv0.x, wa.x); FMA2(a00, xv0.y, wa.y);
            FMA2(a01, xv0.x, wb.x); FMA2(a01, xv0.y, wb.y);
            FMA2(a10, xv1.x, wa.x); FMA2(a10, xv1.y, wa.y);
            FMA2(a11, xv1.x, wb.x); FMA2(a11, xv1.y, wb.y);
            wa = w0t1[icv]; wb = w1t1[icv];
            FMA2(a00, xv1.x, wa.x); FMA2(a00, xv1.y, wa.y);
            FMA2(a01, xv1.x, wb.x); FMA2(a01, xv1.y, wb.y);
            FMA2(a10, xv2.x, wa.x); FMA2(a10, xv2.y, wa.y);
            FMA2(a11, xv2.x, wb.x); FMA2(a11, xv2.y, wb.y);
            wa = w0t2[icv]; wb = w1t2[icv];
            FMA2(a00, xv2.x, wa.x); FMA2(a00, xv2.y, wa.y);
            FMA2(a01, xv2.x, wb.x); FMA2(a01, xv2.y, wb.y);
            FMA2(a10, xv3.x, wa.x); FMA2(a10, xv3.y, wa.y);
            FMA2(a11, xv3.x, wb.x); FMA2(a11, xv3.y, wb.y);
        }
    }

    float l0, h0, l1, h1, l2, h2, l3, h3;
    UNPK2(l0, h0, a00); UNPK2(l1, h1, a01);
    UNPK2(l2, h2, a10); UNPK2(l3, h3, a11);
    float s00 = l0 + h0, s01 = l1 + h1, s10 = l2 + h2, s11 = l3 + h3;

    if (half) {
        float4 r; r.x = s00; r.y = s01; r.z = s10; r.w = s11;
        red[ocp][c] = r;
    }
    __syncthreads();
    if (!half) {
        float4 r = red[ocp][c];
        float b0 = bs[ocp * 2], b1 = bs[ocp * 2 + 1];
        float o00 = s00 + r.x + b0, o01 = s01 + r.y + b1;
        float o10 = s10 + r.z + b0, o11 = s11 + r.w + b1;
        if (RELU) {
            o00 = fmaxf(o00, 0.f); o01 = fmaxf(o01, 0.f);
            o10 = fmaxf(o10, 0.f); o11 = fmaxf(o11, 0.f);
        }
        const int px0 = (r0 << 5) + c;
        const int px1 = ((r0 + 1) << 5) + c;
        float2 oA; oA.x = o00; oA.y = o01;
        float2 oB; oB.x = o10; oB.y = o11;
        *(float2*)&y[(size_t)px0 * OC + obase + ocp * 2] = oA;
        *(float2*)&y[(size_t)px1 * OC + obase + ocp * 2] = oB;
    }
}

// ---------------- channel-last conv, IC=1 ----------------
__global__ __launch_bounds__(128) void conv1_cl(const float* __restrict__ x,
                                                const float* __restrict__ wgt,
                                                const float* __restrict__ bias,
                                                float* __restrict__ y)
{
    __shared__ float xs[6 * 32];
    __shared__ float ws[4][9];
    __shared__ float bs[4];
    const int tid = threadIdx.x;
    const int obase = blockIdx.y * 4;
    x += blockIdx.z * HW;
    y += (size_t)blockIdx.z * DM * HW;
    const int r0 = blockIdx.x * 4;
    for (int k = tid; k < 6 * 32; k += 128) {
        int lr = k >> 5, c = k & 31;
        xs[k] = x[(((r0 - 1 + lr) & 31) << 5) + c];
    }
    if (tid < 36) ws[tid / 9][tid % 9] = wgt[(obase + tid / 9) * 9 + tid % 9];
    if (tid < 4)  bs[tid] = bias[obase + tid];
    __syncthreads();

    const int hl = tid >> 5, c = tid & 31;
    const int cm = (c + 31) & 31, cp = (c + 1) & 31;
    float xv[9];
#pragma unroll
    for (int tr = 0; tr < 3; tr++) {
        xv[tr * 3 + 0] = xs[(hl + tr) * 32 + cm];
        xv[tr * 3 + 1] = xs[(hl + tr) * 32 + c];
        xv[tr * 3 + 2] = xs[(hl + tr) * 32 + cp];
    }
    float4 o; float* op = &o.x;
#pragma unroll
    for (int j = 0; j < 4; j++) {
        float a = bs[j];
#pragma unroll
        for (int t9 = 0; t9 < 9; t9++) a = fmaf(xv[t9], ws[j][t9], a);
        op[j] = fmaxf(a, 0.f);
    }
    const int px = blockIdx.x * 128 + tid;
    *(float4*)&y[(size_t)px * DM + obase] = o;
}

// ---------------- channel-last conv, OC=1 ----------------
__global__ __launch_bounds__(128) void conv_out(const float* __restrict__ x,
                                                const float* __restrict__ wgt,
                                                const float* __restrict__ bias,
                                                float* __restrict__ y)
{
    __shared__ float4 xs[3 * 32 * 17];
    __shared__ float  ws[9][64];
    const int tid = threadIdx.x;
    const int r0 = blockIdx.x;
    const float4* x4 = (const float4*)x;
    for (int k = tid; k < 3 * 32 * 16; k += 128) {
        int lr = k >> 9; int rem = k & 511; int c = rem >> 4; int icv = rem & 15;
        int row = (r0 - 1 + lr) & 31;
        xs[(lr * 32 + c) * 17 + icv] = x4[(((row << 5) + c) << 4) + icv];
    }
    for (int k = tid; k < 576; k += 128) {
        int tap = k >> 6, ic = k & 63;
        ws[tap][ic] = wgt[ic * 9 + tap];
    }
    __syncthreads();

    const int icq = tid & 3, c = tid >> 2;
    const int cm = (c + 31) & 31, cp = (c + 1) & 31;
    float acc = 0.f;
#pragma unroll
    for (int tr = 0; tr < 3; tr++) {
#pragma unroll
        for (int tc = 0; tc < 3; tc++) {
            const int cx = (tc == 0) ? cm : ((tc == 1) ? c : cp);
            const float4* xp = &xs[(tr * 32 + cx) * 17];
            const float4* wp = (const float4*)&ws[tr * 3 + tc][0];
#pragma unroll
            for (int k = 0; k < 4; k++) {
                float4 xv = xp[icq * 4 + k];
                float4 wv = wp[icq * 4 + k];
                acc = fmaf(xv.x, wv.x, fmaf(xv.y, wv.y, fmaf(xv.z, wv.z, fmaf(xv.w, wv.w, acc))));
            }
        }
    }
    acc += __shfl_xor_sync(0xffffffffu, acc, 1);
    acc += __shfl_xor_sync(0xffffffffu, acc, 2);
    if (icq == 0) y[(r0 << 5) + c] = acc + bias[0];
}

__device__ __forceinline__ float sp_f(float x) { return (x > 20.f) ? x : log1pf(expf(x)); }

// ---------------- prep: e,f,delta,u,B fields for encode slots ----------------
__global__ __launch_bounds__(128) void prep(const float* __restrict__ cc,
                                            const float* __restrict__ u,
                                            const float* __restrict__ dtp)
{
    const int s = blockIdx.z;
    cc += (size_t)s * HW * 96;
    u  += (size_t)s * HW * 64;
    const int tid = threadIdx.x;
    const int pl = tid >> 4, dq = tid & 15;
    const int p = blockIdx.x * 8 + pl;
    const float dti = dtp[0];

    float4 dc = *(const float4*)&cc[p * 96 + dq * 4];
    float4 dl4;
    dl4.x = sp_f(dc.x + dti); dl4.y = sp_f(dc.y + dti);
    dl4.z = sp_f(dc.z + dti); dl4.w = sp_f(dc.w + dti);
    float4 a4  = *(const float4*)&g_A[dq * 4];
    float4 ra4 = *(const float4*)&g_rA[dq * 4];
    float4 e4, f4;
    e4.x = __expf(dl4.x * a4.x); e4.y = __expf(dl4.y * a4.y);
    e4.z = __expf(dl4.z * a4.z); e4.w = __expf(dl4.w * a4.w);
    float4 u4 = *(const float4*)&u[p * 64 + dq * 4];
    f4.x = (e4.x - 1.f) * ra4.x * u4.x;
    f4.y = (e4.y - 1.f) * ra4.y * u4.y;
    f4.z = (e4.z - 1.f) * ra4.z * u4.z;
    f4.w = (e4.w - 1.f) * ra4.w * u4.w;

    float4* efp = (float4*)g_ef + (((size_t)s * HW + p) * 16 + dq) * 2;
    efp[0] = e4; efp[1] = f4;
    *(float4*)&g_dl[((size_t)s * HW + p) * 64 + dq * 4] = dl4;
    *(float4*)&g_uf[((size_t)s * HW + p) * 64 + dq * 4] = u4;
    g_Bf[((size_t)s * HW + p) * 16 + dq] = cc[p * 96 + 64 + dq];
}

// ---------------- fused y-kernel (decode step S, 1-based); 64 thr x 256 blocks -----
__global__ __launch_bounds__(64) void fused_y(const float* __restrict__ cc,
                                              const float* __restrict__ u,
                                              const float* __restrict__ Dskip,
                                              const float* __restrict__ dtp,
                                              int S, float* __restrict__ ymax)
{
    __shared__ float Bs[4][16], Cs[4][16];
    __shared__ float Gs[4][NV][MAXS];
    __shared__ float G0[4];
    const int tid = threadIdx.x;
    const int pl = tid >> 4, dq = tid & 15;
    const int p0 = blockIdx.x * 4;
    const int p = p0 + pl;
    const int h = p >> 5, w = p & 31;
    const int slotS = S - 1;
    const float dti = dtp[0];

    float4 dc = *(const float4*)&cc[p * 96 + dq * 4];
    float4 dl4;
    dl4.x = sp_f(dc.x + dti); dl4.y = sp_f(dc.y + dti);
    dl4.z = sp_f(dc.z + dti); dl4.w = sp_f(dc.w + dti);
    float4 a4  = *(const float4*)&g_A[dq * 4];
    float4 ra4 = *(const float4*)&g_rA[dq * 4];
    float4 e4o, f4o;
    e4o.x = __expf(dl4.x * a4.x); e4o.y = __expf(dl4.y * a4.y);
    e4o.z = __expf(dl4.z * a4.z); e4o.w = __expf(dl4.w * a4.w);
    float4 u4 = *(const float4*)&u[p * 64 + dq * 4];
    f4o.x = (e4o.x - 1.f) * ra4.x * u4.x;
    f4o.y = (e4o.y - 1.f) * ra4.y * u4.y;
    f4o.z = (e4o.z - 1.f) * ra4.z * u4.z;
    f4o.w = (e4o.w - 1.f) * ra4.w * u4.w;

    float4* efp = (float4*)g_ef + (((size_t)slotS * HW + p) * 16 + dq) * 2;
    efp[0] = e4o; efp[1] = f4o;
    *(float4*)&g_dl[((size_t)slotS * HW + p) * 64 + dq * 4] = dl4;
    *(float4*)&g_uf[((size_t)slotS * HW + p) * 64 + dq * 4] = u4;
    float bv = cc[p * 96 + 64 + dq];
    g_Bf[((size_t)slotS * HW + p) * 16 + dq] = bv;
    Bs[pl][dq] = bv;
    Cs[pl][dq] = cc[p * 96 + 80 + dq];
    __syncthreads();

    if (tid < 4) {
        float s = 0.f;
#pragma unroll
        for (int n = 0; n < 16; n++) s += Bs[tid][n] * Cs[tid][n];
        G0[tid] = s;
    }
    const int Sm1 = S - 1;
    const int tot = 4 * NV * Sm1;
    for (int idx = tid; idx < tot; idx += 64) {
        int i = idx / (NV * Sm1);
        int rem = idx - i * (NV * Sm1);
        int v = rem / Sm1;
        int k = rem - v * Sm1 + 1;
        int vx = v / 5 - 2, vy = v % 5 - 2;
        int pp = p0 + i;
        int hh = ((pp >> 5) + k * vy) & 31;
        int ww = ((pp & 31) + k * vx) & 31;
        int x = (hh << 5) + ww;
        const float* bp = &g_Bf[((size_t)(S - 1 - k) * HW + x) * 16];
        float s = 0.f;
#pragma unroll
        for (int n = 0; n < 16; n++) s += bp[n] * Cs[i][n];
        Gs[i][v][k] = s;
    }
    __syncthreads();

    float4 best = {-3e38f, -3e38f, -3e38f, -3e38f};
    if (g_uniA) {
        const float g0 = G0[pl];
#pragma unroll 1
        for (int g = 0; g < 5; g++) {
            float4 P[5], acc[5];
#pragma unroll
            for (int j = 0; j < 5; j++) {
                acc[j].x = f4o.x * g0; acc[j].y = f4o.y * g0;
                acc[j].z = f4o.z * g0; acc[j].w = f4o.w * g0;
                P[j] = e4o;
            }
#pragma unroll 1
            for (int k = 1; k < S; k++) {
#pragma unroll
                for (int j = 0; j < 5; j++) {
                    int v = g * 5 + j;
                    int vx = v / 5 - 2, vy = v % 5 - 2;
                    int hh = (h + k * vy) & 31;
                    int ww = (w + k * vx) & 31;
                    int x = (hh << 5) + ww;
                    const float4* ep = (const float4*)g_ef + (((size_t)(S - 1 - k) * HW + x) * 16 + dq) * 2;
                    float4 ee = ep[0];
                    float4 ff = ep[1];
                    float Gv = Gs[pl][v][k];
                    acc[j].x = fmaf(P[j].x * ff.x, Gv, acc[j].x);
                    acc[j].y = fmaf(P[j].y * ff.y, Gv, acc[j].y);
                    acc[j].z = fmaf(P[j].z * ff.z, Gv, acc[j].z);
                    acc[j].w = fmaf(P[j].w * ff.w, Gv, acc[j].w);
                    P[j].x *= ee.x; P[j].y *= ee.y; P[j].z *= ee.z; P[j].w *= ee.w;
                }
            }
#pragma unroll
            for (int j = 0; j < 5; j++) {
                best.x = fmaxf(best.x, acc[j].x);
                best.y = fmaxf(best.y, acc[j].y);
                best.z = fmaxf(best.z, acc[j].z);
                best.w = fmaxf(best.w, acc[j].w);
            }
        }
    } else {
        // generic A fallback (correct for any A)
#pragma unroll 1
        for (int v = 0; v < NV; v++) {
            int vx = v / 5 - 2, vy = v % 5 - 2;
            float4 accv = {0.f, 0.f, 0.f, 0.f};
#pragma unroll 1
            for (int n = 0; n < 16; n++) {
                float4 an4 = *(const float4*)&g_A[n * 64 + dq * 4];
                float4 rn4 = *(const float4*)&g_rA[n * 64 + dq * 4];
                float C = Cs[pl][n];
                float4 e0;
                e0.x = __expf(dl4.x * an4.x); e0.y = __expf(dl4.y * an4.y);
                e0.z = __expf(dl4.z * an4.z); e0.w = __expf(dl4.w * an4.w);
                float bc = Bs[pl][n] * C;
                float4 P = e0, a4c;
                a4c.x = (e0.x - 1.f) * rn4.x * u4.x * bc;
                a4c.y = (e0.y - 1.f) * rn4.y * u4.y * bc;
                a4c.z = (e0.z - 1.f) * rn4.z * u4.z * bc;
                a4c.w = (e0.w - 1.f) * rn4.w * u4.w * bc;
                for (int k = 1; k < S; k++) {
                    int hh = (h + k * vy) & 31;
                    int ww = (w + k * vx) & 31;
                    int x = (hh << 5) + ww;
                    int sl = S - 1 - k;
                    float4 dl = *(const float4*)&g_dl[((size_t)sl * HW + x) * 64 + dq * 4];
                    float4 uu = *(const float4*)&g_uf[((size_t)sl * HW + x) * 64 + dq * 4];
                    float Bt = g_Bf[((size_t)sl * HW + x) * 16 + n] * C;
                    float4 ee;
                    ee.x = __expf(dl.x * an4.x); ee.y = __expf(dl.y * an4.y);
                    ee.z = __expf(dl.z * an4.z); ee.w = __expf(dl.w * an4.w);
                    a4c.x = fmaf(P.x * (ee.x - 1.f) * rn4.x * uu.x, Bt, a4c.x);
                    a4c.y = fmaf(P.y * (ee.y - 1.f) * rn4.y * uu.y, Bt, a4c.y);
                    a4c.z = fmaf(P.z * (ee.z - 1.f) * rn4.z * uu.z, Bt, a4c.z);
                    a4c.w = fmaf(P.w * (ee.w - 1.f) * rn4.w * uu.w, Bt, a4c.w);
                    P.x *= ee.x; P.y *= ee.y; P.z *= ee.z; P.w *= ee.w;
                }
                accv.x += a4c.x; accv.y += a4c.y; accv.z += a4c.z; accv.w += a4c.w;
            }
            best.x = fmaxf(best.x, accv.x);
            best.y = fmaxf(best.y, accv.y);
            best.z = fmaxf(best.z, accv.z);
            best.w = fmaxf(best.w, accv.w);
        }
    }

    float4 dk = *(const float4*)&Dskip[dq * 4];
    float4 o;
    o.x = fmaf(dk.x, u4.x, best.x);
    o.y = fmaf(dk.y, u4.y, best.y);
    o.z = fmaf(dk.z, u4.z, best.z);
    o.w = fmaf(dk.w, u4.w, best.w);
    *(float4*)&ymax[p * 64 + dq * 4] = o;
}

// ---------------- launch ----------------
extern "C" void kernel_launch(void* const* d_in, const int* in_sizes, int n_in,
                              void* d_out, int out_size)
{
    const float* input_seq = (const float*)d_in[0];
    const float* enc_w1 = (const float*)d_in[1];
    const float* enc_b1 = (const float*)d_in[2];
    const float* enc_w2 = (const float*)d_in[3];
    const float* enc_b2 = (const float*)d_in[4];
    const float* wd     = (const float*)d_in[5];
    const float* bd     = (const float*)d_in[6];
    const float* wB     = (const float*)d_in[7];
    const float* wC     = (const float*)d_in[8];
    const float* logA   = (const float*)d_in[9];
    const float* Dskip  = (const float*)d_in[10];
    const float* dt_inv = (const float*)d_in[11];
    const float* dec_w1 = (const float*)d_in[12];
    const float* dec_b1 = (const float*)d_in[13];
    const float* dec_w2 = (const float*)d_in[14];
    const float* dec_b2 = (const float*)d_in[15];
    const float* dec_w3 = (const float*)d_in[16];
    const float* dec_b3 = (const float*)d_in[17];
    float* out = (float*)d_out;

    float *p_u, *p_e1, *p_cc, *p_wpack, *p_bpack, *p_ymax, *p_d1, *p_d2;
    cudaGetSymbolAddress((void**)&p_u, g_u);
    cudaGetSymbolAddress((void**)&p_e1, g_e1);
    cudaGetSymbolAddress((void**)&p_cc, g_cc);
    cudaGetSymbolAddress((void**)&p_wpack, g_wpack);
    cudaGetSymbolAddress((void**)&p_bpack, g_bpack);
    cudaGetSymbolAddress((void**)&p_ymax, g_ymax);
    cudaGetSymbolAddress((void**)&p_d1, g_d1);
    cudaGetSymbolAddress((void**)&p_d2, g_d2);

    pack_w<<<216, 256>>>(wd, bd, wB, wC, logA);
    check_uni<<<1, 256>>>(logA);

    // ---- encode: batched over 4 frames; history fields only ----
    conv1_cl<<<dim3(8, 16, TIN), 128>>>(input_seq, enc_w1, enc_b1, p_e1);
    conv_f4<true><<<dim3(8, 16, TIN), 128>>>(p_e1, enc_w2, enc_b2, p_u, DM);
    conv_f4<false><<<dim3(8, 24, TIN), 128>>>(p_u, p_wpack, p_bpack, p_cc, 96);
    prep<<<dim3(128, 1, TIN), 128>>>(p_cc, p_u, dt_inv);

    // ---- decode ----
    int steps = out_size / HW;
    for (int t = 0; t < steps; t++) {
        const float* src = (t == 0) ? (input_seq + 3 * HW) : (out + (size_t)(t - 1) * HW);
        conv1_cl<<<dim3(8, 16, 1), 128>>>(src, enc_w1, enc_b1, p_e1);
        conv_f2<true><<<dim3(16, 16, 1), 128>>>(p_e1, enc_w2, enc_b2, p_u, DM);
        conv_f2<false><<<dim3(16, 24, 1), 128>>>(p_u, p_wpack, p_bpack, p_cc, 96);
        fused_y<<<256, 64>>>(p_cc, p_u, Dskip, dt_inv, TIN + 1 + t, p_ymax);
        conv_f2<true><<<dim3(16, 16, 1), 128>>>(p_ymax, dec_w1, dec_b1, p_d1, DM);
        conv_f2<true><<<dim3(16, 16, 1), 128>>>(p_d1, dec_w2, dec_b2, p_d2, DM);
        conv_out<<<32, 128>>>(p_d2, dec_w3, dec_b3, out + (size_t)t * HW);
    }
}

// round 12
// speedup vs baseline: 1.4731x; 1.2231x over previous
#include <cuda_runtime.h>
#include <math.h>

#define HW   1024
#define DM   64
#define DS   16
#define NV   25
#define TIN  4
#define MAXS 8

// packed fp32x2 FMA (sm_100+; only reachable via PTX)
#define FMA2(d, a, b) asm("fma.rn.f32x2 %0, %1, %2, %0;" : "+l"(d) : "l"(a), "l"(b))
#define UNPK2(lo, hi, v) asm("mov.b64 {%0, %1}, %2;" : "=f"(lo), "=f"(hi) : "l"(v))

// ---------------- scratch (static device globals; no allocation) ----------------
__device__ __align__(128) float g_u[TIN * HW * DM];
__device__ __align__(128) float g_e1[TIN * HW * DM];
__device__ __align__(128) float g_cc[TIN * HW * 96];            // [t][px][dconv|B|C]
__device__ __align__(128) float g_wpack[96 * DM * 9];           // wd|wB|wC raw concat [oc][ic][9]
__device__ __align__(128) float g_bpack[96];
__device__ __align__(128) float g_A[DS * DM];                   // A[n][d] = -exp(logA[d][n])
__device__ __align__(128) float g_rA[DS * DM];
__device__ int   g_uniA;
// history fields, slot s-1 for step s = 1..8
__device__ __align__(128) float g_ef[MAXS * HW * DM * 2];       // [slot][p][dq][{e4,f4}]
__device__ __align__(128) float g_dl[MAXS * HW * DM];           // delta (generic fallback)
__device__ __align__(128) float g_uf[MAXS * HW * DM];           // u history (generic fallback)
__device__ __align__(128) float g_Bf[MAXS * HW * DS];           // B fields [slot][p][n]
__device__ __align__(128) float g_ymax[HW * DM];
__device__ __align__(128) float g_d1[HW * DM];
__device__ __align__(128) float g_d2[HW * DM];

// ---------------- pack weights (raw concat) + A fields ----------------
__global__ void pack_w(const float* __restrict__ wd, const float* __restrict__ bd,
                       const float* __restrict__ wB, const float* __restrict__ wC,
                       const float* __restrict__ logA)
{
    int k = blockIdx.x * 256 + threadIdx.x;
    const int W1 = DM * DM * 9;
    const int W2 = DS * DM * 9;
    if (k < W1)                 g_wpack[k] = wd[k];
    else if (k < W1 + W2)       g_wpack[k] = wB[k - W1];
    else if (k < W1 + 2 * W2)   g_wpack[k] = wC[k - W1 - W2];
    if (k < DM)                 g_bpack[k] = bd[k];
    else if (k < 96)            g_bpack[k] = 0.f;
    if (k < DS * DM) {
        int n = k >> 6, d = k & 63;
        float a = -expf(logA[d * DS + n]);
        g_A[k] = a;
        g_rA[k] = 1.f / a;
    }
}

// row-wise uniformity: A[d][n] == A[d][0] for all n (fast-path requirement)
__global__ void check_uni(const float* __restrict__ logA)
{
    __shared__ int ok;
    if (threadIdx.x == 0) ok = 1;
    __syncthreads();
    bool bad = false;
    for (int i = threadIdx.x; i < DM * DS; i += 256)
        if (logA[i] != logA[(i / DS) * DS]) bad = true;
    if (bad) atomicAnd(&ok, 0);
    __syncthreads();
    if (threadIdx.x == 0) g_uniA = ok;
}

// ---------------- f32x2 conv, 4 rows/thread ----------------
// Block = 128 thr = 32 c x 2 ocp x 2 ic-half; computes 4 rows x 4 oc.
// grid = (8 row-quads, OC/4, z). 6 staged x rows serve 12 tap-row uses.
template <bool RELU>
__global__ __launch_bounds__(128) void conv_f4(const float* __restrict__ x,
                                               const float* __restrict__ wgt,
                                               const float* __restrict__ bias,
                                               float* __restrict__ y, int OC)
{
    __shared__ float4 xs[6 * 32 * 17];     // 51 KB: rows r0-1 .. r0+4
    __shared__ float  ws[4][9][64];        // 9 KB
    __shared__ float  bs[4];
    __shared__ float4 red[2][32][2];
    const int tid = threadIdx.x;
    const int obase = blockIdx.y * 4;
    const int r0 = blockIdx.x * 4;
    x += (size_t)blockIdx.z * DM * HW;
    y += (size_t)blockIdx.z * (size_t)OC * HW;

    const float4* x4 = (const float4*)x;
    for (int k = tid; k < 6 * 32 * 16; k += 128) {
        int lr = k >> 9; int rem = k & 511; int c = rem >> 4; int icv = rem & 15;
        int row = (r0 - 1 + lr) & 31;
        xs[(lr * 32 + c) * 17 + icv] = x4[(((row << 5) + c) << 4) + icv];
    }
    for (int k = tid; k < 4 * 9 * 64; k += 128) {
        int ocl = k / 576; int rem = k - ocl * 576; int tap = rem >> 6; int ic = rem & 63;
        ws[ocl][tap][ic] = wgt[(obase + ocl) * 576 + ic * 9 + tap];
    }
    if (tid < 4) bs[tid] = bias[obase + tid];
    __syncthreads();

    const int half = tid >> 6;
    const int ocp  = (tid >> 5) & 1;
    const int c    = tid & 31;
    const int cm = (c + 31) & 31, cp = (c + 1) & 31;
    const int hb = half * 8;

    unsigned long long acc[4][2];
#pragma unroll
    for (int p = 0; p < 4; p++) { acc[p][0] = 0ull; acc[p][1] = 0ull; }

#pragma unroll
    for (int tc = 0; tc < 3; tc++) {
        const int cx = (tc == 0) ? cm : ((tc == 1) ? c : cp);
        const ulonglong2* xr[6];
#pragma unroll
        for (int r = 0; r < 6; r++) xr[r] = (const ulonglong2*)&xs[(r * 32 + cx) * 17 + hb];
        const ulonglong2* w0t[3];
        const ulonglong2* w1t[3];
#pragma unroll
        for (int tr = 0; tr < 3; tr++) {
            w0t[tr] = (const ulonglong2*)&ws[ocp * 2 + 0][tr * 3 + tc][half * 32];
            w1t[tr] = (const ulonglong2*)&ws[ocp * 2 + 1][tr * 3 + tc][half * 32];
        }
#pragma unroll
        for (int icv = 0; icv < 8; icv++) {
            ulonglong2 xv[6];
#pragma unroll
            for (int r = 0; r < 6; r++) xv[r] = xr[r][icv];
#pragma unroll
            for (int tr = 0; tr < 3; tr++) {
                ulonglong2 wa = w0t[tr][icv];
                ulonglong2 wb = w1t[tr][icv];
#pragma unroll
                for (int p = 0; p < 4; p++) {
                    FMA2(acc[p][0], xv[p + tr].x, wa.x); FMA2(acc[p][0], xv[p + tr].y, wa.y);
                    FMA2(acc[p][1], xv[p + tr].x, wb.x); FMA2(acc[p][1], xv[p + tr].y, wb.y);
                }
            }
        }
    }

    float s[4][2];
#pragma unroll
    for (int p = 0; p < 4; p++) {
        float lo, hi;
        UNPK2(lo, hi, acc[p][0]); s[p][0] = lo + hi;
        UNPK2(lo, hi, acc[p][1]); s[p][1] = lo + hi;
    }

    if (half) {
        float4 rA; rA.x = s[0][0]; rA.y = s[0][1]; rA.z = s[1][0]; rA.w = s[1][1];
        float4 rB; rB.x = s[2][0]; rB.y = s[2][1]; rB.z = s[3][0]; rB.w = s[3][1];
        red[ocp][c][0] = rA; red[ocp][c][1] = rB;
    }
    __syncthreads();
    if (!half) {
        float4 rA = red[ocp][c][0];
        float4 rB = red[ocp][c][1];
        float b0 = bs[ocp * 2], b1 = bs[ocp * 2 + 1];
        float o[4][2];
        o[0][0] = s[0][0] + rA.x + b0; o[0][1] = s[0][1] + rA.y + b1;
        o[1][0] = s[1][0] + rA.z + b0; o[1][1] = s[1][1] + rA.w + b1;
        o[2][0] = s[2][0] + rB.x + b0; o[2][1] = s[2][1] + rB.y + b1;
        o[3][0] = s[3][0] + rB.z + b0; o[3][1] = s[3][1] + rB.w + b1;
#pragma unroll
        for (int p = 0; p < 4; p++) {
            float v0 = o[p][0], v1 = o[p][1];
            if (RELU) { v0 = fmaxf(v0, 0.f); v1 = fmaxf(v1, 0.f); }
            const int px = ((r0 + p) << 5) + c;
            float2 ov; ov.x = v0; ov.y = v1;
            *(float2*)&y[(size_t)px * OC + obase + ocp * 2] = ov;
        }
    }
}

// ---------------- channel-last conv, IC=1 ----------------
__global__ __launch_bounds__(128) void conv1_cl(const float* __restrict__ x,
                                                const float* __restrict__ wgt,
                                                const float* __restrict__ bias,
                                                float* __restrict__ y)
{
    __shared__ float xs[6 * 32];
    __shared__ float ws[4][9];
    __shared__ float bs[4];
    const int tid = threadIdx.x;
    const int obase = blockIdx.y * 4;
    x += blockIdx.z * HW;
    y += (size_t)blockIdx.z * DM * HW;
    const int r0 = blockIdx.x * 4;
    for (int k = tid; k < 6 * 32; k += 128) {
        int lr = k >> 5, c = k & 31;
        xs[k] = x[(((r0 - 1 + lr) & 31) << 5) + c];
    }
    if (tid < 36) ws[tid / 9][tid % 9] = wgt[(obase + tid / 9) * 9 + tid % 9];
    if (tid < 4)  bs[tid] = bias[obase + tid];
    __syncthreads();

    const int hl = tid >> 5, c = tid & 31;
    const int cm = (c + 31) & 31, cp = (c + 1) & 31;
    float xv[9];
#pragma unroll
    for (int tr = 0; tr < 3; tr++) {
        xv[tr * 3 + 0] = xs[(hl + tr) * 32 + cm];
        xv[tr * 3 + 1] = xs[(hl + tr) * 32 + c];
        xv[tr * 3 + 2] = xs[(hl + tr) * 32 + cp];
    }
    float4 o; float* op = &o.x;
#pragma unroll
    for (int j = 0; j < 4; j++) {
        float a = bs[j];
#pragma unroll
        for (int t9 = 0; t9 < 9; t9++) a = fmaf(xv[t9], ws[j][t9], a);
        op[j] = fmaxf(a, 0.f);
    }
    const int px = blockIdx.x * 128 + tid;
    *(float4*)&y[(size_t)px * DM + obase] = o;
}

// ---------------- channel-last conv, OC=1; 64 blocks (2 per row, 8-lane ic-groups) ----
__global__ __launch_bounds__(128) void conv_out(const float* __restrict__ x,
                                                const float* __restrict__ wgt,
                                                const float* __restrict__ bias,
                                                float* __restrict__ y)
{
    __shared__ float4 xs[3 * 32 * 17];
    __shared__ float  ws[9][64];
    const int tid = threadIdx.x;
    const int r0 = blockIdx.x >> 1;
    const int chalf = blockIdx.x & 1;
    const float4* x4 = (const float4*)x;
    for (int k = tid; k < 3 * 32 * 16; k += 128) {
        int lr = k >> 9; int rem = k & 511; int c = rem >> 4; int icv = rem & 15;
        int row = (r0 - 1 + lr) & 31;
        xs[(lr * 32 + c) * 17 + icv] = x4[(((row << 5) + c) << 4) + icv];
    }
    for (int k = tid; k < 576; k += 128) {
        int tap = k >> 6, ic = k & 63;
        ws[tap][ic] = wgt[ic * 9 + tap];
    }
    __syncthreads();

    const int icg = tid & 7;                   // 8 ic-groups of 8 ic (2 float4)
    const int c = chalf * 16 + (tid >> 3);     // 16 cols per block
    const int cm = (c + 31) & 31, cp = (c + 1) & 31;
    float acc = 0.f;
#pragma unroll
    for (int tr = 0; tr < 3; tr++) {
#pragma unroll
        for (int tc = 0; tc < 3; tc++) {
            const int cx = (tc == 0) ? cm : ((tc == 1) ? c : cp);
            const float4* xp = &xs[(tr * 32 + cx) * 17];
            const float4* wp = (const float4*)&ws[tr * 3 + tc][0];
#pragma unroll
            for (int k = 0; k < 2; k++) {
                float4 xv = xp[icg * 2 + k];
                float4 wv = wp[icg * 2 + k];
                acc = fmaf(xv.x, wv.x, fmaf(xv.y, wv.y, fmaf(xv.z, wv.z, fmaf(xv.w, wv.w, acc))));
            }
        }
    }
    acc += __shfl_xor_sync(0xffffffffu, acc, 1);
    acc += __shfl_xor_sync(0xffffffffu, acc, 2);
    acc += __shfl_xor_sync(0xffffffffu, acc, 4);
    if (icg == 0) y[(r0 << 5) + c] = acc + bias[0];
}

__device__ __forceinline__ float sp_f(float x) { return (x > 20.f) ? x : log1pf(expf(x)); }

// ---------------- prep: e,f,delta,u,B fields for encode slots ----------------
__global__ __launch_bounds__(128) void prep(const float* __restrict__ cc,
                                            const float* __restrict__ u,
                                            const float* __restrict__ dtp)
{
    const int s = blockIdx.z;
    cc += (size_t)s * HW * 96;
    u  += (size_t)s * HW * 64;
    const int tid = threadIdx.x;
    const int pl = tid >> 4, dq = tid & 15;
    const int p = blockIdx.x * 8 + pl;
    const float dti = dtp[0];

    float4 dc = *(const float4*)&cc[p * 96 + dq * 4];
    float4 dl4;
    dl4.x = sp_f(dc.x + dti); dl4.y = sp_f(dc.y + dti);
    dl4.z = sp_f(dc.z + dti); dl4.w = sp_f(dc.w + dti);
    float4 a4  = *(const float4*)&g_A[dq * 4];
    float4 ra4 = *(const float4*)&g_rA[dq * 4];
    float4 e4, f4;
    e4.x = __expf(dl4.x * a4.x); e4.y = __expf(dl4.y * a4.y);
    e4.z = __expf(dl4.z * a4.z); e4.w = __expf(dl4.w * a4.w);
    float4 u4 = *(const float4*)&u[p * 64 + dq * 4];
    f4.x = (e4.x - 1.f) * ra4.x * u4.x;
    f4.y = (e4.y - 1.f) * ra4.y * u4.y;
    f4.z = (e4.z - 1.f) * ra4.z * u4.z;
    f4.w = (e4.w - 1.f) * ra4.w * u4.w;

    float4* efp = (float4*)g_ef + (((size_t)s * HW + p) * 16 + dq) * 2;
    efp[0] = e4; efp[1] = f4;
    *(float4*)&g_dl[((size_t)s * HW + p) * 64 + dq * 4] = dl4;
    *(float4*)&g_uf[((size_t)s * HW + p) * 64 + dq * 4] = u4;
    g_Bf[((size_t)s * HW + p) * 16 + dq] = cc[p * 96 + 64 + dq];
}

// ---- per-chunk v evaluation helper (uniA fast path) ----
template<int CNT>
__device__ __forceinline__ void yv_chunk(int vbase, int S, int h, int w, int dq,
                                         const float* GsRow, float g0,
                                         float4 e4o, float4 f4o, float4& best)
{
    float4 P[CNT], acc[CNT];
#pragma unroll
    for (int j = 0; j < CNT; j++) {
        acc[j].x = f4o.x * g0; acc[j].y = f4o.y * g0;
        acc[j].z = f4o.z * g0; acc[j].w = f4o.w * g0;
        P[j] = e4o;
    }
#pragma unroll 1
    for (int k = 1; k < S; k++) {
#pragma unroll
        for (int j = 0; j < CNT; j++) {
            int v = vbase + j;
            int vx = v / 5 - 2, vy = v % 5 - 2;
            int hh = (h + k * vy) & 31;
            int ww = (w + k * vx) & 31;
            int x = (hh << 5) + ww;
            const float4* ep = (const float4*)g_ef + (((size_t)(S - 1 - k) * HW + x) * 16 + dq) * 2;
            float4 ee = ep[0];
            float4 ff = ep[1];
            float Gv = GsRow[v * MAXS + k];
            acc[j].x = fmaf(P[j].x * ff.x, Gv, acc[j].x);
            acc[j].y = fmaf(P[j].y * ff.y, Gv, acc[j].y);
            acc[j].z = fmaf(P[j].z * ff.z, Gv, acc[j].z);
            acc[j].w = fmaf(P[j].w * ff.w, Gv, acc[j].w);
            P[j].x *= ee.x; P[j].y *= ee.y; P[j].z *= ee.z; P[j].w *= ee.w;
        }
    }
#pragma unroll
    for (int j = 0; j < CNT; j++) {
        best.x = fmaxf(best.x, acc[j].x);
        best.y = fmaxf(best.y, acc[j].y);
        best.z = fmaxf(best.z, acc[j].z);
        best.w = fmaxf(best.w, acc[j].w);
    }
}

// ---------------- fused y-kernel (decode step S, 1-based); 128 thr, v-split x2 ------
__global__ __launch_bounds__(128) void fused_y(const float* __restrict__ cc,
                                               const float* __restrict__ u,
                                               const float* __restrict__ Dskip,
                                               const float* __restrict__ dtp,
                                               int S, float* __restrict__ ymax)
{
    __shared__ float Bs[4][16], Cs[4][16];
    __shared__ float Gs[4][NV][MAXS];
    __shared__ float G0[4];
    __shared__ float4 sb1[4][16];
    const int tid = threadIdx.x;
    const int half = tid >> 6;
    const int t64 = tid & 63;
    const int pl = t64 >> 4, dq = t64 & 15;
    const int p0 = blockIdx.x * 4;
    const int p = p0 + pl;
    const int h = p >> 5, w = p & 31;
    const int slotS = S - 1;
    const float dti = dtp[0];

    // own-step prep (both halves compute; global/smem writes by half 0 only)
    float4 dc = *(const float4*)&cc[p * 96 + dq * 4];
    float4 dl4;
    dl4.x = sp_f(dc.x + dti); dl4.y = sp_f(dc.y + dti);
    dl4.z = sp_f(dc.z + dti); dl4.w = sp_f(dc.w + dti);
    float4 a4  = *(const float4*)&g_A[dq * 4];
    float4 ra4 = *(const float4*)&g_rA[dq * 4];
    float4 e4o, f4o;
    e4o.x = __expf(dl4.x * a4.x); e4o.y = __expf(dl4.y * a4.y);
    e4o.z = __expf(dl4.z * a4.z); e4o.w = __expf(dl4.w * a4.w);
    float4 u4 = *(const float4*)&u[p * 64 + dq * 4];
    f4o.x = (e4o.x - 1.f) * ra4.x * u4.x;
    f4o.y = (e4o.y - 1.f) * ra4.y * u4.y;
    f4o.z = (e4o.z - 1.f) * ra4.z * u4.z;
    f4o.w = (e4o.w - 1.f) * ra4.w * u4.w;

    if (half == 0) {
        float4* efp = (float4*)g_ef + (((size_t)slotS * HW + p) * 16 + dq) * 2;
        efp[0] = e4o; efp[1] = f4o;
        *(float4*)&g_dl[((size_t)slotS * HW + p) * 64 + dq * 4] = dl4;
        *(float4*)&g_uf[((size_t)slotS * HW + p) * 64 + dq * 4] = u4;
        float bv = cc[p * 96 + 64 + dq];
        g_Bf[((size_t)slotS * HW + p) * 16 + dq] = bv;
        Bs[pl][dq] = bv;
        Cs[pl][dq] = cc[p * 96 + 80 + dq];
    }
    __syncthreads();

    if (tid < 4) {
        float s = 0.f;
#pragma unroll
        for (int n = 0; n < 16; n++) s += Bs[tid][n] * Cs[tid][n];
        G0[tid] = s;
    }
    const int Sm1 = S - 1;
    const int tot = 4 * NV * Sm1;
    for (int idx = tid; idx < tot; idx += 128) {
        int i = idx / (NV * Sm1);
        int rem = idx - i * (NV * Sm1);
        int v = rem / Sm1;
        int k = rem - v * Sm1 + 1;
        int vx = v / 5 - 2, vy = v % 5 - 2;
        int pp = p0 + i;
        int hh = ((pp >> 5) + k * vy) & 31;
        int ww = ((pp & 31) + k * vx) & 31;
        int x = (hh << 5) + ww;
        const float* bp = &g_Bf[((size_t)(S - 1 - k) * HW + x) * 16];
        float s = 0.f;
#pragma unroll
        for (int n = 0; n < 16; n++) s += bp[n] * Cs[i][n];
        Gs[i][v][k] = s;
    }
    __syncthreads();

    float4 best = {-3e38f, -3e38f, -3e38f, -3e38f};
    if (g_uniA) {
        const float g0 = G0[pl];
        const float* GsRow = &Gs[pl][0][0];
        if (half == 0) {            // v 0..11
            yv_chunk<4>(0, S, h, w, dq, GsRow, g0, e4o, f4o, best);
            yv_chunk<4>(4, S, h, w, dq, GsRow, g0, e4o, f4o, best);
            yv_chunk<4>(8, S, h, w, dq, GsRow, g0, e4o, f4o, best);
        } else {                    // v 12..24
            yv_chunk<4>(12, S, h, w, dq, GsRow, g0, e4o, f4o, best);
            yv_chunk<4>(16, S, h, w, dq, GsRow, g0, e4o, f4o, best);
            yv_chunk<5>(20, S, h, w, dq, GsRow, g0, e4o, f4o, best);
        }
    } else if (half == 0) {
        // generic A fallback (correct for any A; half 0 covers all 25 v)
#pragma unroll 1
        for (int v = 0; v < NV; v++) {
            int vx = v / 5 - 2, vy = v % 5 - 2;
            float4 accv = {0.f, 0.f, 0.f, 0.f};
#pragma unroll 1
            for (int n = 0; n < 16; n++) {
                float4 an4 = *(const float4*)&g_A[n * 64 + dq * 4];
                float4 rn4 = *(const float4*)&g_rA[n * 64 + dq * 4];
                float C = Cs[pl][n];
                float4 e0;
                e0.x = __expf(dl4.x * an4.x); e0.y = __expf(dl4.y * an4.y);
                e0.z = __expf(dl4.z * an4.z); e0.w = __expf(dl4.w * an4.w);
                float bc = Bs[pl][n] * C;
                float4 P = e0, a4c;
                a4c.x = (e0.x - 1.f) * rn4.x * u4.x * bc;
                a4c.y = (e0.y - 1.f) * rn4.y * u4.y * bc;
                a4c.z = (e0.z - 1.f) * rn4.z * u4.z * bc;
                a4c.w = (e0.w - 1.f) * rn4.w * u4.w * bc;
                for (int k = 1; k < S; k++) {
                    int hh = (h + k * vy) & 31;
                    int ww = (w + k * vx) & 31;
                    int x = (hh << 5) + ww;
                    int sl = S - 1 - k;
                    float4 dl = *(const float4*)&g_dl[((size_t)sl * HW + x) * 64 + dq * 4];
                    float4 uu = *(const float4*)&g_uf[((size_t)sl * HW + x) * 64 + dq * 4];
                    float Bt = g_Bf[((size_t)sl * HW + x) * 16 + n] * C;
                    float4 ee;
                    ee.x = __expf(dl.x * an4.x); ee.y = __expf(dl.y * an4.y);
                    ee.z = __expf(dl.z * an4.z); ee.w = __expf(dl.w * an4.w);
                    a4c.x = fmaf(P.x * (ee.x - 1.f) * rn4.x * uu.x, Bt, a4c.x);
                    a4c.y = fmaf(P.y * (ee.y - 1.f) * rn4.y * uu.y, Bt, a4c.y);
                    a4c.z = fmaf(P.z * (ee.z - 1.f) * rn4.z * uu.z, Bt, a4c.z);
                    a4c.w = fmaf(P.w * (ee.w - 1.f) * rn4.w * uu.w, Bt, a4c.w);
                    P.x *= ee.x; P.y *= ee.y; P.z *= ee.z; P.w *= ee.w;
                }
                accv.x += a4c.x; accv.y += a4c.y; accv.z += a4c.z; accv.w += a4c.w;
            }
            best.x = fmaxf(best.x, accv.x);
            best.y = fmaxf(best.y, accv.y);
            best.z = fmaxf(best.z, accv.z);
            best.w = fmaxf(best.w, accv.w);
        }
    }

    if (half == 1) sb1[pl][dq] = best;
    __syncthreads();
    if (half == 0) {
        float4 b1 = sb1[pl][dq];
        best.x = fmaxf(best.x, b1.x);
        best.y = fmaxf(best.y, b1.y);
        best.z = fmaxf(best.z, b1.z);
        best.w = fmaxf(best.w, b1.w);
        float4 dk = *(const float4*)&Dskip[dq * 4];
        float4 o;
        o.x = fmaf(dk.x, u4.x, best.x);
        o.y = fmaf(dk.y, u4.y, best.y);
        o.z = fmaf(dk.z, u4.z, best.z);
        o.w = fmaf(dk.w, u4.w, best.w);
        *(float4*)&ymax[p * 64 + dq * 4] = o;
    }
}

// ---------------- launch ----------------
extern "C" void kernel_launch(void* const* d_in, const int* in_sizes, int n_in,
                              void* d_out, int out_size)
{
    const float* input_seq = (const float*)d_in[0];
    const float* enc_w1 = (const float*)d_in[1];
    const float* enc_b1 = (const float*)d_in[2];
    const float* enc_w2 = (const float*)d_in[3];
    const float* enc_b2 = (const float*)d_in[4];
    const float* wd     = (const float*)d_in[5];
    const float* bd     = (const float*)d_in[6];
    const float* wB     = (const float*)d_in[7];
    const float* wC     = (const float*)d_in[8];
    const float* logA   = (const float*)d_in[9];
    const float* Dskip  = (const float*)d_in[10];
    const float* dt_inv = (const float*)d_in[11];
    const float* dec_w1 = (const float*)d_in[12];
    const float* dec_b1 = (const float*)d_in[13];
    const float* dec_w2 = (const float*)d_in[14];
    const float* dec_b2 = (const float*)d_in[15];
    const float* dec_w3 = (const float*)d_in[16];
    const float* dec_b3 = (const float*)d_in[17];
    float* out = (float*)d_out;

    float *p_u, *p_e1, *p_cc, *p_wpack, *p_bpack, *p_ymax, *p_d1, *p_d2;
    cudaGetSymbolAddress((void**)&p_u, g_u);
    cudaGetSymbolAddress((void**)&p_e1, g_e1);
    cudaGetSymbolAddress((void**)&p_cc, g_cc);
    cudaGetSymbolAddress((void**)&p_wpack, g_wpack);
    cudaGetSymbolAddress((void**)&p_bpack, g_bpack);
    cudaGetSymbolAddress((void**)&p_ymax, g_ymax);
    cudaGetSymbolAddress((void**)&p_d1, g_d1);
    cudaGetSymbolAddress((void**)&p_d2, g_d2);

    pack_w<<<216, 256>>>(wd, bd, wB, wC, logA);
    check_uni<<<1, 256>>>(logA);

    // ---- encode: batched over 4 frames; history fields only ----
    conv1_cl<<<dim3(8, 16, TIN), 128>>>(input_seq, enc_w1, enc_b1, p_e1);
    conv_f4<true><<<dim3(8, 16, TIN), 128>>>(p_e1, enc_w2, enc_b2, p_u, DM);
    conv_f4<false><<<dim3(8, 24, TIN), 128>>>(p_u, p_wpack, p_bpack, p_cc, 96);
    prep<<<dim3(128, 1, TIN), 128>>>(p_cc, p_u, dt_inv);

    // ---- decode ----
    int steps = out_size / HW;
    for (int t = 0; t < steps; t++) {
        const float* src = (t == 0) ? (input_seq + 3 * HW) : (out + (size_t)(t - 1) * HW);
        conv1_cl<<<dim3(8, 16, 1), 128>>>(src, enc_w1, enc_b1, p_e1);
        conv_f4<true><<<dim3(8, 16, 1), 128>>>(p_e1, enc_w2, enc_b2, p_u, DM);
        conv_f4<false><<<dim3(8, 24, 1), 128>>>(p_u, p_wpack, p_bpack, p_cc, 96);
        fused_y<<<256, 128>>>(p_cc, p_u, Dskip, dt_inv, TIN + 1 + t, p_ymax);
        conv_f4<true><<<dim3(8, 16, 1), 128>>>(p_ymax, dec_w1, dec_b1, p_d1, DM);
        conv_f4<true><<<dim3(8, 16, 1), 128>>>(p_d1, dec_w2, dec_b2, p_d2, DM);
        conv_out<<<64, 128>>>(p_d2, dec_w3, dec_b3, out + (size_t)t * HW);
    }
}

// round 13
// speedup vs baseline: 1.5255x; 1.0356x over previous
#include <cuda_runtime.h>
#include <math.h>

#define HW   1024
#define DM   64
#define DS   16
#define NV   25
#define TIN  4
#define MAXS 8

// packed fp32x2 FMA (sm_100+; only reachable via PTX)
#define FMA2(d, a, b) asm("fma.rn.f32x2 %0, %1, %2, %0;" : "+l"(d) : "l"(a), "l"(b))
#define UNPK2(lo, hi, v) asm("mov.b64 {%0, %1}, %2;" : "=f"(lo), "=f"(hi) : "l"(v))

// ---------------- scratch (static device globals; no allocation) ----------------
__device__ __align__(128) float g_u[TIN * HW * DM];
__device__ __align__(128) float g_e1[TIN * HW * DM];
__device__ __align__(128) float g_cc[TIN * HW * 96];            // [t][px][dconv|B|C]
__device__ __align__(128) float g_wt96[96 * 576];               // wd|wB|wC transposed [oc][tap][ic]
__device__ __align__(128) float g_wtE[64 * 576];                // enc_w2 transposed
__device__ __align__(128) float g_wtD1[64 * 576];
__device__ __align__(128) float g_wtD2[64 * 576];
__device__ __align__(128) float g_bpack[96];
__device__ __align__(128) float g_A[DS * DM];                   // A[n][d] = -exp(logA[d][n])
__device__ __align__(128) float g_rA[DS * DM];
__device__ int   g_uniA;
// history fields, slot s-1 for step s = 1..8
__device__ __align__(128) float g_ef[MAXS * HW * DM * 2];       // [slot][p][dq][{e4,f4}]
__device__ __align__(128) float g_dl[MAXS * HW * DM];           // delta (generic fallback only)
__device__ __align__(128) float g_uf[MAXS * HW * DM];           // u history (generic fallback only)
__device__ __align__(128) float g_Bf[MAXS * HW * DS];           // B fields [slot][p][n]
__device__ __align__(128) float g_ymax[HW * DM];
__device__ __align__(128) float g_d1[HW * DM];
__device__ __align__(128) float g_d2[HW * DM];

// ---------------- pack: transposed weights + bias + A fields ----------------
__global__ void pack_all(const float* __restrict__ wd, const float* __restrict__ bd,
                         const float* __restrict__ wB, const float* __restrict__ wC,
                         const float* __restrict__ logA,
                         const float* __restrict__ ew2, const float* __restrict__ dw1,
                         const float* __restrict__ dw2)
{
    int k = blockIdx.x * 256 + threadIdx.x;
    const int R0 = 96 * 576;
    const int R1 = R0 + 3 * 64 * 576;
    if (k < R0) {
        int oc = k / 576, rem = k - oc * 576;
        int tap = rem >> 6, ic = rem & 63;
        float v;
        if (oc < 64)      v = wd[oc * 576 + ic * 9 + tap];
        else if (oc < 80) v = wB[(oc - 64) * 576 + ic * 9 + tap];
        else              v = wC[(oc - 80) * 576 + ic * 9 + tap];
        g_wt96[k] = v;
    } else if (k < R1) {
        int k2 = k - R0;
        int which = k2 / (64 * 576);
        int k3 = k2 - which * (64 * 576);
        int oc = k3 / 576, rem = k3 - oc * 576;
        int tap = rem >> 6, ic = rem & 63;
        const float* s = (which == 0) ? ew2 : ((which == 1) ? dw1 : dw2);
        float v = s[oc * 576 + ic * 9 + tap];
        if (which == 0) g_wtE[k3] = v;
        else if (which == 1) g_wtD1[k3] = v;
        else g_wtD2[k3] = v;
    }
    if (k < DM)       g_bpack[k] = bd[k];
    else if (k < 96)  g_bpack[k] = 0.f;
    if (k < DS * DM) {
        int n = k >> 6, d = k & 63;
        float a = -expf(logA[d * DS + n]);
        g_A[k] = a;
        g_rA[k] = 1.f / a;
    }
}

// row-wise uniformity: A[d][n] == A[d][0] for all n (fast-path requirement)
__global__ void check_uni(const float* __restrict__ logA)
{
    __shared__ int ok;
    if (threadIdx.x == 0) ok = 1;
    __syncthreads();
    bool bad = false;
    for (int i = threadIdx.x; i < DM * DS; i += 256)
        if (logA[i] != logA[(i / DS) * DS]) bad = true;
    if (bad) atomicAnd(&ok, 0);
    __syncthreads();
    if (threadIdx.x == 0) g_uniA = ok;
}

// ---------------- f32x2 conv, 4 rows/thread; weights pre-transposed ----------------
// Block = 128 thr = 32 c x 2 ocp x 2 ic-half; computes 4 rows x 4 oc.
// grid = (8 row-quads, OC/4, z). w staging = coalesced float4 copy.
template <bool RELU>
__global__ __launch_bounds__(128) void conv_f4(const float* __restrict__ x,
                                               const float* __restrict__ wgt,
                                               const float* __restrict__ bias,
                                               float* __restrict__ y, int OC)
{
    __shared__ float4 xs[6 * 32 * 17];     // 51 KB: rows r0-1 .. r0+4
    __shared__ float  ws[4][9][64];        // 9 KB, [ocl][tap][ic]
    __shared__ float  bs[4];
    __shared__ float4 red[2][32][2];
    const int tid = threadIdx.x;
    const int obase = blockIdx.y * 4;
    const int r0 = blockIdx.x * 4;
    x += (size_t)blockIdx.z * DM * HW;
    y += (size_t)blockIdx.z * (size_t)OC * HW;

    const float4* x4 = (const float4*)x;
    for (int k = tid; k < 6 * 32 * 16; k += 128) {
        int lr = k >> 9; int rem = k & 511; int c = rem >> 4; int icv = rem & 15;
        int row = (r0 - 1 + lr) & 31;
        xs[(lr * 32 + c) * 17 + icv] = x4[(((row << 5) + c) << 4) + icv];
    }
    {
        const float4* wsrc = (const float4*)(wgt + (size_t)obase * 576);
        float4* wdst = (float4*)&ws[0][0][0];
        for (int k = tid; k < 576; k += 128) wdst[k] = wsrc[k];
    }
    if (tid < 4) bs[tid] = bias[obase + tid];
    __syncthreads();

    const int half = tid >> 6;
    const int ocp  = (tid >> 5) & 1;
    const int c    = tid & 31;
    const int cm = (c + 31) & 31, cp = (c + 1) & 31;
    const int hb = half * 8;

    unsigned long long acc[4][2];
#pragma unroll
    for (int p = 0; p < 4; p++) { acc[p][0] = 0ull; acc[p][1] = 0ull; }

#pragma unroll
    for (int tc = 0; tc < 3; tc++) {
        const int cx = (tc == 0) ? cm : ((tc == 1) ? c : cp);
        const ulonglong2* xr[6];
#pragma unroll
        for (int r = 0; r < 6; r++) xr[r] = (const ulonglong2*)&xs[(r * 32 + cx) * 17 + hb];
        const ulonglong2* w0t[3];
        const ulonglong2* w1t[3];
#pragma unroll
        for (int tr = 0; tr < 3; tr++) {
            w0t[tr] = (const ulonglong2*)&ws[ocp * 2 + 0][tr * 3 + tc][half * 32];
            w1t[tr] = (const ulonglong2*)&ws[ocp * 2 + 1][tr * 3 + tc][half * 32];
        }
#pragma unroll
        for (int icv = 0; icv < 8; icv++) {
            ulonglong2 xv[6];
#pragma unroll
            for (int r = 0; r < 6; r++) xv[r] = xr[r][icv];
#pragma unroll
            for (int tr = 0; tr < 3; tr++) {
                ulonglong2 wa = w0t[tr][icv];
                ulonglong2 wb = w1t[tr][icv];
#pragma unroll
                for (int p = 0; p < 4; p++) {
                    FMA2(acc[p][0], xv[p + tr].x, wa.x); FMA2(acc[p][0], xv[p + tr].y, wa.y);
                    FMA2(acc[p][1], xv[p + tr].x, wb.x); FMA2(acc[p][1], xv[p + tr].y, wb.y);
                }
            }
        }
    }

    float s[4][2];
#pragma unroll
    for (int p = 0; p < 4; p++) {
        float lo, hi;
        UNPK2(lo, hi, acc[p][0]); s[p][0] = lo + hi;
        UNPK2(lo, hi, acc[p][1]); s[p][1] = lo + hi;
    }

    if (half) {
        float4 rA; rA.x = s[0][0]; rA.y = s[0][1]; rA.z = s[1][0]; rA.w = s[1][1];
        float4 rB; rB.x = s[2][0]; rB.y = s[2][1]; rB.z = s[3][0]; rB.w = s[3][1];
        red[ocp][c][0] = rA; red[ocp][c][1] = rB;
    }
    __syncthreads();
    if (!half) {
        float4 rA = red[ocp][c][0];
        float4 rB = red[ocp][c][1];
        float b0 = bs[ocp * 2], b1 = bs[ocp * 2 + 1];
        float o[4][2];
        o[0][0] = s[0][0] + rA.x + b0; o[0][1] = s[0][1] + rA.y + b1;
        o[1][0] = s[1][0] + rA.z + b0; o[1][1] = s[1][1] + rA.w + b1;
        o[2][0] = s[2][0] + rB.x + b0; o[2][1] = s[2][1] + rB.y + b1;
        o[3][0] = s[3][0] + rB.z + b0; o[3][1] = s[3][1] + rB.w + b1;
#pragma unroll
        for (int p = 0; p < 4; p++) {
            float v0 = o[p][0], v1 = o[p][1];
            if (RELU) { v0 = fmaxf(v0, 0.f); v1 = fmaxf(v1, 0.f); }
            const int px = ((r0 + p) << 5) + c;
            float2 ov; ov.x = v0; ov.y = v1;
            *(float2*)&y[(size_t)px * OC + obase + ocp * 2] = ov;
        }
    }
}

// ---------------- channel-last conv, IC=1 ----------------
__global__ __launch_bounds__(128) void conv1_cl(const float* __restrict__ x,
                                                const float* __restrict__ wgt,
                                                const float* __restrict__ bias,
                                                float* __restrict__ y)
{
    __shared__ float xs[6 * 32];
    __shared__ float ws[4][9];
    __shared__ float bs[4];
    const int tid = threadIdx.x;
    const int obase = blockIdx.y * 4;
    x += blockIdx.z * HW;
    y += (size_t)blockIdx.z * DM * HW;
    const int r0 = blockIdx.x * 4;
    for (int k = tid; k < 6 * 32; k += 128) {
        int lr = k >> 5, c = k & 31;
        xs[k] = x[(((r0 - 1 + lr) & 31) << 5) + c];
    }
    if (tid < 36) ws[tid / 9][tid % 9] = wgt[(obase + tid / 9) * 9 + tid % 9];
    if (tid < 4)  bs[tid] = bias[obase + tid];
    __syncthreads();

    const int hl = tid >> 5, c = tid & 31;
    const int cm = (c + 31) & 31, cp = (c + 1) & 31;
    float xv[9];
#pragma unroll
    for (int tr = 0; tr < 3; tr++) {
        xv[tr * 3 + 0] = xs[(hl + tr) * 32 + cm];
        xv[tr * 3 + 1] = xs[(hl + tr) * 32 + c];
        xv[tr * 3 + 2] = xs[(hl + tr) * 32 + cp];
    }
    float4 o; float* op = &o.x;
#pragma unroll
    for (int j = 0; j < 4; j++) {
        float a = bs[j];
#pragma unroll
        for (int t9 = 0; t9 < 9; t9++) a = fmaf(xv[t9], ws[j][t9], a);
        op[j] = fmaxf(a, 0.f);
    }
    const int px = blockIdx.x * 128 + tid;
    *(float4*)&y[(size_t)px * DM + obase] = o;
}

// ---------------- channel-last conv, OC=1; 64 blocks (2 per row, 8-lane ic-groups) ----
__global__ __launch_bounds__(128) void conv_out(const float* __restrict__ x,
                                                const float* __restrict__ wgt,
                                                const float* __restrict__ bias,
                                                float* __restrict__ y)
{
    __shared__ float4 xs[3 * 32 * 17];
    __shared__ float  ws[9][64];
    const int tid = threadIdx.x;
    const int r0 = blockIdx.x >> 1;
    const int chalf = blockIdx.x & 1;
    const float4* x4 = (const float4*)x;
    for (int k = tid; k < 3 * 32 * 16; k += 128) {
        int lr = k >> 9; int rem = k & 511; int c = rem >> 4; int icv = rem & 15;
        int row = (r0 - 1 + lr) & 31;
        xs[(lr * 32 + c) * 17 + icv] = x4[(((row << 5) + c) << 4) + icv];
    }
    for (int k = tid; k < 576; k += 128) {
        int tap = k >> 6, ic = k & 63;
        ws[tap][ic] = wgt[ic * 9 + tap];
    }
    __syncthreads();

    const int icg = tid & 7;
    const int c = chalf * 16 + (tid >> 3);
    const int cm = (c + 31) & 31, cp = (c + 1) & 31;
    float acc = 0.f;
#pragma unroll
    for (int tr = 0; tr < 3; tr++) {
#pragma unroll
        for (int tc = 0; tc < 3; tc++) {
            const int cx = (tc == 0) ? cm : ((tc == 1) ? c : cp);
            const float4* xp = &xs[(tr * 32 + cx) * 17];
            const float4* wp = (const float4*)&ws[tr * 3 + tc][0];
#pragma unroll
            for (int k = 0; k < 2; k++) {
                float4 xv = xp[icg * 2 + k];
                float4 wv = wp[icg * 2 + k];
                acc = fmaf(xv.x, wv.x, fmaf(xv.y, wv.y, fmaf(xv.z, wv.z, fmaf(xv.w, wv.w, acc))));
            }
        }
    }
    acc += __shfl_xor_sync(0xffffffffu, acc, 1);
    acc += __shfl_xor_sync(0xffffffffu, acc, 2);
    acc += __shfl_xor_sync(0xffffffffu, acc, 4);
    if (icg == 0) y[(r0 << 5) + c] = acc + bias[0];
}

__device__ __forceinline__ float sp_f(float x) { return (x > 20.f) ? x : log1pf(expf(x)); }

// ---------------- prep: e,f,(delta,u),B fields for encode slots ----------------
__global__ __launch_bounds__(128) void prep(const float* __restrict__ cc,
                                            const float* __restrict__ u,
                                            const float* __restrict__ dtp)
{
    const int s = blockIdx.z;
    cc += (size_t)s * HW * 96;
    u  += (size_t)s * HW * 64;
    const int tid = threadIdx.x;
    const int pl = tid >> 4, dq = tid & 15;
    const int p = blockIdx.x * 8 + pl;
    const float dti = dtp[0];

    float4 dc = *(const float4*)&cc[p * 96 + dq * 4];
    float4 dl4;
    dl4.x = sp_f(dc.x + dti); dl4.y = sp_f(dc.y + dti);
    dl4.z = sp_f(dc.z + dti); dl4.w = sp_f(dc.w + dti);
    float4 a4  = *(const float4*)&g_A[dq * 4];
    float4 ra4 = *(const float4*)&g_rA[dq * 4];
    float4 e4, f4;
    e4.x = __expf(dl4.x * a4.x); e4.y = __expf(dl4.y * a4.y);
    e4.z = __expf(dl4.z * a4.z); e4.w = __expf(dl4.w * a4.w);
    float4 u4 = *(const float4*)&u[p * 64 + dq * 4];
    f4.x = (e4.x - 1.f) * ra4.x * u4.x;
    f4.y = (e4.y - 1.f) * ra4.y * u4.y;
    f4.z = (e4.z - 1.f) * ra4.z * u4.z;
    f4.w = (e4.w - 1.f) * ra4.w * u4.w;

    float4* efp = (float4*)g_ef + (((size_t)s * HW + p) * 16 + dq) * 2;
    efp[0] = e4; efp[1] = f4;
    if (!g_uniA) {      // generic fallback history only
        *(float4*)&g_dl[((size_t)s * HW + p) * 64 + dq * 4] = dl4;
        *(float4*)&g_uf[((size_t)s * HW + p) * 64 + dq * 4] = u4;
    }
    g_Bf[((size_t)s * HW + p) * 16 + dq] = cc[p * 96 + 64 + dq];
}

// ---- per-chunk v evaluation helper (uniA fast path) ----
template<int CNT>
__device__ __forceinline__ void yv_chunk(int vbase, int S, int h, int w, int dq,
                                         const float* GsRow, float g0,
                                         float4 e4o, float4 f4o, float4& best)
{
    float4 P[CNT], acc[CNT];
#pragma unroll
    for (int j = 0; j < CNT; j++) {
        acc[j].x = f4o.x * g0; acc[j].y = f4o.y * g0;
        acc[j].z = f4o.z * g0; acc[j].w = f4o.w * g0;
        P[j] = e4o;
    }
#pragma unroll 1
    for (int k = 1; k < S; k++) {
#pragma unroll
        for (int j = 0; j < CNT; j++) {
            int v = vbase + j;
            int vx = v / 5 - 2, vy = v % 5 - 2;
            int hh = (h + k * vy) & 31;
            int ww = (w + k * vx) & 31;
            int x = (hh << 5) + ww;
            const float4* ep = (const float4*)g_ef + (((size_t)(S - 1 - k) * HW + x) * 16 + dq) * 2;
            float4 ee = ep[0];
            float4 ff = ep[1];
            float Gv = GsRow[v * MAXS + k];
            acc[j].x = fmaf(P[j].x * ff.x, Gv, acc[j].x);
            acc[j].y = fmaf(P[j].y * ff.y, Gv, acc[j].y);
            acc[j].z = fmaf(P[j].z * ff.z, Gv, acc[j].z);
            acc[j].w = fmaf(P[j].w * ff.w, Gv, acc[j].w);
            P[j].x *= ee.x; P[j].y *= ee.y; P[j].z *= ee.z; P[j].w *= ee.w;
        }
    }
#pragma unroll
    for (int j = 0; j < CNT; j++) {
        best.x = fmaxf(best.x, acc[j].x);
        best.y = fmaxf(best.y, acc[j].y);
        best.z = fmaxf(best.z, acc[j].z);
        best.w = fmaxf(best.w, acc[j].w);
    }
}

// ---------------- fused y-kernel (decode step S, 1-based); 128 thr, v-split x2 ------
__global__ __launch_bounds__(128) void fused_y(const float* __restrict__ cc,
                                               const float* __restrict__ u,
                                               const float* __restrict__ Dskip,
                                               const float* __restrict__ dtp,
                                               int S, float* __restrict__ ymax)
{
    __shared__ float Bs[4][16], Cs[4][16];
    __shared__ float Gs[4][NV][MAXS];
    __shared__ float G0[4];
    __shared__ float4 sb1[4][16];
    const int tid = threadIdx.x;
    const int half = tid >> 6;
    const int t64 = tid & 63;
    const int pl = t64 >> 4, dq = t64 & 15;
    const int p0 = blockIdx.x * 4;
    const int p = p0 + pl;
    const int h = p >> 5, w = p & 31;
    const int slotS = S - 1;
    const float dti = dtp[0];

    // own-step prep (both halves compute; global/smem writes by half 0 only)
    float4 dc = *(const float4*)&cc[p * 96 + dq * 4];
    float4 dl4;
    dl4.x = sp_f(dc.x + dti); dl4.y = sp_f(dc.y + dti);
    dl4.z = sp_f(dc.z + dti); dl4.w = sp_f(dc.w + dti);
    float4 a4  = *(const float4*)&g_A[dq * 4];
    float4 ra4 = *(const float4*)&g_rA[dq * 4];
    float4 e4o, f4o;
    e4o.x = __expf(dl4.x * a4.x); e4o.y = __expf(dl4.y * a4.y);
    e4o.z = __expf(dl4.z * a4.z); e4o.w = __expf(dl4.w * a4.w);
    float4 u4 = *(const float4*)&u[p * 64 + dq * 4];
    f4o.x = (e4o.x - 1.f) * ra4.x * u4.x;
    f4o.y = (e4o.y - 1.f) * ra4.y * u4.y;
    f4o.z = (e4o.z - 1.f) * ra4.z * u4.z;
    f4o.w = (e4o.w - 1.f) * ra4.w * u4.w;

    if (half == 0) {
        float4* efp = (float4*)g_ef + (((size_t)slotS * HW + p) * 16 + dq) * 2;
        efp[0] = e4o; efp[1] = f4o;
        if (!g_uniA) {
            *(float4*)&g_dl[((size_t)slotS * HW + p) * 64 + dq * 4] = dl4;
            *(float4*)&g_uf[((size_t)slotS * HW + p) * 64 + dq * 4] = u4;
        }
        float bv = cc[p * 96 + 64 + dq];
        g_Bf[((size_t)slotS * HW + p) * 16 + dq] = bv;
        Bs[pl][dq] = bv;
        Cs[pl][dq] = cc[p * 96 + 80 + dq];
    }
    __syncthreads();

    if (tid < 4) {
        float s = 0.f;
#pragma unroll
        for (int n = 0; n < 16; n++) s += Bs[tid][n] * Cs[tid][n];
        G0[tid] = s;
    }
    const int Sm1 = S - 1;
    const int tot = 4 * NV * Sm1;
    for (int idx = tid; idx < tot; idx += 128) {
        int i = idx / (NV * Sm1);
        int rem = idx - i * (NV * Sm1);
        int v = rem / Sm1;
        int k = rem - v * Sm1 + 1;
        int vx = v / 5 - 2, vy = v % 5 - 2;
        int pp = p0 + i;
        int hh = ((pp >> 5) + k * vy) & 31;
        int ww = ((pp & 31) + k * vx) & 31;
        int x = (hh << 5) + ww;
        const float* bp = &g_Bf[((size_t)(S - 1 - k) * HW + x) * 16];
        float s = 0.f;
#pragma unroll
        for (int n = 0; n < 16; n++) s += bp[n] * Cs[i][n];
        Gs[i][v][k] = s;
    }
    __syncthreads();

    float4 best = {-3e38f, -3e38f, -3e38f, -3e38f};
    if (g_uniA) {
        const float g0 = G0[pl];
        const float* GsRow = &Gs[pl][0][0];
        if (half == 0) {            // v 0..11
            yv_chunk<4>(0, S, h, w, dq, GsRow, g0, e4o, f4o, best);
            yv_chunk<4>(4, S, h, w, dq, GsRow, g0, e4o, f4o, best);
            yv_chunk<4>(8, S, h, w, dq, GsRow, g0, e4o, f4o, best);
        } else {                    // v 12..24
            yv_chunk<4>(12, S, h, w, dq, GsRow, g0, e4o, f4o, best);
            yv_chunk<4>(16, S, h, w, dq, GsRow, g0, e4o, f4o, best);
            yv_chunk<5>(20, S, h, w, dq, GsRow, g0, e4o, f4o, best);
        }
    } else if (half == 0) {
        // generic A fallback (correct for any A; half 0 covers all 25 v)
#pragma unroll 1
        for (int v = 0; v < NV; v++) {
            int vx = v / 5 - 2, vy = v % 5 - 2;
            float4 accv = {0.f, 0.f, 0.f, 0.f};
#pragma unroll 1
            for (int n = 0; n < 16; n++) {
                float4 an4 = *(const float4*)&g_A[n * 64 + dq * 4];
                float4 rn4 = *(const float4*)&g_rA[n * 64 + dq * 4];
                float C = Cs[pl][n];
                float4 e0;
                e0.x = __expf(dl4.x * an4.x); e0.y = __expf(dl4.y * an4.y);
                e0.z = __expf(dl4.z * an4.z); e0.w = __expf(dl4.w * an4.w);
                float bc = Bs[pl][n] * C;
                float4 P = e0, a4c;
                a4c.x = (e0.x - 1.f) * rn4.x * u4.x * bc;
                a4c.y = (e0.y - 1.f) * rn4.y * u4.y * bc;
                a4c.z = (e0.z - 1.f) * rn4.z * u4.z * bc;
                a4c.w = (e0.w - 1.f) * rn4.w * u4.w * bc;
                for (int k = 1; k < S; k++) {
                    int hh = (h + k * vy) & 31;
                    int ww = (w + k * vx) & 31;
                    int x = (hh << 5) + ww;
                    int sl = S - 1 - k;
                    float4 dl = *(const float4*)&g_dl[((size_t)sl * HW + x) * 64 + dq * 4];
                    float4 uu = *(const float4*)&g_uf[((size_t)sl * HW + x) * 64 + dq * 4];
                    float Bt = g_Bf[((size_t)sl * HW + x) * 16 + n] * C;
                    float4 ee;
                    ee.x = __expf(dl.x * an4.x); ee.y = __expf(dl.y * an4.y);
                    ee.z = __expf(dl.z * an4.z); ee.w = __expf(dl.w * an4.w);
                    a4c.x = fmaf(P.x * (ee.x - 1.f) * rn4.x * uu.x, Bt, a4c.x);
                    a4c.y = fmaf(P.y * (ee.y - 1.f) * rn4.y * uu.y, Bt, a4c.y);
                    a4c.z = fmaf(P.z * (ee.z - 1.f) * rn4.z * uu.z, Bt, a4c.z);
                    a4c.w = fmaf(P.w * (ee.w - 1.f) * rn4.w * uu.w, Bt, a4c.w);
                    P.x *= ee.x; P.y *= ee.y; P.z *= ee.z; P.w *= ee.w;
                }
                accv.x += a4c.x; accv.y += a4c.y; accv.z += a4c.z; accv.w += a4c.w;
            }
            best.x = fmaxf(best.x, accv.x);
            best.y = fmaxf(best.y, accv.y);
            best.z = fmaxf(best.z, accv.z);
            best.w = fmaxf(best.w, accv.w);
        }
    }

    if (half == 1) sb1[pl][dq] = best;
    __syncthreads();
    if (half == 0) {
        float4 b1 = sb1[pl][dq];
        best.x = fmaxf(best.x, b1.x);
        best.y = fmaxf(best.y, b1.y);
        best.z = fmaxf(best.z, b1.z);
        best.w = fmaxf(best.w, b1.w);
        float4 dk = *(const float4*)&Dskip[dq * 4];
        float4 o;
        o.x = fmaf(dk.x, u4.x, best.x);
        o.y = fmaf(dk.y, u4.y, best.y);
        o.z = fmaf(dk.z, u4.z, best.z);
        o.w = fmaf(dk.w, u4.w, best.w);
        *(float4*)&ymax[p * 64 + dq * 4] = o;
    }
}

// ---------------- launch ----------------
extern "C" void kernel_launch(void* const* d_in, const int* in_sizes, int n_in,
                              void* d_out, int out_size)
{
    const float* input_seq = (const float*)d_in[0];
    const float* enc_w1 = (const float*)d_in[1];
    const float* enc_b1 = (const float*)d_in[2];
    const float* enc_w2 = (const float*)d_in[3];
    const float* enc_b2 = (const float*)d_in[4];
    const float* wd     = (const float*)d_in[5];
    const float* bd     = (const float*)d_in[6];
    const float* wB     = (const float*)d_in[7];
    const float* wC     = (const float*)d_in[8];
    const float* logA   = (const float*)d_in[9];
    const float* Dskip  = (const float*)d_in[10];
    const float* dt_inv = (const float*)d_in[11];
    const float* dec_w1 = (const float*)d_in[12];
    const float* dec_b1 = (const float*)d_in[13];
    const float* dec_w2 = (const float*)d_in[14];
    const float* dec_b2 = (const float*)d_in[15];
    const float* dec_w3 = (const float*)d_in[16];
    const float* dec_b3 = (const float*)d_in[17];
    float* out = (float*)d_out;

    float *p_u, *p_e1, *p_cc, *p_wt96, *p_wtE, *p_wtD1, *p_wtD2, *p_bpack;
    float *p_ymax, *p_d1, *p_d2;
    cudaGetSymbolAddress((void**)&p_u, g_u);
    cudaGetSymbolAddress((void**)&p_e1, g_e1);
    cudaGetSymbolAddress((void**)&p_cc, g_cc);
    cudaGetSymbolAddress((void**)&p_wt96, g_wt96);
    cudaGetSymbolAddress((void**)&p_wtE, g_wtE);
    cudaGetSymbolAddress((void**)&p_wtD1, g_wtD1);
    cudaGetSymbolAddress((void**)&p_wtD2, g_wtD2);
    cudaGetSymbolAddress((void**)&p_bpack, g_bpack);
    cudaGetSymbolAddress((void**)&p_ymax, g_ymax);
    cudaGetSymbolAddress((void**)&p_d1, g_d1);
    cudaGetSymbolAddress((void**)&p_d2, g_d2);

    pack_all<<<648, 256>>>(wd, bd, wB, wC, logA, enc_w2, dec_w1, dec_w2);
    check_uni<<<1, 256>>>(logA);

    // ---- encode: batched over 4 frames; history fields only ----
    conv1_cl<<<dim3(8, 16, TIN), 128>>>(input_seq, enc_w1, enc_b1, p_e1);
    conv_f4<true><<<dim3(8, 16, TIN), 128>>>(p_e1, p_wtE, enc_b2, p_u, DM);
    conv_f4<false><<<dim3(8, 24, TIN), 128>>>(p_u, p_wt96, p_bpack, p_cc, 96);
    prep<<<dim3(128, 1, TIN), 128>>>(p_cc, p_u, dt_inv);

    // ---- decode ----
    int steps = out_size / HW;
    for (int t = 0; t < steps; t++) {
        const float* src = (t == 0) ? (input_seq + 3 * HW) : (out + (size_t)(t - 1) * HW);
        conv1_cl<<<dim3(8, 16, 1), 128>>>(src, enc_w1, enc_b1, p_e1);
        conv_f4<true><<<dim3(8, 16, 1), 128>>>(p_e1, p_wtE, enc_b2, p_u, DM);
        conv_f4<false><<<dim3(8, 24, 1), 128>>>(p_u, p_wt96, p_bpack, p_cc, 96);
        fused_y<<<256, 128>>>(p_cc, p_u, Dskip, dt_inv, TIN + 1 + t, p_ymax);
        conv_f4<true><<<dim3(8, 16, 1), 128>>>(p_ymax, p_wtD1, dec_b1, p_d1, DM);
        conv_f4<true><<<dim3(8, 16, 1), 128>>>(p_d1, p_wtD2, dec_b2, p_d2, DM);
        conv_out<<<64, 128>>>(p_d2, dec_w3, dec_b3, out + (size_t)t * HW);
    }
}

// round 14
// speedup vs baseline: 1.5276x; 1.0013x over previous
#include <cuda_runtime.h>
#include <math.h>

#define HW   1024
#define DM   64
#define DS   16
#define NV   25
#define TIN  4
#define MAXS 8

// packed fp32x2 FMA (sm_100+; only reachable via PTX)
#define FMA2(d, a, b) asm("fma.rn.f32x2 %0, %1, %2, %0;" : "+l"(d) : "l"(a), "l"(b))
#define UNPK2(lo, hi, v) asm("mov.b64 {%0, %1}, %2;" : "=f"(lo), "=f"(hi) : "l"(v))

// ---------------- scratch (static device globals; no allocation) ----------------
__device__ __align__(128) float g_u[TIN * HW * DM];
__device__ __align__(128) float g_e1[TIN * HW * DM];
__device__ __align__(128) float g_cc[TIN * HW * 96];            // [t][px][dconv|B|C]
__device__ __align__(128) float g_wt96[96 * 576];               // wd|wB|wC transposed [oc][tap][ic]
__device__ __align__(128) float g_wtE[64 * 576];                // enc_w2 transposed
__device__ __align__(128) float g_wtD1[64 * 576];
__device__ __align__(128) float g_wtD2[64 * 576];
__device__ __align__(128) float g_bpack[96];
__device__ __align__(128) float g_A[DS * DM];                   // A[n][d] = -exp(logA[d][n])
__device__ __align__(128) float g_rA[DS * DM];
__device__ int   g_uniA;
// history fields, slot s-1 for step s = 1..8
__device__ __align__(128) float g_ef[MAXS * HW * DM * 2];       // [slot][p][dq][{e4,f4}]
__device__ __align__(128) float g_dl[MAXS * HW * DM];           // delta (generic fallback only)
__device__ __align__(128) float g_uf[MAXS * HW * DM];           // u history (generic fallback only)
__device__ __align__(128) float g_Bf[MAXS * HW * DS];           // B fields [slot][p][n]
__device__ __align__(128) float g_ymax[HW * DM];
__device__ __align__(128) float g_d1[HW * DM];
__device__ __align__(128) float g_d2[HW * DM];

// ---------------- pack: transposed weights + bias + A fields ----------------
__global__ void pack_all(const float* __restrict__ wd, const float* __restrict__ bd,
                         const float* __restrict__ wB, const float* __restrict__ wC,
                         const float* __restrict__ logA,
                         const float* __restrict__ ew2, const float* __restrict__ dw1,
                         const float* __restrict__ dw2)
{
    int k = blockIdx.x * 256 + threadIdx.x;
    const int R0 = 96 * 576;
    const int R1 = R0 + 3 * 64 * 576;
    if (k < R0) {
        int oc = k / 576, rem = k - oc * 576;
        int tap = rem >> 6, ic = rem & 63;
        float v;
        if (oc < 64)      v = wd[oc * 576 + ic * 9 + tap];
        else if (oc < 80) v = wB[(oc - 64) * 576 + ic * 9 + tap];
        else              v = wC[(oc - 80) * 576 + ic * 9 + tap];
        g_wt96[k] = v;
    } else if (k < R1) {
        int k2 = k - R0;
        int which = k2 / (64 * 576);
        int k3 = k2 - which * (64 * 576);
        int oc = k3 / 576, rem = k3 - oc * 576;
        int tap = rem >> 6, ic = rem & 63;
        const float* s = (which == 0) ? ew2 : ((which == 1) ? dw1 : dw2);
        float v = s[oc * 576 + ic * 9 + tap];
        if (which == 0) g_wtE[k3] = v;
        else if (which == 1) g_wtD1[k3] = v;
        else g_wtD2[k3] = v;
    }
    if (k < DM)       g_bpack[k] = bd[k];
    else if (k < 96)  g_bpack[k] = 0.f;
    if (k < DS * DM) {
        int n = k >> 6, d = k & 63;
        float a = -expf(logA[d * DS + n]);
        g_A[k] = a;
        g_rA[k] = 1.f / a;
    }
}

// row-wise uniformity: A[d][n] == A[d][0] for all n (fast-path requirement)
__global__ void check_uni(const float* __restrict__ logA)
{
    __shared__ int ok;
    if (threadIdx.x == 0) ok = 1;
    __syncthreads();
    bool bad = false;
    for (int i = threadIdx.x; i < DM * DS; i += 256)
        if (logA[i] != logA[(i / DS) * DS]) bad = true;
    if (bad) atomicAnd(&ok, 0);
    __syncthreads();
    if (threadIdx.x == 0) g_uniA = ok;
}

// ---------------- f32x2 conv, 4 rows x 8 oc per block, 256 thr (batched path) -------
// tid = c(32) x ocp(4) x half(2). x tile in dynamic smem (51 KB), staged once per 8 oc.
// grid = (8 row-quads, OC/8, z) -> enc2 batched 256 blocks, cc batched 384: single wave.
template <bool RELU>
__global__ __launch_bounds__(256) void conv_f4w(const float* __restrict__ x,
                                                const float* __restrict__ wgt,
                                                const float* __restrict__ bias,
                                                float* __restrict__ y, int OC)
{
    extern __shared__ float4 xs[];         // 6*32*17 float4 = 51 KB
    __shared__ float  ws[8][9][64];        // 18 KB, [ocl][tap][ic]
    __shared__ float  bs[8];
    __shared__ float4 red[4][32][2];       // 4 KB
    const int tid = threadIdx.x;
    const int obase = blockIdx.y * 8;
    const int r0 = blockIdx.x * 4;
    x += (size_t)blockIdx.z * DM * HW;
    y += (size_t)blockIdx.z * (size_t)OC * HW;

    const float4* x4 = (const float4*)x;
    for (int k = tid; k < 6 * 32 * 16; k += 256) {
        int lr = k >> 9; int rem = k & 511; int c = rem >> 4; int icv = rem & 15;
        int row = (r0 - 1 + lr) & 31;
        xs[(lr * 32 + c) * 17 + icv] = x4[(((row << 5) + c) << 4) + icv];
    }
    {
        const float4* wsrc = (const float4*)(wgt + (size_t)obase * 576);
        float4* wdst = (float4*)&ws[0][0][0];
        for (int k = tid; k < 1152; k += 256) wdst[k] = wsrc[k];
    }
    if (tid < 8) bs[tid] = bias[obase + tid];
    __syncthreads();

    const int half = tid >> 7;             // ic-half
    const int ocp  = (tid >> 5) & 3;       // oc-pair (0..3)
    const int c    = tid & 31;
    const int cm = (c + 31) & 31, cp = (c + 1) & 31;
    const int hb = half * 8;

    unsigned long long acc[4][2];
#pragma unroll
    for (int p = 0; p < 4; p++) { acc[p][0] = 0ull; acc[p][1] = 0ull; }

#pragma unroll
    for (int tc = 0; tc < 3; tc++) {
        const int cx = (tc == 0) ? cm : ((tc == 1) ? c : cp);
        const ulonglong2* xr[6];
#pragma unroll
        for (int r = 0; r < 6; r++) xr[r] = (const ulonglong2*)&xs[(r * 32 + cx) * 17 + hb];
        const ulonglong2* w0t[3];
        const ulonglong2* w1t[3];
#pragma unroll
        for (int tr = 0; tr < 3; tr++) {
            w0t[tr] = (const ulonglong2*)&ws[ocp * 2 + 0][tr * 3 + tc][half * 32];
            w1t[tr] = (const ulonglong2*)&ws[ocp * 2 + 1][tr * 3 + tc][half * 32];
        }
#pragma unroll
        for (int icv = 0; icv < 8; icv++) {
            ulonglong2 xv[6];
#pragma unroll
            for (int r = 0; r < 6; r++) xv[r] = xr[r][icv];
#pragma unroll
            for (int tr = 0; tr < 3; tr++) {
                ulonglong2 wa = w0t[tr][icv];
                ulonglong2 wb = w1t[tr][icv];
#pragma unroll
                for (int p = 0; p < 4; p++) {
                    FMA2(acc[p][0], xv[p + tr].x, wa.x); FMA2(acc[p][0], xv[p + tr].y, wa.y);
                    FMA2(acc[p][1], xv[p + tr].x, wb.x); FMA2(acc[p][1], xv[p + tr].y, wb.y);
                }
            }
        }
    }

    float s[4][2];
#pragma unroll
    for (int p = 0; p < 4; p++) {
        float lo, hi;
        UNPK2(lo, hi, acc[p][0]); s[p][0] = lo + hi;
        UNPK2(lo, hi, acc[p][1]); s[p][1] = lo + hi;
    }

    if (half) {
        float4 rA; rA.x = s[0][0]; rA.y = s[0][1]; rA.z = s[1][0]; rA.w = s[1][1];
        float4 rB; rB.x = s[2][0]; rB.y = s[2][1]; rB.z = s[3][0]; rB.w = s[3][1];
        red[ocp][c][0] = rA; red[ocp][c][1] = rB;
    }
    __syncthreads();
    if (!half) {
        float4 rA = red[ocp][c][0];
        float4 rB = red[ocp][c][1];
        float b0 = bs[ocp * 2], b1 = bs[ocp * 2 + 1];
        float o[4][2];
        o[0][0] = s[0][0] + rA.x + b0; o[0][1] = s[0][1] + rA.y + b1;
        o[1][0] = s[1][0] + rA.z + b0; o[1][1] = s[1][1] + rA.w + b1;
        o[2][0] = s[2][0] + rB.x + b0; o[2][1] = s[2][1] + rB.y + b1;
        o[3][0] = s[3][0] + rB.z + b0; o[3][1] = s[3][1] + rB.w + b1;
#pragma unroll
        for (int p = 0; p < 4; p++) {
            float v0 = o[p][0], v1 = o[p][1];
            if (RELU) { v0 = fmaxf(v0, 0.f); v1 = fmaxf(v1, 0.f); }
            const int px = ((r0 + p) << 5) + c;
            float2 ov; ov.x = v0; ov.y = v1;
            *(float2*)&y[(size_t)px * OC + obase + ocp * 2] = ov;
        }
    }
}

// ---------------- f32x2 conv, 4 rows/thread, 128 thr (single-frame path) ----------
template <bool RELU>
__global__ __launch_bounds__(128) void conv_f4(const float* __restrict__ x,
                                               const float* __restrict__ wgt,
                                               const float* __restrict__ bias,
                                               float* __restrict__ y, int OC)
{
    __shared__ float4 xs[6 * 32 * 17];
    __shared__ float  ws[4][9][64];
    __shared__ float  bs[4];
    __shared__ float4 red[2][32][2];
    const int tid = threadIdx.x;
    const int obase = blockIdx.y * 4;
    const int r0 = blockIdx.x * 4;
    x += (size_t)blockIdx.z * DM * HW;
    y += (size_t)blockIdx.z * (size_t)OC * HW;

    const float4* x4 = (const float4*)x;
    for (int k = tid; k < 6 * 32 * 16; k += 128) {
        int lr = k >> 9; int rem = k & 511; int c = rem >> 4; int icv = rem & 15;
        int row = (r0 - 1 + lr) & 31;
        xs[(lr * 32 + c) * 17 + icv] = x4[(((row << 5) + c) << 4) + icv];
    }
    {
        const float4* wsrc = (const float4*)(wgt + (size_t)obase * 576);
        float4* wdst = (float4*)&ws[0][0][0];
        for (int k = tid; k < 576; k += 128) wdst[k] = wsrc[k];
    }
    if (tid < 4) bs[tid] = bias[obase + tid];
    __syncthreads();

    const int half = tid >> 6;
    const int ocp  = (tid >> 5) & 1;
    const int c    = tid & 31;
    const int cm = (c + 31) & 31, cp = (c + 1) & 31;
    const int hb = half * 8;

    unsigned long long acc[4][2];
#pragma unroll
    for (int p = 0; p < 4; p++) { acc[p][0] = 0ull; acc[p][1] = 0ull; }

#pragma unroll
    for (int tc = 0; tc < 3; tc++) {
        const int cx = (tc == 0) ? cm : ((tc == 1) ? c : cp);
        const ulonglong2* xr[6];
#pragma unroll
        for (int r = 0; r < 6; r++) xr[r] = (const ulonglong2*)&xs[(r * 32 + cx) * 17 + hb];
        const ulonglong2* w0t[3];
        const ulonglong2* w1t[3];
#pragma unroll
        for (int tr = 0; tr < 3; tr++) {
            w0t[tr] = (const ulonglong2*)&ws[ocp * 2 + 0][tr * 3 + tc][half * 32];
            w1t[tr] = (const ulonglong2*)&ws[ocp * 2 + 1][tr * 3 + tc][half * 32];
        }
#pragma unroll
        for (int icv = 0; icv < 8; icv++) {
            ulonglong2 xv[6];
#pragma unroll
            for (int r = 0; r < 6; r++) xv[r] = xr[r][icv];
#pragma unroll
            for (int tr = 0; tr < 3; tr++) {
                ulonglong2 wa = w0t[tr][icv];
                ulonglong2 wb = w1t[tr][icv];
#pragma unroll
                for (int p = 0; p < 4; p++) {
                    FMA2(acc[p][0], xv[p + tr].x, wa.x); FMA2(acc[p][0], xv[p + tr].y, wa.y);
                    FMA2(acc[p][1], xv[p + tr].x, wb.x); FMA2(acc[p][1], xv[p + tr].y, wb.y);
                }
            }
        }
    }

    float s[4][2];
#pragma unroll
    for (int p = 0; p < 4; p++) {
        float lo, hi;
        UNPK2(lo, hi, acc[p][0]); s[p][0] = lo + hi;
        UNPK2(lo, hi, acc[p][1]); s[p][1] = lo + hi;
    }

    if (half) {
        float4 rA; rA.x = s[0][0]; rA.y = s[0][1]; rA.z = s[1][0]; rA.w = s[1][1];
        float4 rB; rB.x = s[2][0]; rB.y = s[2][1]; rB.z = s[3][0]; rB.w = s[3][1];
        red[ocp][c][0] = rA; red[ocp][c][1] = rB;
    }
    __syncthreads();
    if (!half) {
        float4 rA = red[ocp][c][0];
        float4 rB = red[ocp][c][1];
        float b0 = bs[ocp * 2], b1 = bs[ocp * 2 + 1];
        float o[4][2];
        o[0][0] = s[0][0] + rA.x + b0; o[0][1] = s[0][1] + rA.y + b1;
        o[1][0] = s[1][0] + rA.z + b0; o[1][1] = s[1][1] + rA.w + b1;
        o[2][0] = s[2][0] + rB.x + b0; o[2][1] = s[2][1] + rB.y + b1;
        o[3][0] = s[3][0] + rB.z + b0; o[3][1] = s[3][1] + rB.w + b1;
#pragma unroll
        for (int p = 0; p < 4; p++) {
            float v0 = o[p][0], v1 = o[p][1];
            if (RELU) { v0 = fmaxf(v0, 0.f); v1 = fmaxf(v1, 0.f); }
            const int px = ((r0 + p) << 5) + c;
            float2 ov; ov.x = v0; ov.y = v1;
            *(float2*)&y[(size_t)px * OC + obase + ocp * 2] = ov;
        }
    }
}

// ---------------- channel-last conv, IC=1 ----------------
__global__ __launch_bounds__(128) void conv1_cl(const float* __restrict__ x,
                                                const float* __restrict__ wgt,
                                                const float* __restrict__ bias,
                                                float* __restrict__ y)
{
    __shared__ float xs[6 * 32];
    __shared__ float ws[4][9];
    __shared__ float bs[4];
    const int tid = threadIdx.x;
    const int obase = blockIdx.y * 4;
    x += blockIdx.z * HW;
    y += (size_t)blockIdx.z * DM * HW;
    const int r0 = blockIdx.x * 4;
    for (int k = tid; k < 6 * 32; k += 128) {
        int lr = k >> 5, c = k & 31;
        xs[k] = x[(((r0 - 1 + lr) & 31) << 5) + c];
    }
    if (tid < 36) ws[tid / 9][tid % 9] = wgt[(obase + tid / 9) * 9 + tid % 9];
    if (tid < 4)  bs[tid] = bias[obase + tid];
    __syncthreads();

    const int hl = tid >> 5, c = tid & 31;
    const int cm = (c + 31) & 31, cp = (c + 1) & 31;
    float xv[9];
#pragma unroll
    for (int tr = 0; tr < 3; tr++) {
        xv[tr * 3 + 0] = xs[(hl + tr) * 32 + cm];
        xv[tr * 3 + 1] = xs[(hl + tr) * 32 + c];
        xv[tr * 3 + 2] = xs[(hl + tr) * 32 + cp];
    }
    float4 o; float* op = &o.x;
#pragma unroll
    for (int j = 0; j < 4; j++) {
        float a = bs[j];
#pragma unroll
        for (int t9 = 0; t9 < 9; t9++) a = fmaf(xv[t9], ws[j][t9], a);
        op[j] = fmaxf(a, 0.f);
    }
    const int px = blockIdx.x * 128 + tid;
    *(float4*)&y[(size_t)px * DM + obase] = o;
}

// ---------------- channel-last conv, OC=1; 64 blocks ----------------
__global__ __launch_bounds__(128) void conv_out(const float* __restrict__ x,
                                                const float* __restrict__ wgt,
                                                const float* __restrict__ bias,
                                                float* __restrict__ y)
{
    __shared__ float4 xs[3 * 32 * 17];
    __shared__ float  ws[9][64];
    const int tid = threadIdx.x;
    const int r0 = blockIdx.x >> 1;
    const int chalf = blockIdx.x & 1;
    const float4* x4 = (const float4*)x;
    for (int k = tid; k < 3 * 32 * 16; k += 128) {
        int lr = k >> 9; int rem = k & 511; int c = rem >> 4; int icv = rem & 15;
        int row = (r0 - 1 + lr) & 31;
        xs[(lr * 32 + c) * 17 + icv] = x4[(((row << 5) + c) << 4) + icv];
    }
    for (int k = tid; k < 576; k += 128) {
        int tap = k >> 6, ic = k & 63;
        ws[tap][ic] = wgt[ic * 9 + tap];
    }
    __syncthreads();

    const int icg = tid & 7;
    const int c = chalf * 16 + (tid >> 3);
    const int cm = (c + 31) & 31, cp = (c + 1) & 31;
    float acc = 0.f;
#pragma unroll
    for (int tr = 0; tr < 3; tr++) {
#pragma unroll
        for (int tc = 0; tc < 3; tc++) {
            const int cx = (tc == 0) ? cm : ((tc == 1) ? c : cp);
            const float4* xp = &xs[(tr * 32 + cx) * 17];
            const float4* wp = (const float4*)&ws[tr * 3 + tc][0];
#pragma unroll
            for (int k = 0; k < 2; k++) {
                float4 xv = xp[icg * 2 + k];
                float4 wv = wp[icg * 2 + k];
                acc = fmaf(xv.x, wv.x, fmaf(xv.y, wv.y, fmaf(xv.z, wv.z, fmaf(xv.w, wv.w, acc))));
            }
        }
    }
    acc += __shfl_xor_sync(0xffffffffu, acc, 1);
    acc += __shfl_xor_sync(0xffffffffu, acc, 2);
    acc += __shfl_xor_sync(0xffffffffu, acc, 4);
    if (icg == 0) y[(r0 << 5) + c] = acc + bias[0];
}

__device__ __forceinline__ float sp_f(float x) { return (x > 20.f) ? x : log1pf(expf(x)); }

// ---------------- prep: e,f,(delta,u),B fields for encode slots ----------------
__global__ __launch_bounds__(128) void prep(const float* __restrict__ cc,
                                            const float* __restrict__ u,
                                            const float* __restrict__ dtp)
{
    const int s = blockIdx.z;
    cc += (size_t)s * HW * 96;
    u  += (size_t)s * HW * 64;
    const int tid = threadIdx.x;
    const int pl = tid >> 4, dq = tid & 15;
    const int p = blockIdx.x * 8 + pl;
    const float dti = dtp[0];

    float4 dc = *(const float4*)&cc[p * 96 + dq * 4];
    float4 dl4;
    dl4.x = sp_f(dc.x + dti); dl4.y = sp_f(dc.y + dti);
    dl4.z = sp_f(dc.z + dti); dl4.w = sp_f(dc.w + dti);
    float4 a4  = *(const float4*)&g_A[dq * 4];
    float4 ra4 = *(const float4*)&g_rA[dq * 4];
    float4 e4, f4;
    e4.x = __expf(dl4.x * a4.x); e4.y = __expf(dl4.y * a4.y);
    e4.z = __expf(dl4.z * a4.z); e4.w = __expf(dl4.w * a4.w);
    float4 u4 = *(const float4*)&u[p * 64 + dq * 4];
    f4.x = (e4.x - 1.f) * ra4.x * u4.x;
    f4.y = (e4.y - 1.f) * ra4.y * u4.y;
    f4.z = (e4.z - 1.f) * ra4.z * u4.z;
    f4.w = (e4.w - 1.f) * ra4.w * u4.w;

    float4* efp = (float4*)g_ef + (((size_t)s * HW + p) * 16 + dq) * 2;
    efp[0] = e4; efp[1] = f4;
    if (!g_uniA) {
        *(float4*)&g_dl[((size_t)s * HW + p) * 64 + dq * 4] = dl4;
        *(float4*)&g_uf[((size_t)s * HW + p) * 64 + dq * 4] = u4;
    }
    g_Bf[((size_t)s * HW + p) * 16 + dq] = cc[p * 96 + 64 + dq];
}

// ---- per-chunk v evaluation helper (uniA fast path) ----
template<int CNT>
__device__ __forceinline__ void yv_chunk(int vbase, int S, int h, int w, int dq,
                                         const float* GsRow, float g0,
                                         float4 e4o, float4 f4o, float4& best)
{
    float4 P[CNT], acc[CNT];
#pragma unroll
    for (int j = 0; j < CNT; j++) {
        acc[j].x = f4o.x * g0; acc[j].y = f4o.y * g0;
        acc[j].z = f4o.z * g0; acc[j].w = f4o.w * g0;
        P[j] = e4o;
    }
#pragma unroll 1
    for (int k = 1; k < S; k++) {
#pragma unroll
        for (int j = 0; j < CNT; j++) {
            int v = vbase + j;
            int vx = v / 5 - 2, vy = v % 5 - 2;
            int hh = (h + k * vy) & 31;
            int ww = (w + k * vx) & 31;
            int x = (hh << 5) + ww;
            const float4* ep = (const float4*)g_ef + (((size_t)(S - 1 - k) * HW + x) * 16 + dq) * 2;
            float4 ee = ep[0];
            float4 ff = ep[1];
            float Gv = GsRow[v * MAXS + k];
            acc[j].x = fmaf(P[j].x * ff.x, Gv, acc[j].x);
            acc[j].y = fmaf(P[j].y * ff.y, Gv, acc[j].y);
            acc[j].z = fmaf(P[j].z * ff.z, Gv, acc[j].z);
            acc[j].w = fmaf(P[j].w * ff.w, Gv, acc[j].w);
            P[j].x *= ee.x; P[j].y *= ee.y; P[j].z *= ee.z; P[j].w *= ee.w;
        }
    }
#pragma unroll
    for (int j = 0; j < CNT; j++) {
        best.x = fmaxf(best.x, acc[j].x);
        best.y = fmaxf(best.y, acc[j].y);
        best.z = fmaxf(best.z, acc[j].z);
        best.w = fmaxf(best.w, acc[j].w);
    }
}

// ---------------- fused y-kernel (decode step S, 1-based); 128 thr, v-split x2 ------
__global__ __launch_bounds__(128) void fused_y(const float* __restrict__ cc,
                                               const float* __restrict__ u,
                                               const float* __restrict__ Dskip,
                                               const float* __restrict__ dtp,
                                               int S, float* __restrict__ ymax)
{
    __shared__ float Bs[4][16], Cs[4][16];
    __shared__ float Gs[4][NV][MAXS];
    __shared__ float G0[4];
    __shared__ float4 sb1[4][16];
    const int tid = threadIdx.x;
    const int half = tid >> 6;
    const int t64 = tid & 63;
    const int pl = t64 >> 4, dq = t64 & 15;
    const int p0 = blockIdx.x * 4;
    const int p = p0 + pl;
    const int h = p >> 5, w = p & 31;
    const int slotS = S - 1;
    const float dti = dtp[0];

    float4 dc = *(const float4*)&cc[p * 96 + dq * 4];
    float4 dl4;
    dl4.x = sp_f(dc.x + dti); dl4.y = sp_f(dc.y + dti);
    dl4.z = sp_f(dc.z + dti); dl4.w = sp_f(dc.w + dti);
    float4 a4  = *(const float4*)&g_A[dq * 4];
    float4 ra4 = *(const float4*)&g_rA[dq * 4];
    float4 e4o, f4o;
    e4o.x = __expf(dl4.x * a4.x); e4o.y = __expf(dl4.y * a4.y);
    e4o.z = __expf(dl4.z * a4.z); e4o.w = __expf(dl4.w * a4.w);
    float4 u4 = *(const float4*)&u[p * 64 + dq * 4];
    f4o.x = (e4o.x - 1.f) * ra4.x * u4.x;
    f4o.y = (e4o.y - 1.f) * ra4.y * u4.y;
    f4o.z = (e4o.z - 1.f) * ra4.z * u4.z;
    f4o.w = (e4o.w - 1.f) * ra4.w * u4.w;

    if (half == 0) {
        float4* efp = (float4*)g_ef + (((size_t)slotS * HW + p) * 16 + dq) * 2;
        efp[0] = e4o; efp[1] = f4o;
        if (!g_uniA) {
            *(float4*)&g_dl[((size_t)slotS * HW + p) * 64 + dq * 4] = dl4;
            *(float4*)&g_uf[((size_t)slotS * HW + p) * 64 + dq * 4] = u4;
        }
        float bv = cc[p * 96 + 64 + dq];
        g_Bf[((size_t)slotS * HW + p) * 16 + dq] = bv;
        Bs[pl][dq] = bv;
        Cs[pl][dq] = cc[p * 96 + 80 + dq];
    }
    __syncthreads();

    if (tid < 4) {
        float s = 0.f;
#pragma unroll
        for (int n = 0; n < 16; n++) s += Bs[tid][n] * Cs[tid][n];
        G0[tid] = s;
    }
    const int Sm1 = S - 1;
    const int tot = 4 * NV * Sm1;
    for (int idx = tid; idx < tot; idx += 128) {
        int i = idx / (NV * Sm1);
        int rem = idx - i * (NV * Sm1);
        int v = rem / Sm1;
        int k = rem - v * Sm1 + 1;
        int vx = v / 5 - 2, vy = v % 5 - 2;
        int pp = p0 + i;
        int hh = ((pp >> 5) + k * vy) & 31;
        int ww = ((pp & 31) + k * vx) & 31;
        int x = (hh << 5) + ww;
        const float* bp = &g_Bf[((size_t)(S - 1 - k) * HW + x) * 16];
        float s = 0.f;
#pragma unroll
        for (int n = 0; n < 16; n++) s += bp[n] * Cs[i][n];
        Gs[i][v][k] = s;
    }
    __syncthreads();

    float4 best = {-3e38f, -3e38f, -3e38f, -3e38f};
    if (g_uniA) {
        const float g0 = G0[pl];
        const float* GsRow = &Gs[pl][0][0];
        if (half == 0) {
            yv_chunk<4>(0, S, h, w, dq, GsRow, g0, e4o, f4o, best);
            yv_chunk<4>(4, S, h, w, dq, GsRow, g0, e4o, f4o, best);
            yv_chunk<4>(8, S, h, w, dq, GsRow, g0, e4o, f4o, best);
        } else {
            yv_chunk<4>(12, S, h, w, dq, GsRow, g0, e4o, f4o, best);
            yv_chunk<4>(16, S, h, w, dq, GsRow, g0, e4o, f4o, best);
            yv_chunk<5>(20, S, h, w, dq, GsRow, g0, e4o, f4o, best);
        }
    } else if (half == 0) {
        // generic A fallback (correct for any A; half 0 covers all 25 v)
#pragma unroll 1
        for (int v = 0; v < NV; v++) {
            int vx = v / 5 - 2, vy = v % 5 - 2;
            float4 accv = {0.f, 0.f, 0.f, 0.f};
#pragma unroll 1
            for (int n = 0; n < 16; n++) {
                float4 an4 = *(const float4*)&g_A[n * 64 + dq * 4];
                float4 rn4 = *(const float4*)&g_rA[n * 64 + dq * 4];
                float C = Cs[pl][n];
                float4 e0;
                e0.x = __expf(dl4.x * an4.x); e0.y = __expf(dl4.y * an4.y);
                e0.z = __expf(dl4.z * an4.z); e0.w = __expf(dl4.w * an4.w);
                float bc = Bs[pl][n] * C;
                float4 P = e0, a4c;
                a4c.x = (e0.x - 1.f) * rn4.x * u4.x * bc;
                a4c.y = (e0.y - 1.f) * rn4.y * u4.y * bc;
                a4c.z = (e0.z - 1.f) * rn4.z * u4.z * bc;
                a4c.w = (e0.w - 1.f) * rn4.w * u4.w * bc;
                for (int k = 1; k < S; k++) {
                    int hh = (h + k * vy) & 31;
                    int ww = (w + k * vx) & 31;
                    int x = (hh << 5) + ww;
                    int sl = S - 1 - k;
                    float4 dl = *(const float4*)&g_dl[((size_t)sl * HW + x) * 64 + dq * 4];
                    float4 uu = *(const float4*)&g_uf[((size_t)sl * HW + x) * 64 + dq * 4];
                    float Bt = g_Bf[((size_t)sl * HW + x) * 16 + n] * C;
                    float4 ee;
                    ee.x = __expf(dl.x * an4.x); ee.y = __expf(dl.y * an4.y);
                    ee.z = __expf(dl.z * an4.z); ee.w = __expf(dl.w * an4.w);
                    a4c.x = fmaf(P.x * (ee.x - 1.f) * rn4.x * uu.x, Bt, a4c.x);
                    a4c.y = fmaf(P.y * (ee.y - 1.f) * rn4.y * uu.y, Bt, a4c.y);
                    a4c.z = fmaf(P.z * (ee.z - 1.f) * rn4.z * uu.z, Bt, a4c.z);
                    a4c.w = fmaf(P.w * (ee.w - 1.f) * rn4.w * uu.w, Bt, a4c.w);
                    P.x *= ee.x; P.y *= ee.y; P.z *= ee.z; P.w *= ee.w;
                }
                accv.x += a4c.x; accv.y += a4c.y; accv.z += a4c.z; accv.w += a4c.w;
            }
            best.x = fmaxf(best.x, accv.x);
            best.y = fmaxf(best.y, accv.y);
            best.z = fmaxf(best.z, accv.z);
            best.w = fmaxf(best.w, accv.w);
        }
    }

    if (half == 1) sb1[pl][dq] = best;
    __syncthreads();
    if (half == 0) {
        float4 b1 = sb1[pl][dq];
        best.x = fmaxf(best.x, b1.x);
        best.y = fmaxf(best.y, b1.y);
        best.z = fmaxf(best.z, b1.z);
        best.w = fmaxf(best.w, b1.w);
        float4 dk = *(const float4*)&Dskip[dq * 4];
        float4 o;
        o.x = fmaf(dk.x, u4.x, best.x);
        o.y = fmaf(dk.y, u4.y, best.y);
        o.z = fmaf(dk.z, u4.z, best.z);
        o.w = fmaf(dk.w, u4.w, best.w);
        *(float4*)&ymax[p * 64 + dq * 4] = o;
    }
}

// ---------------- launch ----------------
extern "C" void kernel_launch(void* const* d_in, const int* in_sizes, int n_in,
                              void* d_out, int out_size)
{
    const float* input_seq = (const float*)d_in[0];
    const float* enc_w1 = (const float*)d_in[1];
    const float* enc_b1 = (const float*)d_in[2];
    const float* enc_w2 = (const float*)d_in[3];
    const float* enc_b2 = (const float*)d_in[4];
    const float* wd     = (const float*)d_in[5];
    const float* bd     = (const float*)d_in[6];
    const float* wB     = (const float*)d_in[7];
    const float* wC     = (const float*)d_in[8];
    const float* logA   = (const float*)d_in[9];
    const float* Dskip  = (const float*)d_in[10];
    const float* dt_inv = (const float*)d_in[11];
    const float* dec_w1 = (const float*)d_in[12];
    const float* dec_b1 = (const float*)d_in[13];
    const float* dec_w2 = (const float*)d_in[14];
    const float* dec_b2 = (const float*)d_in[15];
    const float* dec_w3 = (const float*)d_in[16];
    const float* dec_b3 = (const float*)d_in[17];
    float* out = (float*)d_out;

    float *p_u, *p_e1, *p_cc, *p_wt96, *p_wtE, *p_wtD1, *p_wtD2, *p_bpack;
    float *p_ymax, *p_d1, *p_d2;
    cudaGetSymbolAddress((void**)&p_u, g_u);
    cudaGetSymbolAddress((void**)&p_e1, g_e1);
    cudaGetSymbolAddress((void**)&p_cc, g_cc);
    cudaGetSymbolAddress((void**)&p_wt96, g_wt96);
    cudaGetSymbolAddress((void**)&p_wtE, g_wtE);
    cudaGetSymbolAddress((void**)&p_wtD1, g_wtD1);
    cudaGetSymbolAddress((void**)&p_wtD2, g_wtD2);
    cudaGetSymbolAddress((void**)&p_bpack, g_bpack);
    cudaGetSymbolAddress((void**)&p_ymax, g_ymax);
    cudaGetSymbolAddress((void**)&p_d1, g_d1);
    cudaGetSymbolAddress((void**)&p_d2, g_d2);

    const int XS_BYTES = 6 * 32 * 17 * 16;   // 52224
    cudaFuncSetAttribute(conv_f4w<true>,  cudaFuncAttributeMaxDynamicSharedMemorySize, XS_BYTES);
    cudaFuncSetAttribute(conv_f4w<false>, cudaFuncAttributeMaxDynamicSharedMemorySize, XS_BYTES);

    pack_all<<<648, 256>>>(wd, bd, wB, wC, logA, enc_w2, dec_w1, dec_w2);
    check_uni<<<1, 256>>>(logA);

    // ---- encode: batched over 4 frames; single-wave wide conv blocks ----
    conv1_cl<<<dim3(8, 16, TIN), 128>>>(input_seq, enc_w1, enc_b1, p_e1);
    conv_f4w<true><<<dim3(8, 8, TIN), 256, XS_BYTES>>>(p_e1, p_wtE, enc_b2, p_u, DM);
    conv_f4w<false><<<dim3(8, 12, TIN), 256, XS_BYTES>>>(p_u, p_wt96, p_bpack, p_cc, 96);
    prep<<<dim3(128, 1, TIN), 128>>>(p_cc, p_u, dt_inv);

    // ---- decode ----
    int steps = out_size / HW;
    for (int t = 0; t < steps; t++) {
        const float* src = (t == 0) ? (input_seq + 3 * HW) : (out + (size_t)(t - 1) * HW);
        conv1_cl<<<dim3(8, 16, 1), 128>>>(src, enc_w1, enc_b1, p_e1);
        conv_f4<true><<<dim3(8, 16, 1), 128>>>(p_e1, p_wtE, enc_b2, p_u, DM);
        conv_f4<false><<<dim3(8, 24, 1), 128>>>(p_u, p_wt96, p_bpack, p_cc, 96);
        fused_y<<<256, 128>>>(p_cc, p_u, Dskip, dt_inv, TIN + 1 + t, p_ymax);
        conv_f4<true><<<dim3(8, 16, 1), 128>>>(p_ymax, p_wtD1, dec_b1, p_d1, DM);
        conv_f4<true><<<dim3(8, 16, 1), 128>>>(p_d1, p_wtD2, dec_b2, p_d2, DM);
        conv_out<<<64, 128>>>(p_d2, dec_w3, dec_b3, out + (size_t)t * HW);
    }
}